// round 2
// baseline (speedup 1.0000x reference)
#include <cuda_runtime.h>
#include <math.h>

#define Nn 512
#define CSd 384
#define CZd 128
#define Hh 12
#define Cc 16
#define PQd 4
#define PVd 8
#define OUTD 2112   // H*(C + 3*PV + PV + CZ) = 12*176

// ---------------- scratch (no allocation allowed) ----------------
__device__ float g_q[Nn*Hh*Cc], g_k[Nn*Hh*Cc], g_v[Nn*Hh*Cc];
__device__ float g_qp[Nn*Hh*PQd*3], g_kp[Nn*Hh*PQd*3], g_vp[Nn*Hh*PVd*3];
__device__ float g_gq[Nn*Hh*PQd*3], g_gk[Nn*Hh*PQd*3], g_gv[Nn*Hh*PVd*3];
__device__ float g_sqq[Nn*Hh], g_sqk[Nn*Hh];
__device__ float g_logits[Nn*Nn*Hh];      // layout [i][h][j]
__device__ float g_concat[Nn*OUTD];
__device__ float g_s1[Nn*CSd], g_h1[Nn*CSd], g_h2[Nn*CSd], g_s2[Nn*CSd];
__device__ float g_rotn[Nn*9], g_trn[Nn*3];
__device__ float g_partial[Nn];

// ---------------- helpers ----------------
__device__ __forceinline__ float blockSum384(float v, float* red) {
    int tid = threadIdx.x;
    red[tid] = v;
    if (tid < 128) red[384 + tid] = 0.f;
    __syncthreads();
    for (int s = 256; s > 0; s >>= 1) {
        if (tid < s) red[tid] += red[tid + s];
        __syncthreads();
    }
    float r = red[0];
    __syncthreads();
    return r;
}

// ---------------- projections: 4 rows per block ----------------
__global__ void rowgemm_k(const float* __restrict__ A, const float* __restrict__ W,
                          float* __restrict__ out, int M) {
    __shared__ float sA[4][CSd];
    int n0 = blockIdx.x * 4, tid = threadIdx.x;
    for (int t = tid; t < 4 * CSd; t += blockDim.x)
        sA[t / CSd][t % CSd] = A[(n0 + t / CSd) * CSd + (t % CSd)];
    __syncthreads();
    if (tid < M) {
        float a0 = 0.f, a1 = 0.f, a2 = 0.f, a3 = 0.f;
        for (int k2 = 0; k2 < CSd; k2++) {
            float w = W[k2 * M + tid];
            a0 += sA[0][k2] * w; a1 += sA[1][k2] * w;
            a2 += sA[2][k2] * w; a3 += sA[3][k2] * w;
        }
        out[(n0 + 0) * M + tid] = a0;
        out[(n0 + 1) * M + tid] = a1;
        out[(n0 + 2) * M + tid] = a2;
        out[(n0 + 3) * M + tid] = a3;
    }
}

// ---------------- global frames: g* = rot @ p + trans ----------------
__global__ void frames_k(const float* __restrict__ rot, const float* __restrict__ trans) {
    int idx = blockIdx.x * blockDim.x + threadIdx.x;
    const int NQ = Nn * Hh * PQd;               // 24576
    const int total = 2 * NQ + Nn * Hh * PVd;   // 73728... + gv
    if (idx >= total) return;
    const float* src; float* dst; int per;
    if (idx < NQ)            { src = g_qp; dst = g_gq; per = Hh * PQd; }
    else if (idx < 2 * NQ)   { idx -= NQ; src = g_kp; dst = g_gk; per = Hh * PQd; }
    else                     { idx -= 2 * NQ; src = g_vp; dst = g_gv; per = Hh * PVd; }
    int n = idx / per, e = idx % per;
    float b0 = src[(n * per + e) * 3 + 0];
    float b1 = src[(n * per + e) * 3 + 1];
    float b2 = src[(n * per + e) * 3 + 2];
    #pragma unroll
    for (int a = 0; a < 3; a++) {
        dst[(n * per + e) * 3 + a] =
            rot[n * 9 + a * 3 + 0] * b0 + rot[n * 9 + a * 3 + 1] * b1 +
            rot[n * 9 + a * 3 + 2] * b2 + trans[n * 3 + a];
    }
}

__global__ void sq_k() {
    int idx = blockIdx.x * blockDim.x + threadIdx.x;
    if (idx >= Nn * Hh * 2) return;
    int which = idx / (Nn * Hh);
    int r = idx % (Nn * Hh);
    const float* g = which ? g_gk : g_gq;
    float s = 0.f;
    #pragma unroll
    for (int e = 0; e < 12; e++) { float x = g[r * 12 + e]; s += x * x; }
    (which ? g_sqk : g_sqq)[r] = s;
}

// ---------------- fused logits: qk + bias(pair@Wb) - 0.5*WC*gamma*d2 ----------------
__global__ void logits_k(const float* __restrict__ pair, const float* __restrict__ Wb,
                         const float* __restrict__ gamma_raw) {
    __shared__ float pairS[64][129];
    __shared__ float WbS[CZd * Hh];
    __shared__ float qS[Hh * Cc], gqS[Hh * 12], sqqS[Hh], gamS[Hh];
    int i = blockIdx.x, j0 = blockIdx.y * 64, tid = threadIdx.x;

    for (int t = tid; t < 64 * CZd; t += 256) {
        int jl = t >> 7, z = t & 127;
        pairS[jl][z] = pair[(size_t)(i * Nn + j0 + jl) * CZd + z];
    }
    for (int t = tid; t < CZd * Hh; t += 256) WbS[t] = Wb[t];
    for (int t = tid; t < Hh * Cc; t += 256) qS[t] = g_q[i * Hh * Cc + t];
    for (int t = tid; t < Hh * 12; t += 256) gqS[t] = g_gq[i * Hh * 12 + t];
    if (tid < Hh) {
        sqqS[tid] = g_sqq[i * Hh + tid];
        float x = gamma_raw[tid];
        gamS[tid] = (x > 20.f) ? x : log1pf(expf(x));
    }
    __syncthreads();

    const float WLc = 0.5773502691896258f;   // sqrt(1/3)
    const float WCc = 0.23570226039551584f;  // sqrt(2/(9*PQ)) = sqrt(1/18)
    for (int t = tid; t < 64 * Hh; t += 256) {
        int jl = t / Hh, h = t % Hh;
        int j = j0 + jl;
        float bias = 0.f;
        #pragma unroll 8
        for (int z = 0; z < CZd; z++) bias += pairS[jl][z] * WbS[z * Hh + h];
        float qk = 0.f;
        const float* kr = &g_k[(j * Hh + h) * Cc];
        #pragma unroll
        for (int c = 0; c < Cc; c++) qk += qS[h * Cc + c] * kr[c];
        qk *= 0.25f;  // C^{-1/2}
        float cross = 0.f;
        const float* gkr = &g_gk[(j * Hh + h) * 12];
        #pragma unroll
        for (int r = 0; r < 12; r++) cross += gqS[h * 12 + r] * gkr[r];
        float d2 = sqqS[h] + g_sqk[j * Hh + h] - 2.f * cross;
        g_logits[(size_t)(i * Hh + h) * Nn + j] = WLc * (qk + bias - 0.5f * WCc * gamS[h] * d2);
    }
}

// ---------------- softmax over j, in place ----------------
__global__ void softmax_k() {
    int r = blockIdx.x;
    float* L = &g_logits[(size_t)r * Nn];
    __shared__ float red[256];
    int tid = threadIdx.x;
    float m = -1e30f;
    for (int j = tid; j < Nn; j += 256) m = fmaxf(m, L[j]);
    red[tid] = m; __syncthreads();
    for (int s = 128; s > 0; s >>= 1) {
        if (tid < s) red[tid] = fmaxf(red[tid], red[tid + s]);
        __syncthreads();
    }
    m = red[0]; __syncthreads();
    float sum = 0.f;
    for (int j = tid; j < Nn; j += 256) { float e = expf(L[j] - m); L[j] = e; sum += e; }
    red[tid] = sum; __syncthreads();
    for (int s = 128; s > 0; s >>= 1) {
        if (tid < s) red[tid] += red[tid + s];
        __syncthreads();
    }
    float inv = 1.f / red[0];
    __syncthreads();
    for (int j = tid; j < Nn; j += 256) L[j] *= inv;
}

// ---------------- fused output accumulation per query row i ----------------
// cells: [0,1536) o_pair(h,z) ; [1536,1728) o_v(h,c) ; [1728,2016) o_pt(h,p,a)
__global__ void accum_k(const float* __restrict__ pair, const float* __restrict__ rot,
                        const float* __restrict__ trans) {
    __shared__ float pairS[32][132];
    __shared__ float aT[Hh][32];
    __shared__ float optS[Hh * PVd * 3];
    int i = blockIdx.x, tid = threadIdx.x;
    float acc[8];
    #pragma unroll
    for (int s = 0; s < 8; s++) acc[s] = 0.f;

    for (int jt = 0; jt < 16; jt++) {
        int j0 = jt * 32;
        __syncthreads();
        for (int t = tid; t < 32 * CZd; t += 256) {
            int jl = t >> 7, z = t & 127;
            pairS[jl][z] = pair[(size_t)(i * Nn + j0 + jl) * CZd + z];
        }
        for (int t = tid; t < Hh * 32; t += 256) {
            int h = t >> 5, jl = t & 31;
            aT[h][jl] = g_logits[(size_t)(i * Hh + h) * Nn + j0 + jl];
        }
        __syncthreads();
        #pragma unroll
        for (int s = 0; s < 8; s++) {
            int c = s * 256 + tid;
            if (c < 1536) {
                int h = c >> 7, z = c & 127;
                float a2 = acc[s];
                #pragma unroll 8
                for (int jl = 0; jl < 32; jl++) a2 += aT[h][jl] * pairS[jl][z];
                acc[s] = a2;
            } else if (c < 1728) {
                int o = c - 1536, h = o >> 4, ch = o & 15;
                float a2 = acc[s];
                for (int jl = 0; jl < 32; jl++)
                    a2 += aT[h][jl] * g_v[((j0 + jl) * Hh + h) * Cc + ch];
                acc[s] = a2;
            } else if (c < 2016) {
                int o = c - 1728, h = o / 24, rr = o % 24;
                float a2 = acc[s];
                for (int jl = 0; jl < 32; jl++)
                    a2 += aT[h][jl] * g_gv[(j0 + jl) * (Hh * PVd * 3) + h * 24 + rr];
                acc[s] = a2;
            }
        }
    }
    __syncthreads();
    float* crow = &g_concat[(size_t)i * OUTD];
    #pragma unroll
    for (int s = 0; s < 8; s++) {
        int c = s * 256 + tid;
        if (c < 1536)        crow[576 + c] = acc[s];        // o_pair at offset 576
        else if (c < 1728)   crow[c - 1536] = acc[s];       // o_v at offset 0
        else if (c < 2016)   optS[c - 1728] = acc[s];       // o_pt staged
    }
    __syncthreads();
    if (tid < Hh * PVd) {
        int base = tid * 3;  // optS laid out h*24+p*3+a == tid*3+a
        float b0 = optS[base + 0] - trans[i * 3 + 0];
        float b1 = optS[base + 1] - trans[i * 3 + 1];
        float b2 = optS[base + 2] - trans[i * 3 + 2];
        // local[a] = sum_b rot[b][a] * x[b]  (rot transpose)
        float l0 = rot[i * 9 + 0] * b0 + rot[i * 9 + 3] * b1 + rot[i * 9 + 6] * b2;
        float l1 = rot[i * 9 + 1] * b0 + rot[i * 9 + 4] * b1 + rot[i * 9 + 7] * b2;
        float l2 = rot[i * 9 + 2] * b0 + rot[i * 9 + 5] * b1 + rot[i * 9 + 8] * b2;
        crow[192 + tid * 3 + 0] = l0;
        crow[192 + tid * 3 + 1] = l1;
        crow[192 + tid * 3 + 2] = l2;
        crow[480 + tid] = sqrtf(l0 * l0 + l1 * l1 + l2 * l2 + 1e-8f);
    }
}

// ---------------- ipa_out = concat @ Wo + bo ; residual ; LN1 (4 rows/block) ----------------
__global__ void ipa_ln1_k(const float* __restrict__ single_in, const float* __restrict__ Wo,
                          const float* __restrict__ bo, const float* __restrict__ g,
                          const float* __restrict__ b) {
    __shared__ float cS[4][OUTD];
    __shared__ float red[512];
    int n0 = blockIdx.x * 4, tid = threadIdx.x;
    for (int t = tid; t < 4 * OUTD; t += 384)
        cS[t / OUTD][t % OUTD] = g_concat[(size_t)(n0 + t / OUTD) * OUTD + (t % OUTD)];
    __syncthreads();
    float a0 = bo[tid], a1 = a0, a2 = a0, a3 = a0;
    for (int d = 0; d < OUTD; d++) {
        float w = Wo[(size_t)d * CSd + tid];
        a0 += cS[0][d] * w; a1 += cS[1][d] * w;
        a2 += cS[2][d] * w; a3 += cS[3][d] * w;
    }
    float x[4];
    x[0] = single_in[(n0 + 0) * CSd + tid] + a0;
    x[1] = single_in[(n0 + 1) * CSd + tid] + a1;
    x[2] = single_in[(n0 + 2) * CSd + tid] + a2;
    x[3] = single_in[(n0 + 3) * CSd + tid] + a3;
    for (int r = 0; r < 4; r++) {
        float mean = blockSum384(x[r], red) * (1.f / CSd);
        float dx = x[r] - mean;
        float var = blockSum384(dx * dx, red) * (1.f / CSd);
        g_s1[(n0 + r) * CSd + tid] = dx * rsqrtf(var + 1e-5f) * g[tid] + b[tid];
    }
}

// ---------------- FFN relu layer (4 rows/block) ----------------
__global__ void ffn_relu_k(const float* __restrict__ in, const float* __restrict__ W,
                           const float* __restrict__ b, float* __restrict__ out) {
    __shared__ float sA[4][CSd];
    int n0 = blockIdx.x * 4, tid = threadIdx.x;
    for (int t = tid; t < 4 * CSd; t += 384)
        sA[t / CSd][t % CSd] = in[(n0 + t / CSd) * CSd + (t % CSd)];
    __syncthreads();
    float a0 = b[tid], a1 = a0, a2 = a0, a3 = a0;
    for (int k2 = 0; k2 < CSd; k2++) {
        float w = W[k2 * CSd + tid];
        a0 += sA[0][k2] * w; a1 += sA[1][k2] * w;
        a2 += sA[2][k2] * w; a3 += sA[3][k2] * w;
    }
    out[(n0 + 0) * CSd + tid] = fmaxf(a0, 0.f);
    out[(n0 + 1) * CSd + tid] = fmaxf(a1, 0.f);
    out[(n0 + 2) * CSd + tid] = fmaxf(a2, 0.f);
    out[(n0 + 3) * CSd + tid] = fmaxf(a3, 0.f);
}

// ---------------- FFN third layer + residual + LN2 -> d_out and g_s2 ----------------
__global__ void ffn3_ln2_k(const float* __restrict__ W3, const float* __restrict__ b3,
                           const float* __restrict__ g, const float* __restrict__ bb,
                           float* __restrict__ out) {
    __shared__ float sA[4][CSd];
    __shared__ float red[512];
    int n0 = blockIdx.x * 4, tid = threadIdx.x;
    for (int t = tid; t < 4 * CSd; t += 384)
        sA[t / CSd][t % CSd] = g_h2[(n0 + t / CSd) * CSd + (t % CSd)];
    __syncthreads();
    float a0 = b3[tid], a1 = a0, a2 = a0, a3 = a0;
    for (int k2 = 0; k2 < CSd; k2++) {
        float w = W3[k2 * CSd + tid];
        a0 += sA[0][k2] * w; a1 += sA[1][k2] * w;
        a2 += sA[2][k2] * w; a3 += sA[3][k2] * w;
    }
    float x[4];
    x[0] = g_s1[(n0 + 0) * CSd + tid] + a0;
    x[1] = g_s1[(n0 + 1) * CSd + tid] + a1;
    x[2] = g_s1[(n0 + 2) * CSd + tid] + a2;
    x[3] = g_s1[(n0 + 3) * CSd + tid] + a3;
    for (int r = 0; r < 4; r++) {
        float mean = blockSum384(x[r], red) * (1.f / CSd);
        float dx = x[r] - mean;
        float var = blockSum384(dx * dx, red) * (1.f / CSd);
        float y = dx * rsqrtf(var + 1e-5f) * g[tid] + bb[tid];
        out[(n0 + r) * CSd + tid] = y;       // single output at offset 0
        g_s2[(n0 + r) * CSd + tid] = y;
    }
}

// ---------------- backbone update ----------------
__global__ void update_k(const float* __restrict__ rot, const float* __restrict__ trans,
                         const float* __restrict__ Wbu, const float* __restrict__ bbu,
                         float* __restrict__ out) {
    int n = blockIdx.x * blockDim.x + threadIdx.x;
    if (n >= Nn) return;
    float u[6];
    #pragma unroll
    for (int j = 0; j < 6; j++) u[j] = bbu[j];
    for (int s = 0; s < CSd; s++) {
        float x = g_s2[n * CSd + s];
        #pragma unroll
        for (int j = 0; j < 6; j++) u[j] += x * Wbu[s * 6 + j];
    }
    float b = u[0], c = u[1], d = u[2];
    float inq = rsqrtf(1.f + b * b + c * c + d * d);
    float a = inq; b *= inq; c *= inq; d *= inq;
    float R[9] = {
        a * a + b * b - c * c - d * d, 2.f * (b * c - a * d),         2.f * (b * d + a * c),
        2.f * (b * c + a * d),         a * a - b * b + c * c - d * d, 2.f * (c * d - a * b),
        2.f * (b * d - a * c),         2.f * (c * d + a * b),         a * a - b * b - c * c + d * d };
    float rn[9];
    #pragma unroll
    for (int aa = 0; aa < 3; aa++)
        #pragma unroll
        for (int cc = 0; cc < 3; cc++) {
            float s2 = 0.f;
            #pragma unroll
            for (int bbx = 0; bbx < 3; bbx++) s2 += rot[n * 9 + aa * 3 + bbx] * R[bbx * 3 + cc];
            rn[aa * 3 + cc] = s2;
        }
    float t0 = u[3], t1 = u[4], t2 = u[5];
    float tn[3];
    #pragma unroll
    for (int aa = 0; aa < 3; aa++)
        tn[aa] = rot[n * 9 + aa * 3 + 0] * t0 + rot[n * 9 + aa * 3 + 1] * t1 +
                 rot[n * 9 + aa * 3 + 2] * t2 + trans[n * 3 + aa];
    #pragma unroll
    for (int e = 0; e < 9; e++) { g_rotn[n * 9 + e] = rn[e]; out[Nn * CSd + n * 9 + e] = rn[e]; }
    #pragma unroll
    for (int e = 0; e < 3; e++) { g_trn[n * 3 + e] = tn[e]; out[Nn * CSd + Nn * 9 + n * 3 + e] = tn[e]; }
}

// ---------------- loss (two-stage deterministic reduction) ----------------
__global__ void loss_part_k(const float* __restrict__ rt, const float* __restrict__ tt) {
    int i = blockIdx.x, tid = threadIdx.x;
    __shared__ float red[256];
    float rn[9], rte[9], tni[3], tti[3];
    #pragma unroll
    for (int e = 0; e < 9; e++) { rn[e] = g_rotn[i * 9 + e]; rte[e] = rt[i * 9 + e]; }
    #pragma unroll
    for (int e = 0; e < 3; e++) { tni[e] = g_trn[i * 3 + e]; tti[e] = tt[i * 3 + e]; }
    float s = 0.f;
    for (int j = tid; j < Nn; j += 256) {
        float db0 = g_trn[j * 3 + 0] - tni[0];
        float db1 = g_trn[j * 3 + 1] - tni[1];
        float db2 = g_trn[j * 3 + 2] - tni[2];
        float dp0 = rn[0] * db0 + rn[3] * db1 + rn[6] * db2;
        float dp1 = rn[1] * db0 + rn[4] * db1 + rn[7] * db2;
        float dp2 = rn[2] * db0 + rn[5] * db1 + rn[8] * db2;
        float eb0 = tt[j * 3 + 0] - tti[0];
        float eb1 = tt[j * 3 + 1] - tti[1];
        float eb2 = tt[j * 3 + 2] - tti[2];
        float dt0 = rte[0] * eb0 + rte[3] * eb1 + rte[6] * eb2;
        float dt1 = rte[1] * eb0 + rte[4] * eb1 + rte[7] * eb2;
        float dt2 = rte[2] * eb0 + rte[5] * eb1 + rte[8] * eb2;
        float d0 = dp0 - dt0, d1 = dp1 - dt1, d2 = dp2 - dt2;
        float dd = sqrtf(d0 * d0 + d1 * d1 + d2 * d2 + 1e-12f);
        s += fminf(dd, 10.f);
    }
    red[tid] = s; __syncthreads();
    for (int st = 128; st > 0; st >>= 1) {
        if (tid < st) red[tid] += red[tid + st];
        __syncthreads();
    }
    if (tid == 0) g_partial[i] = red[0];
}

__global__ void loss_final_k(float* __restrict__ out) {
    __shared__ float red[512];
    int tid = threadIdx.x;
    red[tid] = g_partial[tid];
    __syncthreads();
    for (int s = 256; s > 0; s >>= 1) {
        if (tid < s) red[tid] += red[tid + s];
        __syncthreads();
    }
    if (tid == 0)
        out[Nn * CSd + Nn * 9 + Nn * 3] = red[0] / ((float)Nn * (float)Nn) * 0.1f;
}

// ---------------- launch ----------------
template <typename T>
static float* symaddr(T& sym) {
    void* p = nullptr;
    cudaGetSymbolAddress(&p, sym);
    return (float*)p;
}

extern "C" void kernel_launch(void* const* d_in, const int* in_sizes, int n_in,
                              void* d_out, int out_size) {
    const float* single     = (const float*)d_in[0];
    const float* pair       = (const float*)d_in[1];
    const float* rot        = (const float*)d_in[2];
    const float* trans      = (const float*)d_in[3];
    const float* rot_truth  = (const float*)d_in[4];
    const float* trans_truth= (const float*)d_in[5];
    const float* Wq  = (const float*)d_in[6];
    const float* Wk  = (const float*)d_in[7];
    const float* Wv  = (const float*)d_in[8];
    const float* Wqp = (const float*)d_in[9];
    const float* Wkp = (const float*)d_in[10];
    const float* Wvp = (const float*)d_in[11];
    const float* Wb  = (const float*)d_in[12];
    const float* Wo  = (const float*)d_in[13];
    const float* bo  = (const float*)d_in[14];
    const float* gamma_raw = (const float*)d_in[15];
    const float* ln1_g = (const float*)d_in[16];
    const float* ln1_b = (const float*)d_in[17];
    const float* ln2_g = (const float*)d_in[18];
    const float* ln2_b = (const float*)d_in[19];
    const float* W1 = (const float*)d_in[20];
    const float* b1 = (const float*)d_in[21];
    const float* W2 = (const float*)d_in[22];
    const float* b2 = (const float*)d_in[23];
    const float* W3 = (const float*)d_in[24];
    const float* b3 = (const float*)d_in[25];
    const float* Wbu = (const float*)d_in[26];
    const float* bbu = (const float*)d_in[27];
    float* out = (float*)d_out;

    float* pq  = symaddr(g_q);
    float* pk  = symaddr(g_k);
    float* pv  = symaddr(g_v);
    float* pqp = symaddr(g_qp);
    float* pkp = symaddr(g_kp);
    float* pvp = symaddr(g_vp);
    float* ps1 = symaddr(g_s1);
    float* ph1 = symaddr(g_h1);
    float* ph2 = symaddr(g_h2);

    rowgemm_k<<<Nn / 4, 192>>>(single, Wq,  pq,  192);
    rowgemm_k<<<Nn / 4, 192>>>(single, Wk,  pk,  192);
    rowgemm_k<<<Nn / 4, 192>>>(single, Wv,  pv,  192);
    rowgemm_k<<<Nn / 4, 144>>>(single, Wqp, pqp, 144);
    rowgemm_k<<<Nn / 4, 144>>>(single, Wkp, pkp, 144);
    rowgemm_k<<<Nn / 4, 288>>>(single, Wvp, pvp, 288);

    frames_k<<<(2 * Nn * Hh * PQd + Nn * Hh * PVd + 255) / 256, 256>>>(rot, trans);
    sq_k<<<(Nn * Hh * 2 + 255) / 256, 256>>>();

    logits_k<<<dim3(Nn, Nn / 64), 256>>>(pair, Wb, gamma_raw);
    softmax_k<<<Nn * Hh, 256>>>();
    accum_k<<<Nn, 256>>>(pair, rot, trans);

    ipa_ln1_k<<<Nn / 4, 384>>>(single, Wo, bo, ln1_g, ln1_b);
    ffn_relu_k<<<Nn / 4, 384>>>(ps1, W1, b1, ph1);
    ffn_relu_k<<<Nn / 4, 384>>>(ph1, W2, b2, ph2);
    ffn3_ln2_k<<<Nn / 4, 384>>>(W3, b3, ln2_g, ln2_b, out);

    update_k<<<(Nn + 127) / 128, 128>>>(rot, trans, Wbu, bbu, out);
    loss_part_k<<<Nn, 256>>>(rot_truth, trans_truth);
    loss_final_k<<<1, 512>>>(out);
}

// round 3
// speedup vs baseline: 1.8442x; 1.8442x over previous
#include <cuda_runtime.h>
#include <math.h>

#define Nn 512
#define CSd 384
#define CZd 128
#define Hh 12
#define Cc 16
#define PQd 4
#define PVd 8
#define OUTD 2112
#define PROJD 1152  // 192+192+192+144+144+288
// column offsets in fused projection
#define OQ 0
#define OK0 192
#define OV 384
#define OQP 576
#define OKP 720
#define OVP 864

__device__ float g_Wf[CSd * PROJD];
__device__ float g_proj[Nn * PROJD];
__device__ float g_gq[Nn * Hh * PQd * 3], g_gk[Nn * Hh * PQd * 3], g_gv[Nn * Hh * PVd * 3];
__device__ float g_E[Hh * Nn * 32], g_F[Hh * Nn * 32];
__device__ float g_logits[Nn * Hh * Nn];   // [i][h][j]; becomes attention after softmax
__device__ float g_concat[Nn * OUTD];
__device__ float g_opt[Nn * Hh * PVd * 3];
__device__ float g_wop[4 * Nn * CSd];
__device__ float g_s1[Nn * CSd], g_h1[Nn * CSd], g_h2[Nn * CSd], g_h3[Nn * CSd], g_s2[Nn * CSd];
__device__ float g_rotn[Nn * 9], g_trn[Nn * 3];
__device__ float g_partial[Nn];

#define WLc 0.5773502691896258f
#define WCc 0.23570226039551584f

// ---------------- fuse weights into [384][1152] ----------------
__global__ void fuse_w_k(const float* __restrict__ Wq, const float* __restrict__ Wk,
                         const float* __restrict__ Wv, const float* __restrict__ Wqp,
                         const float* __restrict__ Wkp, const float* __restrict__ Wvp) {
    int idx = blockIdx.x * blockDim.x + threadIdx.x;
    if (idx >= CSd * PROJD) return;
    int r = idx / PROJD, c = idx % PROJD;
    float v;
    if (c < 192)        v = Wq [r * 192 + c];
    else if (c < 384)   v = Wk [r * 192 + (c - 192)];
    else if (c < 576)   v = Wv [r * 192 + (c - 384)];
    else if (c < 720)   v = Wqp[r * 144 + (c - 576)];
    else if (c < 864)   v = Wkp[r * 144 + (c - 720)];
    else                v = Wvp[r * 288 + (c - 864)];
    g_Wf[idx] = v;
}

// ---------------- generic tiled SGEMM: C = A[MxK] * B[KxN] ----------------
template<int BM, int BN, int BK, int TM, int TN, bool BIAS, bool RELU, bool SPLITK>
__global__ void sgemm_k(const float* __restrict__ A, const float* __restrict__ B,
                        const float* __restrict__ bias, float* __restrict__ C,
                        int M, int N, int K, int KC) {
    __shared__ float As[BK][BM];
    __shared__ float Bs[BK][BN];
    int n0 = blockIdx.x * BN, m0 = blockIdx.y * BM;
    int kstart = SPLITK ? blockIdx.z * KC : 0;
    if (SPLITK) C += (size_t)blockIdx.z * M * N;
    int tid = threadIdx.x;
    int tr = tid / (BN / TN), tc = tid % (BN / TN);
    float acc[TM][TN];
    #pragma unroll
    for (int i = 0; i < TM; i++)
        #pragma unroll
        for (int j = 0; j < TN; j++) acc[i][j] = 0.f;
    int nsteps = KC / BK;
    int arow = tid / (BK / 4), akq = tid % (BK / 4);
    int bkr = tid / (BN / 4), bnq = tid % (BN / 4);
    for (int kt = 0; kt < nsteps; kt++) {
        int kb = kstart + kt * BK;
        float4 va = *(const float4*)&A[(size_t)(m0 + arow) * K + kb + akq * 4];
        As[akq * 4 + 0][arow] = va.x; As[akq * 4 + 1][arow] = va.y;
        As[akq * 4 + 2][arow] = va.z; As[akq * 4 + 3][arow] = va.w;
        *(float4*)&Bs[bkr][bnq * 4] = *(const float4*)&B[(size_t)(kb + bkr) * N + n0 + bnq * 4];
        __syncthreads();
        #pragma unroll
        for (int k = 0; k < BK; k++) {
            float ra[TM], rb[TN];
            #pragma unroll
            for (int i = 0; i < TM; i++) ra[i] = As[k][tr * TM + i];
            #pragma unroll
            for (int j = 0; j < TN; j++) rb[j] = Bs[k][tc * TN + j];
            #pragma unroll
            for (int i = 0; i < TM; i++)
                #pragma unroll
                for (int j = 0; j < TN; j++) acc[i][j] += ra[i] * rb[j];
        }
        __syncthreads();
    }
    #pragma unroll
    for (int i = 0; i < TM; i++) {
        int m = m0 + tr * TM + i;
        #pragma unroll
        for (int j = 0; j < TN; j++) {
            int n = n0 + tc * TN + j;
            float v = acc[i][j];
            if (BIAS) v += bias[n];
            if (RELU) v = fmaxf(v, 0.f);
            C[(size_t)m * N + n] = v;
        }
    }
}

// ---------------- frames ----------------
__global__ void frames_k(const float* __restrict__ rot, const float* __restrict__ trans) {
    int idx = blockIdx.x * blockDim.x + threadIdx.x;
    const int NQ = Nn * Hh * PQd;
    const int total = 2 * NQ + Nn * Hh * PVd;
    if (idx >= total) return;
    const float* src; float* dst; int per; int srcoff;
    if (idx < NQ)          { dst = g_gq; per = Hh * PQd; srcoff = OQP; }
    else if (idx < 2 * NQ) { idx -= NQ; dst = g_gk; per = Hh * PQd; srcoff = OKP; }
    else                   { idx -= 2 * NQ; dst = g_gv; per = Hh * PVd; srcoff = OVP; }
    int n = idx / per, e = idx % per;
    src = &g_proj[(size_t)n * PROJD + srcoff];
    float b0 = src[e * 3 + 0], b1 = src[e * 3 + 1], b2 = src[e * 3 + 2];
    #pragma unroll
    for (int a = 0; a < 3; a++) {
        dst[(n * per + e) * 3 + a] =
            rot[n * 9 + a * 3 + 0] * b0 + rot[n * 9 + a * 3 + 1] * b1 +
            rot[n * 9 + a * 3 + 2] * b2 + trans[n * 3 + a];
    }
}

// ---------------- build E/F factor rows (32-dim) ----------------
__global__ void ef_k(const float* __restrict__ gamma_raw) {
    int idx = blockIdx.x * blockDim.x + threadIdx.x;
    if (idx >= Hh * Nn) return;
    int n = idx & 511, h = idx >> 9;
    float x = gamma_raw[h];
    float gam = (x > 20.f) ? x : log1pf(expf(x));
    float wcg = WCc * gam;
    const float* q  = &g_proj[(size_t)n * PROJD + OQ  + h * Cc];
    const float* kk = &g_proj[(size_t)n * PROJD + OK0 + h * Cc];
    const float* gq = &g_gq[n * (Hh * 12) + h * 12];
    const float* gk = &g_gk[n * (Hh * 12) + h * 12];
    float sqq = 0.f, sqk = 0.f;
    #pragma unroll
    for (int e = 0; e < 12; e++) { sqq += gq[e] * gq[e]; sqk += gk[e] * gk[e]; }
    float* Er = &g_E[(size_t)idx * 32];
    float* Fr = &g_F[(size_t)idx * 32];
    #pragma unroll
    for (int c = 0; c < 16; c++) { Er[c] = 0.25f * q[c]; Fr[c] = kk[c]; }
    #pragma unroll
    for (int e = 0; e < 12; e++) { Er[16 + e] = wcg * gq[e]; Fr[16 + e] = gk[e]; }
    Er[28] = sqq; Er[29] = 1.f; Er[30] = 0.f; Er[31] = 0.f;
    Fr[28] = -0.5f * wcg; Fr[29] = -0.5f * wcg * sqk; Fr[30] = 0.f; Fr[31] = 0.f;
}

// ---------------- logit core: L[i][h][j] = WL * E_i . F_j ----------------
__global__ void core_k() {
    __shared__ float As[32][64], BsT[32][64];
    int h = blockIdx.z, i0 = blockIdx.y * 64, j0 = blockIdx.x * 64;
    int tid = threadIdx.x;
    const float* Eh = &g_E[((size_t)h * Nn + i0) * 32];
    const float* Fh = &g_F[((size_t)h * Nn + j0) * 32];
    for (int t = tid; t < 512; t += 256) {
        int row = t >> 3, d4 = t & 7;
        float4 v = *(const float4*)&Eh[row * 32 + d4 * 4];
        As[d4 * 4 + 0][row] = v.x; As[d4 * 4 + 1][row] = v.y;
        As[d4 * 4 + 2][row] = v.z; As[d4 * 4 + 3][row] = v.w;
        float4 w = *(const float4*)&Fh[row * 32 + d4 * 4];
        BsT[d4 * 4 + 0][row] = w.x; BsT[d4 * 4 + 1][row] = w.y;
        BsT[d4 * 4 + 2][row] = w.z; BsT[d4 * 4 + 3][row] = w.w;
    }
    __syncthreads();
    int tr = tid / 16, tc = tid % 16;
    float acc[4][4];
    #pragma unroll
    for (int i = 0; i < 4; i++)
        #pragma unroll
        for (int j = 0; j < 4; j++) acc[i][j] = 0.f;
    #pragma unroll
    for (int d = 0; d < 32; d++) {
        float ra[4], rb[4];
        #pragma unroll
        for (int i = 0; i < 4; i++) ra[i] = As[d][tr * 4 + i];
        #pragma unroll
        for (int j = 0; j < 4; j++) rb[j] = BsT[d][tc * 4 + j];
        #pragma unroll
        for (int i = 0; i < 4; i++)
            #pragma unroll
            for (int j = 0; j < 4; j++) acc[i][j] += ra[i] * rb[j];
    }
    #pragma unroll
    for (int i = 0; i < 4; i++)
        #pragma unroll
        for (int j = 0; j < 4; j++)
            g_logits[((size_t)(i0 + tr * 4 + i) * Hh + h) * Nn + j0 + tc * 4 + j] = WLc * acc[i][j];
}

// ---------------- fused pair-bias + softmax, one block per i ----------------
// dyn smem: WbS[1536] | logitS[12*520] | pairS[64*132] | comb[3*64*12] | red[32]
__global__ void bias_softmax_k(const float* __restrict__ pair, const float* __restrict__ Wb) {
    extern __shared__ float sm[];
    float* WbS    = sm;                 // 1536
    float* logitS = WbS + 1536;         // 6240
    float* pairS  = logitS + 6240;      // 8448
    float* comb   = pairS + 8448;       // 2304
    float* red    = comb + 2304;        // 32
    int i = blockIdx.x, tid = threadIdx.x;
    for (int t = tid; t < CZd * Hh; t += 256) WbS[t] = Wb[t];
    for (int t = tid; t < Hh * Nn; t += 256) {
        int h = t >> 9, j = t & 511;
        logitS[h * 520 + j] = g_logits[((size_t)i * Hh + h) * Nn + j];
    }
    int zq = tid >> 6;            // 0..3
    int pos = tid & 63;
    int hg = pos >> 4;            // 0..3 (3 h each)
    int jg = pos & 15;            // 0..15 (4 j each)
    for (int chunk = 0; chunk < 8; chunk++) {
        int j0 = chunk * 64;
        __syncthreads();
        for (int t = tid; t < 2048; t += 256) {
            int row = t >> 5, c4 = t & 31;
            *(float4*)&pairS[row * 132 + c4 * 4] =
                *(const float4*)&pair[((size_t)i * Nn + j0 + row) * CZd + c4 * 4];
        }
        __syncthreads();
        float acc[4][3];
        #pragma unroll
        for (int a = 0; a < 4; a++)
            #pragma unroll
            for (int b = 0; b < 3; b++) acc[a][b] = 0.f;
        int zbase = zq * 32;
        for (int z = zbase; z < zbase + 32; z++) {
            float pv[4], wv[3];
            #pragma unroll
            for (int a = 0; a < 4; a++) pv[a] = pairS[(jg * 4 + a) * 132 + z];
            #pragma unroll
            for (int b = 0; b < 3; b++) wv[b] = WbS[z * Hh + hg * 3 + b];
            #pragma unroll
            for (int a = 0; a < 4; a++)
                #pragma unroll
                for (int b = 0; b < 3; b++) acc[a][b] += pv[a] * wv[b];
        }
        if (zq > 0) {
            float* c = &comb[((zq - 1) * 64 + pos) * 12];
            #pragma unroll
            for (int a = 0; a < 4; a++)
                #pragma unroll
                for (int b = 0; b < 3; b++) c[a * 3 + b] = acc[a][b];
        }
        __syncthreads();
        if (zq == 0) {
            #pragma unroll
            for (int a = 0; a < 4; a++)
                #pragma unroll
                for (int b = 0; b < 3; b++) {
                    float s = acc[a][b] + comb[(0 * 64 + pos) * 12 + a * 3 + b]
                                        + comb[(1 * 64 + pos) * 12 + a * 3 + b]
                                        + comb[(2 * 64 + pos) * 12 + a * 3 + b];
                    logitS[(hg * 3 + b) * 520 + j0 + jg * 4 + a] += WLc * s;
                }
        }
    }
    __syncthreads();
    int lane = tid & 31, wid = tid >> 5;
    for (int h = 0; h < Hh; h++) {
        float* L = &logitS[h * 520];
        float x0 = L[2 * tid], x1 = L[2 * tid + 1];
        float m = fmaxf(x0, x1);
        #pragma unroll
        for (int off = 16; off; off >>= 1) m = fmaxf(m, __shfl_xor_sync(0xffffffffu, m, off));
        if (lane == 0) red[wid] = m;
        __syncthreads();
        m = red[0];
        #pragma unroll
        for (int w = 1; w < 8; w++) m = fmaxf(m, red[w]);
        float e0 = expf(x0 - m), e1 = expf(x1 - m);
        float s = e0 + e1;
        #pragma unroll
        for (int off = 16; off; off >>= 1) s += __shfl_xor_sync(0xffffffffu, s, off);
        __syncthreads();
        if (lane == 0) red[wid] = s;
        __syncthreads();
        float tot = red[0];
        #pragma unroll
        for (int w = 1; w < 8; w++) tot += red[w];
        float inv = 1.f / tot;
        L[2 * tid] = e0 * inv;
        L[2 * tid + 1] = e1 * inv;
        __syncthreads();
    }
    for (int t = tid; t < Hh * Nn; t += 256) {
        int h = t >> 9, j = t & 511;
        g_logits[((size_t)i * Hh + h) * Nn + j] = logitS[h * 520 + j];
    }
}

// ---------------- o_pair: per i, register-tiled [12h x 128z] over j ----------------
__global__ void accum_pair_k(const float* __restrict__ pair) {
    __shared__ float pairS[32 * 132];
    __shared__ float aS[12 * 33];
    __shared__ float comb[128 * 12];
    int i = blockIdx.x, tid = threadIdx.x;
    int jh = tid >> 7;            // 0/1
    int rem = tid & 127;
    int hg = rem >> 5;            // 0..3 (3 h)
    int zg = rem & 31;            // 0..31 (4 z)
    float acc[3][4];
    #pragma unroll
    for (int b = 0; b < 3; b++)
        #pragma unroll
        for (int a = 0; a < 4; a++) acc[b][a] = 0.f;
    for (int chunk = 0; chunk < 16; chunk++) {
        int j0 = chunk * 32;
        __syncthreads();
        for (int t = tid; t < 1024; t += 256) {
            int row = t >> 5, c4 = t & 31;
            *(float4*)&pairS[row * 132 + c4 * 4] =
                *(const float4*)&pair[((size_t)i * Nn + j0 + row) * CZd + c4 * 4];
        }
        for (int t = tid; t < 384; t += 256) {
            int h = t >> 5, jl = t & 31;
            aS[h * 33 + jl] = g_logits[((size_t)i * Hh + h) * Nn + j0 + jl];
        }
        __syncthreads();
        int jb = jh * 16;
        for (int l = 0; l < 16; l++) {
            int jl = jb + l;
            float4 pv = *(const float4*)&pairS[jl * 132 + zg * 4];
            float av[3];
            #pragma unroll
            for (int b = 0; b < 3; b++) av[b] = aS[(hg * 3 + b) * 33 + jl];
            #pragma unroll
            for (int b = 0; b < 3; b++) {
                acc[b][0] += av[b] * pv.x; acc[b][1] += av[b] * pv.y;
                acc[b][2] += av[b] * pv.z; acc[b][3] += av[b] * pv.w;
            }
        }
    }
    __syncthreads();
    if (jh == 1) {
        float* c = &comb[rem * 12];
        #pragma unroll
        for (int b = 0; b < 3; b++)
            #pragma unroll
            for (int a = 0; a < 4; a++) c[b * 4 + a] = acc[b][a];
    }
    __syncthreads();
    if (jh == 0) {
        const float* c = &comb[rem * 12];
        #pragma unroll
        for (int b = 0; b < 3; b++) {
            int h = hg * 3 + b;
            float4 v;
            v.x = acc[b][0] + c[b * 4 + 0];
            v.y = acc[b][1] + c[b * 4 + 1];
            v.z = acc[b][2] + c[b * 4 + 2];
            v.w = acc[b][3] + c[b * 4 + 3];
            *(float4*)&g_concat[(size_t)i * OUTD + 576 + h * CZd + zg * 4] = v;
        }
    }
}

// ---------------- o_v & o_pt: batched per-head GEMM [64i x 48c] ----------------
__global__ void ov_k() {
    __shared__ float As[64 * 33];
    __shared__ float Bs[32 * 49];
    int i0 = blockIdx.x * 64, h = blockIdx.y;
    int tid = threadIdx.x;
    int tr = tid / 16, tc = tid % 16;   // tr: 4 i each; tc: 3 c each
    float acc[4][3];
    #pragma unroll
    for (int a = 0; a < 4; a++)
        #pragma unroll
        for (int b = 0; b < 3; b++) acc[a][b] = 0.f;
    for (int chunk = 0; chunk < 16; chunk++) {
        int j0 = chunk * 32;
        __syncthreads();
        for (int t = tid; t < 2048; t += 256) {
            int il = t >> 5, jl = t & 31;
            As[il * 33 + jl] = g_logits[((size_t)(i0 + il) * Hh + h) * Nn + j0 + jl];
        }
        for (int t = tid; t < 1536; t += 256) {
            int jl = t / 48, c = t % 48;
            float v = 0.f;
            if (c < 16)      v = g_proj[(size_t)(j0 + jl) * PROJD + OV + h * Cc + c];
            else if (c < 40) v = g_gv[(j0 + jl) * (Hh * 24) + h * 24 + (c - 16)];
            Bs[jl * 49 + c] = v;
        }
        __syncthreads();
        for (int jl = 0; jl < 32; jl++) {
            float ra[4], rb[3];
            #pragma unroll
            for (int a = 0; a < 4; a++) ra[a] = As[(tr * 4 + a) * 33 + jl];
            #pragma unroll
            for (int b = 0; b < 3; b++) rb[b] = Bs[jl * 49 + tc * 3 + b];
            #pragma unroll
            for (int a = 0; a < 4; a++)
                #pragma unroll
                for (int b = 0; b < 3; b++) acc[a][b] += ra[a] * rb[b];
        }
    }
    #pragma unroll
    for (int a = 0; a < 4; a++) {
        int i = i0 + tr * 4 + a;
        #pragma unroll
        for (int b = 0; b < 3; b++) {
            int c = tc * 3 + b;
            if (c < 16)      g_concat[(size_t)i * OUTD + h * Cc + c] = acc[a][b];
            else if (c < 40) g_opt[i * (Hh * 24) + h * 24 + (c - 16)] = acc[a][b];
        }
    }
}

// ---------------- o_pt -> local frame + norms into concat ----------------
__global__ void post_pt_k(const float* __restrict__ rot, const float* __restrict__ trans) {
    int idx = blockIdx.x * blockDim.x + threadIdx.x;
    if (idx >= Nn * Hh * PVd) return;
    int i = idx / (Hh * PVd), t = idx % (Hh * PVd);
    float b0 = g_opt[i * (Hh * 24) + t * 3 + 0] - trans[i * 3 + 0];
    float b1 = g_opt[i * (Hh * 24) + t * 3 + 1] - trans[i * 3 + 1];
    float b2 = g_opt[i * (Hh * 24) + t * 3 + 2] - trans[i * 3 + 2];
    float l0 = rot[i * 9 + 0] * b0 + rot[i * 9 + 3] * b1 + rot[i * 9 + 6] * b2;
    float l1 = rot[i * 9 + 1] * b0 + rot[i * 9 + 4] * b1 + rot[i * 9 + 7] * b2;
    float l2 = rot[i * 9 + 2] * b0 + rot[i * 9 + 5] * b1 + rot[i * 9 + 8] * b2;
    float* crow = &g_concat[(size_t)i * OUTD];
    crow[192 + t * 3 + 0] = l0;
    crow[192 + t * 3 + 1] = l1;
    crow[192 + t * 3 + 2] = l2;
    crow[480 + t] = sqrtf(l0 * l0 + l1 * l1 + l2 * l2 + 1e-8f);
}

// ---------------- layer norms ----------------
__device__ __forceinline__ float blockSum384(float v, float* red) {
    int tid = threadIdx.x;
    red[tid] = v;
    if (tid < 128) red[384 + tid] = 0.f;
    __syncthreads();
    for (int s = 256; s > 0; s >>= 1) {
        if (tid < s) red[tid] += red[tid + s];
        __syncthreads();
    }
    float r = red[0];
    __syncthreads();
    return r;
}

__global__ void ln1_k(const float* __restrict__ single_in, const float* __restrict__ bo,
                      const float* __restrict__ g, const float* __restrict__ b) {
    __shared__ float red[512];
    int row = blockIdx.x, tid = threadIdx.x;
    float x = single_in[row * CSd + tid] + bo[tid];
    #pragma unroll
    for (int z = 0; z < 4; z++) x += g_wop[(size_t)z * Nn * CSd + row * CSd + tid];
    float mean = blockSum384(x, red) * (1.f / CSd);
    float dx = x - mean;
    float var = blockSum384(dx * dx, red) * (1.f / CSd);
    g_s1[row * CSd + tid] = dx * rsqrtf(var + 1e-5f) * g[tid] + b[tid];
}

__global__ void ln2_k(const float* __restrict__ g, const float* __restrict__ b,
                      float* __restrict__ out) {
    __shared__ float red[512];
    int row = blockIdx.x, tid = threadIdx.x;
    float x = g_s1[row * CSd + tid] + g_h3[row * CSd + tid];
    float mean = blockSum384(x, red) * (1.f / CSd);
    float dx = x - mean;
    float var = blockSum384(dx * dx, red) * (1.f / CSd);
    float y = dx * rsqrtf(var + 1e-5f) * g[tid] + b[tid];
    out[row * CSd + tid] = y;
    g_s2[row * CSd + tid] = y;
}

// ---------------- backbone update ----------------
__global__ void update_k(const float* __restrict__ rot, const float* __restrict__ trans,
                         const float* __restrict__ Wbu, const float* __restrict__ bbu,
                         float* __restrict__ out) {
    int n = blockIdx.x * blockDim.x + threadIdx.x;
    if (n >= Nn) return;
    float u[6];
    #pragma unroll
    for (int j = 0; j < 6; j++) u[j] = bbu[j];
    for (int s = 0; s < CSd; s++) {
        float x = g_s2[n * CSd + s];
        #pragma unroll
        for (int j = 0; j < 6; j++) u[j] += x * Wbu[s * 6 + j];
    }
    float b = u[0], c = u[1], d = u[2];
    float inq = rsqrtf(1.f + b * b + c * c + d * d);
    float a = inq; b *= inq; c *= inq; d *= inq;
    float R[9] = {
        a*a + b*b - c*c - d*d, 2.f*(b*c - a*d),       2.f*(b*d + a*c),
        2.f*(b*c + a*d),       a*a - b*b + c*c - d*d, 2.f*(c*d - a*b),
        2.f*(b*d - a*c),       2.f*(c*d + a*b),       a*a - b*b - c*c + d*d };
    float rn[9];
    #pragma unroll
    for (int aa = 0; aa < 3; aa++)
        #pragma unroll
        for (int cc = 0; cc < 3; cc++) {
            float s2 = 0.f;
            #pragma unroll
            for (int bx = 0; bx < 3; bx++) s2 += rot[n * 9 + aa * 3 + bx] * R[bx * 3 + cc];
            rn[aa * 3 + cc] = s2;
        }
    float t0 = u[3], t1 = u[4], t2 = u[5];
    float tn[3];
    #pragma unroll
    for (int aa = 0; aa < 3; aa++)
        tn[aa] = rot[n * 9 + aa * 3 + 0] * t0 + rot[n * 9 + aa * 3 + 1] * t1 +
                 rot[n * 9 + aa * 3 + 2] * t2 + trans[n * 3 + aa];
    #pragma unroll
    for (int e = 0; e < 9; e++) { g_rotn[n * 9 + e] = rn[e]; out[Nn * CSd + n * 9 + e] = rn[e]; }
    #pragma unroll
    for (int e = 0; e < 3; e++) { g_trn[n * 3 + e] = tn[e]; out[Nn * CSd + Nn * 9 + n * 3 + e] = tn[e]; }
}

// ---------------- loss ----------------
__global__ void loss_part_k(const float* __restrict__ rt, const float* __restrict__ tt) {
    int i = blockIdx.x, tid = threadIdx.x;
    __shared__ float red[256];
    float rn[9], rte[9], tni[3], tti[3];
    #pragma unroll
    for (int e = 0; e < 9; e++) { rn[e] = g_rotn[i * 9 + e]; rte[e] = rt[i * 9 + e]; }
    #pragma unroll
    for (int e = 0; e < 3; e++) { tni[e] = g_trn[i * 3 + e]; tti[e] = tt[i * 3 + e]; }
    float s = 0.f;
    for (int j = tid; j < Nn; j += 256) {
        float db0 = g_trn[j * 3 + 0] - tni[0];
        float db1 = g_trn[j * 3 + 1] - tni[1];
        float db2 = g_trn[j * 3 + 2] - tni[2];
        float dp0 = rn[0] * db0 + rn[3] * db1 + rn[6] * db2;
        float dp1 = rn[1] * db0 + rn[4] * db1 + rn[7] * db2;
        float dp2 = rn[2] * db0 + rn[5] * db1 + rn[8] * db2;
        float eb0 = tt[j * 3 + 0] - tti[0];
        float eb1 = tt[j * 3 + 1] - tti[1];
        float eb2 = tt[j * 3 + 2] - tti[2];
        float dt0 = rte[0] * eb0 + rte[3] * eb1 + rte[6] * eb2;
        float dt1 = rte[1] * eb0 + rte[4] * eb1 + rte[7] * eb2;
        float dt2 = rte[2] * eb0 + rte[5] * eb1 + rte[8] * eb2;
        float d0 = dp0 - dt0, d1 = dp1 - dt1, d2 = dp2 - dt2;
        float dd = sqrtf(d0 * d0 + d1 * d1 + d2 * d2 + 1e-12f);
        s += fminf(dd, 10.f);
    }
    red[tid] = s; __syncthreads();
    for (int st = 128; st > 0; st >>= 1) {
        if (tid < st) red[tid] += red[tid + st];
        __syncthreads();
    }
    if (tid == 0) g_partial[i] = red[0];
}

__global__ void loss_final_k(float* __restrict__ out) {
    __shared__ float red[512];
    int tid = threadIdx.x;
    red[tid] = g_partial[tid];
    __syncthreads();
    for (int s = 256; s > 0; s >>= 1) {
        if (tid < s) red[tid] += red[tid + s];
        __syncthreads();
    }
    if (tid == 0)
        out[Nn * CSd + Nn * 9 + Nn * 3] = red[0] / ((float)Nn * (float)Nn) * 0.1f;
}

// ---------------- host ----------------
template <typename T>
static float* symaddr(T& sym) {
    void* p = nullptr;
    cudaGetSymbolAddress(&p, sym);
    return (float*)p;
}

extern "C" void kernel_launch(void* const* d_in, const int* in_sizes, int n_in,
                              void* d_out, int out_size) {
    const float* single      = (const float*)d_in[0];
    const float* pair        = (const float*)d_in[1];
    const float* rot         = (const float*)d_in[2];
    const float* trans       = (const float*)d_in[3];
    const float* rot_truth   = (const float*)d_in[4];
    const float* trans_truth = (const float*)d_in[5];
    const float* Wq  = (const float*)d_in[6];
    const float* Wk  = (const float*)d_in[7];
    const float* Wv  = (const float*)d_in[8];
    const float* Wqp = (const float*)d_in[9];
    const float* Wkp = (const float*)d_in[10];
    const float* Wvp = (const float*)d_in[11];
    const float* Wb  = (const float*)d_in[12];
    const float* Wo  = (const float*)d_in[13];
    const float* bo  = (const float*)d_in[14];
    const float* gamma_raw = (const float*)d_in[15];
    const float* ln1_g = (const float*)d_in[16];
    const float* ln1_b = (const float*)d_in[17];
    const float* ln2_g = (const float*)d_in[18];
    const float* ln2_b = (const float*)d_in[19];
    const float* W1 = (const float*)d_in[20];
    const float* b1 = (const float*)d_in[21];
    const float* W2 = (const float*)d_in[22];
    const float* b2 = (const float*)d_in[23];
    const float* W3 = (const float*)d_in[24];
    const float* b3 = (const float*)d_in[25];
    const float* Wbu = (const float*)d_in[26];
    const float* bbu = (const float*)d_in[27];
    float* out = (float*)d_out;

    float* pWf     = symaddr(g_Wf);
    float* pProj   = symaddr(g_proj);
    float* pConcat = symaddr(g_concat);
    float* pWop    = symaddr(g_wop);
    float* pS1     = symaddr(g_s1);
    float* pH1     = symaddr(g_h1);
    float* pH2     = symaddr(g_h2);
    float* pH3     = symaddr(g_h3);

    cudaFuncSetAttribute(bias_softmax_k, cudaFuncAttributeMaxDynamicSharedMemorySize, 76000);

    fuse_w_k<<<(CSd * PROJD + 255) / 256, 256>>>(Wq, Wk, Wv, Wqp, Wkp, Wvp);

    // projections: [512x384] @ [384x1152]
    sgemm_k<64,64,16,4,4,false,false,false><<<dim3(PROJD/64, Nn/64, 1), 256>>>(
        single, pWf, nullptr, pProj, Nn, PROJD, CSd, CSd);

    frames_k<<<(2 * Nn * Hh * PQd + Nn * Hh * PVd + 255) / 256, 256>>>(rot, trans);
    ef_k<<<(Hh * Nn + 255) / 256, 256>>>(gamma_raw);
    core_k<<<dim3(Nn/64, Nn/64, Hh), 256>>>();

    bias_softmax_k<<<Nn, 256, 76000>>>(pair, Wb);
    accum_pair_k<<<Nn, 256>>>(pair);
    ov_k<<<dim3(Nn/64, Hh), 256>>>();
    post_pt_k<<<(Nn * Hh * PVd + 255) / 256, 256>>>(rot, trans);

    // Wo split-K=4: [512x2112] @ [2112x384] -> 4 partials
    sgemm_k<64,64,16,4,4,false,false,true><<<dim3(CSd/64, Nn/64, 4), 256>>>(
        pConcat, Wo, nullptr, pWop, Nn, CSd, OUTD, OUTD/4);
    ln1_k<<<Nn, CSd>>>(single, bo, ln1_g, ln1_b);

    sgemm_k<64,64,16,4,4,true,true,false><<<dim3(CSd/64, Nn/64, 1), 256>>>(
        pS1, W1, b1, pH1, Nn, CSd, CSd, CSd);
    sgemm_k<64,64,16,4,4,true,true,false><<<dim3(CSd/64, Nn/64, 1), 256>>>(
        pH1, W2, b2, pH2, Nn, CSd, CSd, CSd);
    sgemm_k<64,64,16,4,4,true,false,false><<<dim3(CSd/64, Nn/64, 1), 256>>>(
        pH2, W3, b3, pH3, Nn, CSd, CSd, CSd);
    ln2_k<<<Nn, CSd>>>(ln2_g, ln2_b, out);

    update_k<<<(Nn + 127) / 128, 128>>>(rot, trans, Wbu, bbu, out);
    loss_part_k<<<Nn, 256>>>(rot_truth, trans_truth);
    loss_final_k<<<1, 512>>>(out);
}

// round 4
// speedup vs baseline: 2.2874x; 1.2403x over previous
#include <cuda_runtime.h>
#include <math.h>

#define Nn 512
#define CSd 384
#define CZd 128
#define Hh 12
#define Cc 16
#define PQd 4
#define PVd 8
#define OUTD 2112
#define PROJD 1152
#define OQ 0
#define OK0 192
#define OV 384
#define OQP 576
#define OKP 720
#define OVP 864

__device__ float g_Wf[CSd * PROJD];
__device__ float g_proj[Nn * PROJD];
__device__ float g_gv[Nn * Hh * PVd * 3];
__device__ float g_E[Hh * Nn * 32], g_F[Hh * Nn * 32];
__device__ float g_logits[Nn * Hh * Nn];
__device__ float g_concat[Nn * OUTD];
__device__ float g_opt[Nn * Hh * PVd * 3];
__device__ float g_wop[4 * Nn * CSd];
__device__ float g_s1[Nn * CSd], g_h1[Nn * CSd], g_h2[Nn * CSd], g_h3[Nn * CSd], g_s2[Nn * CSd];
__device__ float g_rotn[Nn * 9], g_trn[Nn * 3];
__device__ float g_partial[Nn];

#define WLc 0.5773502691896258f
#define WCc 0.23570226039551584f

__device__ __forceinline__ void cp16(void* smem_dst, const void* gmem_src) {
    unsigned s = (unsigned)__cvta_generic_to_shared(smem_dst);
    asm volatile("cp.async.cg.shared.global [%0], [%1], 16;" :: "r"(s), "l"(gmem_src));
}
__device__ __forceinline__ void cp_commit() { asm volatile("cp.async.commit_group;"); }
template<int N> __device__ __forceinline__ void cp_wait() {
    asm volatile("cp.async.wait_group %0;" :: "n"(N));
}

// ---------------- fuse weights ----------------
__global__ void fuse_w_k(const float* __restrict__ Wq, const float* __restrict__ Wk,
                         const float* __restrict__ Wv, const float* __restrict__ Wqp,
                         const float* __restrict__ Wkp, const float* __restrict__ Wvp) {
    int idx = blockIdx.x * blockDim.x + threadIdx.x;
    if (idx >= CSd * PROJD) return;
    int r = idx / PROJD, c = idx % PROJD;
    float v;
    if (c < 192)        v = Wq [r * 192 + c];
    else if (c < 384)   v = Wk [r * 192 + (c - 192)];
    else if (c < 576)   v = Wv [r * 192 + (c - 384)];
    else if (c < 720)   v = Wqp[r * 144 + (c - 576)];
    else if (c < 864)   v = Wkp[r * 144 + (c - 720)];
    else                v = Wvp[r * 288 + (c - 864)];
    g_Wf[idx] = v;
}

// ---------------- double-buffered tiled SGEMM ----------------
template<int BM, int BN, int BK, int TM, int TN, bool BIAS, bool RELU, bool SPLITK>
__global__ void sgemm_k(const float* __restrict__ A, const float* __restrict__ B,
                        const float* __restrict__ bias, float* __restrict__ C,
                        int M, int N, int K, int KC) {
    const int THREADS = (BM / TM) * (BN / TN);
    __shared__ float As[2][BK][BM];
    __shared__ float Bs[2][BK][BN + 4];
    int n0 = blockIdx.x * BN, m0 = blockIdx.y * BM;
    int kstart = SPLITK ? blockIdx.z * KC : 0;
    if (SPLITK) C += (size_t)blockIdx.z * M * N;
    int tid = threadIdx.x;
    int tr = tid / (BN / TN), tc = tid % (BN / TN);
    float acc[TM][TN];
    #pragma unroll
    for (int i = 0; i < TM; i++)
        #pragma unroll
        for (int j = 0; j < TN; j++) acc[i][j] = 0.f;
    int nsteps = KC / BK;

    auto loadA = [&](int kt, int buf) {
        #pragma unroll
        for (int r = tid; r < BM * BK / 4; r += THREADS) {
            int arow = r / (BK / 4), aq = r % (BK / 4);
            float4 v = *(const float4*)&A[(size_t)(m0 + arow) * K + kstart + kt * BK + aq * 4];
            As[buf][aq * 4 + 0][arow] = v.x; As[buf][aq * 4 + 1][arow] = v.y;
            As[buf][aq * 4 + 2][arow] = v.z; As[buf][aq * 4 + 3][arow] = v.w;
        }
    };
    auto loadB = [&](int kt, int buf) {
        #pragma unroll
        for (int r = tid; r < BK * BN / 4; r += THREADS) {
            int brow = r / (BN / 4), bq = r % (BN / 4);
            cp16(&Bs[buf][brow][bq * 4], &B[(size_t)(kstart + kt * BK + brow) * N + n0 + bq * 4]);
        }
    };
    loadA(0, 0); loadB(0, 0); cp_commit();
    for (int kt = 0; kt < nsteps; kt++) {
        int buf = kt & 1;
        if (kt + 1 < nsteps) {
            loadA(kt + 1, buf ^ 1); loadB(kt + 1, buf ^ 1); cp_commit();
            cp_wait<1>();
        } else cp_wait<0>();
        __syncthreads();
        #pragma unroll
        for (int k = 0; k < BK; k++) {
            float ra[TM], rb[TN];
            #pragma unroll
            for (int i = 0; i < TM; i += 4)
                *(float4*)&ra[i] = *(const float4*)&As[buf][k][tr * TM + i];
            #pragma unroll
            for (int j = 0; j < TN; j += 4)
                *(float4*)&rb[j] = *(const float4*)&Bs[buf][k][tc * TN + j];
            #pragma unroll
            for (int i = 0; i < TM; i++)
                #pragma unroll
                for (int j = 0; j < TN; j++) acc[i][j] += ra[i] * rb[j];
        }
        __syncthreads();
    }
    #pragma unroll
    for (int i = 0; i < TM; i++) {
        int m = m0 + tr * TM + i;
        #pragma unroll
        for (int j = 0; j < TN; j++) {
            int n = n0 + tc * TN + j;
            float v = acc[i][j];
            if (BIAS) v += bias[n];
            if (RELU) v = fmaxf(v, 0.f);
            C[(size_t)m * N + n] = v;
        }
    }
}

// ---------------- prep: frames + squared norms + E/F, one block per n ----------------
__global__ void prep_k(const float* __restrict__ rot, const float* __restrict__ trans,
                       const float* __restrict__ gamma_raw) {
    __shared__ float R[9], T[3], gqS[144], gkS[144], sqqS[12], sqkS[12], wcgS[12];
    int n = blockIdx.x, tid = threadIdx.x;
    if (tid < 9) R[tid] = rot[n * 9 + tid];
    if (tid < 3) T[tid] = trans[n * 3 + tid];
    if (tid >= 16 && tid < 28) {
        int h = tid - 16;
        float x = gamma_raw[h];
        wcgS[h] = WCc * ((x > 20.f) ? x : log1pf(expf(x)));
    }
    __syncthreads();
    const float* base = &g_proj[(size_t)n * PROJD];
    // gq (48 pts), gk (48 pts) -> smem only
    for (int t = tid; t < 96; t += 128) {
        int which = t / 48, p = t % 48;
        const float* src = base + (which ? OKP : OQP) + p * 3;
        float b0 = src[0], b1 = src[1], b2 = src[2];
        float* dst = (which ? gkS : gqS) + p * 3;
        #pragma unroll
        for (int a = 0; a < 3; a++)
            dst[a] = R[a * 3 + 0] * b0 + R[a * 3 + 1] * b1 + R[a * 3 + 2] * b2 + T[a];
    }
    // gv (96 pts) -> global
    for (int t = tid; t < 96; t += 128) {
        const float* src = base + OVP + t * 3;
        float b0 = src[0], b1 = src[1], b2 = src[2];
        #pragma unroll
        for (int a = 0; a < 3; a++)
            g_gv[n * 288 + t * 3 + a] =
                R[a * 3 + 0] * b0 + R[a * 3 + 1] * b1 + R[a * 3 + 2] * b2 + T[a];
    }
    __syncthreads();
    if (tid < 24) {
        int h = tid >> 1, which = tid & 1;
        const float* g = (which ? gkS : gqS) + h * 12;
        float s = 0.f;
        #pragma unroll
        for (int e = 0; e < 12; e++) s += g[e] * g[e];
        (which ? sqkS : sqqS)[h] = s;
    }
    __syncthreads();
    for (int t = tid; t < Hh * 32; t += 128) {
        int h = t >> 5, c = t & 31;
        float wcg = wcgS[h];
        float e, f;
        if (c < 16)      { e = 0.25f * base[OQ + h * 16 + c]; f = base[OK0 + h * 16 + c]; }
        else if (c < 28) { e = wcg * gqS[h * 12 + c - 16];    f = gkS[h * 12 + c - 16]; }
        else if (c == 28){ e = sqqS[h];                        f = -0.5f * wcg; }
        else if (c == 29){ e = 1.f;                            f = -0.5f * wcg * sqkS[h]; }
        else             { e = 0.f;                            f = 0.f; }
        g_E[(size_t)((h << 9) | n) * 32 + c] = e;
        g_F[(size_t)((h << 9) | n) * 32 + c] = f;
    }
}

// ---------------- logit core ----------------
__global__ void core_k() {
    __shared__ float As[32][64], BsT[32][64];
    int h = blockIdx.z, i0 = blockIdx.y * 64, j0 = blockIdx.x * 64;
    int tid = threadIdx.x;
    const float* Eh = &g_E[((size_t)h * Nn + i0) * 32];
    const float* Fh = &g_F[((size_t)h * Nn + j0) * 32];
    for (int t = tid; t < 512; t += 256) {
        int row = t >> 3, d4 = t & 7;
        float4 v = *(const float4*)&Eh[row * 32 + d4 * 4];
        As[d4 * 4 + 0][row] = v.x; As[d4 * 4 + 1][row] = v.y;
        As[d4 * 4 + 2][row] = v.z; As[d4 * 4 + 3][row] = v.w;
        float4 w = *(const float4*)&Fh[row * 32 + d4 * 4];
        BsT[d4 * 4 + 0][row] = w.x; BsT[d4 * 4 + 1][row] = w.y;
        BsT[d4 * 4 + 2][row] = w.z; BsT[d4 * 4 + 3][row] = w.w;
    }
    __syncthreads();
    int tr = tid / 16, tc = tid % 16;
    float acc[4][4];
    #pragma unroll
    for (int i = 0; i < 4; i++)
        #pragma unroll
        for (int j = 0; j < 4; j++) acc[i][j] = 0.f;
    #pragma unroll
    for (int d = 0; d < 32; d++) {
        float ra[4], rb[4];
        *(float4*)ra = *(const float4*)&As[d][tr * 4];
        *(float4*)rb = *(const float4*)&BsT[d][tc * 4];
        #pragma unroll
        for (int i = 0; i < 4; i++)
            #pragma unroll
            for (int j = 0; j < 4; j++) acc[i][j] += ra[i] * rb[j];
    }
    #pragma unroll
    for (int i = 0; i < 4; i++)
        #pragma unroll
        for (int j = 0; j < 4; j++)
            g_logits[((size_t)(i0 + tr * 4 + i) * Hh + h) * Nn + j0 + tc * 4 + j] = WLc * acc[i][j];
}

// ---------------- fused pair-bias + softmax, double-buffered ----------------
__global__ void bias_softmax_k(const float* __restrict__ pair, const float* __restrict__ Wb) {
    extern __shared__ float sm[];
    float* WbS    = sm;                  // 1536
    float* logitS = WbS + 1536;          // 12*520 = 6240
    float* pairS  = logitS + 6240;       // 2 * 64*132 = 16896
    float* comb   = pairS + 16896;       // 2304
    int i = blockIdx.x, tid = threadIdx.x;
    for (int t = tid; t < CZd * Hh; t += 256) WbS[t] = Wb[t];
    for (int t = tid; t < Hh * 128; t += 256) {
        int h = t >> 7, q = t & 127;
        *(float4*)&logitS[h * 520 + q * 4] =
            *(const float4*)&g_logits[((size_t)i * Hh + h) * Nn + q * 4];
    }
    int zq = tid >> 6, pos = tid & 63, hg = pos >> 4, jg = pos & 15;

    // prefetch chunk 0
    {
        for (int r = tid; r < 2048; r += 256) {
            int row = r >> 5, q = r & 31;
            cp16(&pairS[row * 132 + q * 4], &pair[((size_t)i * Nn + row) * CZd + q * 4]);
        }
        cp_commit();
    }
    for (int chunk = 0; chunk < 8; chunk++) {
        int buf = chunk & 1;
        float* pb = pairS + buf * 8448;
        if (chunk + 1 < 8) {
            float* pn = pairS + (buf ^ 1) * 8448;
            int j0n = (chunk + 1) * 64;
            for (int r = tid; r < 2048; r += 256) {
                int row = r >> 5, q = r & 31;
                cp16(&pn[row * 132 + q * 4], &pair[((size_t)i * Nn + j0n + row) * CZd + q * 4]);
            }
            cp_commit();
            cp_wait<1>();
        } else cp_wait<0>();
        __syncthreads();
        int j0 = chunk * 64;
        float acc[4][3];
        #pragma unroll
        for (int a = 0; a < 4; a++)
            #pragma unroll
            for (int b = 0; b < 3; b++) acc[a][b] = 0.f;
        int zbase = zq * 32;
        for (int z = zbase; z < zbase + 32; z++) {
            float pv[4], wv[3];
            #pragma unroll
            for (int a = 0; a < 4; a++) pv[a] = pb[(jg * 4 + a) * 132 + z];
            #pragma unroll
            for (int b = 0; b < 3; b++) wv[b] = WbS[z * Hh + hg * 3 + b];
            #pragma unroll
            for (int a = 0; a < 4; a++)
                #pragma unroll
                for (int b = 0; b < 3; b++) acc[a][b] += pv[a] * wv[b];
        }
        if (zq > 0) {
            float* c = &comb[((zq - 1) * 64 + pos) * 12];
            #pragma unroll
            for (int a = 0; a < 4; a++)
                #pragma unroll
                for (int b = 0; b < 3; b++) c[a * 3 + b] = acc[a][b];
        }
        __syncthreads();
        if (zq == 0) {
            #pragma unroll
            for (int a = 0; a < 4; a++)
                #pragma unroll
                for (int b = 0; b < 3; b++) {
                    float s = acc[a][b] + comb[(0 * 64 + pos) * 12 + a * 3 + b]
                                        + comb[(1 * 64 + pos) * 12 + a * 3 + b]
                                        + comb[(2 * 64 + pos) * 12 + a * 3 + b];
                    logitS[(hg * 3 + b) * 520 + j0 + jg * 4 + a] += WLc * s;
                }
        }
    }
    __syncthreads();
    // warp-private softmax: warp w -> head w; warps 0..3 also head 8+w
    int wid = tid >> 5, lane = tid & 31;
    #pragma unroll
    for (int rep = 0; rep < 2; rep++) {
        int h = wid + rep * 8;
        if (h < Hh) {
            float* L = &logitS[h * 520];
            float x[16];
            float m = -1e30f;
            #pragma unroll
            for (int l = 0; l < 16; l++) { x[l] = L[l * 32 + lane]; m = fmaxf(m, x[l]); }
            #pragma unroll
            for (int off = 16; off; off >>= 1) m = fmaxf(m, __shfl_xor_sync(0xffffffffu, m, off));
            float s = 0.f;
            #pragma unroll
            for (int l = 0; l < 16; l++) { x[l] = __expf(x[l] - m); s += x[l]; }
            #pragma unroll
            for (int off = 16; off; off >>= 1) s += __shfl_xor_sync(0xffffffffu, s, off);
            float inv = 1.f / s;
            #pragma unroll
            for (int l = 0; l < 16; l++) L[l * 32 + lane] = x[l] * inv;
        }
    }
    __syncthreads();
    for (int t = tid; t < Hh * 128; t += 256) {
        int h = t >> 7, q = t & 127;
        *(float4*)&g_logits[((size_t)i * Hh + h) * Nn + q * 4] =
            *(const float4*)&logitS[h * 520 + q * 4];
    }
}

// ---------------- o_pair, double-buffered ----------------
__global__ void accum_pair_k(const float* __restrict__ pair) {
    __shared__ float pairS[2][32 * 132];
    __shared__ float aS[2][12 * 33];
    __shared__ float comb[128 * 12];
    int i = blockIdx.x, tid = threadIdx.x;
    int jh = tid >> 7, rem = tid & 127, hg = rem >> 5, zg = rem & 31;
    float acc[3][4];
    #pragma unroll
    for (int b = 0; b < 3; b++)
        #pragma unroll
        for (int a = 0; a < 4; a++) acc[b][a] = 0.f;

    // prefetch chunk 0
    for (int r = tid; r < 1024; r += 256) {
        int row = r >> 5, q = r & 31;
        cp16(&pairS[0][row * 132 + q * 4], &pair[((size_t)i * Nn + row) * CZd + q * 4]);
    }
    cp_commit();
    for (int t = tid; t < 384; t += 256) {
        int h = t >> 5, jl = t & 31;
        aS[0][h * 33 + jl] = g_logits[((size_t)i * Hh + h) * Nn + jl];
    }
    for (int chunk = 0; chunk < 16; chunk++) {
        int buf = chunk & 1;
        if (chunk + 1 < 16) {
            int j0n = (chunk + 1) * 32;
            for (int r = tid; r < 1024; r += 256) {
                int row = r >> 5, q = r & 31;
                cp16(&pairS[buf ^ 1][row * 132 + q * 4],
                     &pair[((size_t)i * Nn + j0n + row) * CZd + q * 4]);
            }
            cp_commit();
            for (int t = tid; t < 384; t += 256) {
                int h = t >> 5, jl = t & 31;
                aS[buf ^ 1][h * 33 + jl] = g_logits[((size_t)i * Hh + h) * Nn + j0n + jl];
            }
            cp_wait<1>();
        } else cp_wait<0>();
        __syncthreads();
        int jb = jh * 16;
        #pragma unroll 4
        for (int l = 0; l < 16; l++) {
            int jl = jb + l;
            float4 pv = *(const float4*)&pairS[buf][jl * 132 + zg * 4];
            float av[3];
            #pragma unroll
            for (int b = 0; b < 3; b++) av[b] = aS[buf][(hg * 3 + b) * 33 + jl];
            #pragma unroll
            for (int b = 0; b < 3; b++) {
                acc[b][0] += av[b] * pv.x; acc[b][1] += av[b] * pv.y;
                acc[b][2] += av[b] * pv.z; acc[b][3] += av[b] * pv.w;
            }
        }
        __syncthreads();
    }
    if (jh == 1) {
        float* c = &comb[rem * 12];
        #pragma unroll
        for (int b = 0; b < 3; b++)
            #pragma unroll
            for (int a = 0; a < 4; a++) c[b * 4 + a] = acc[b][a];
    }
    __syncthreads();
    if (jh == 0) {
        const float* c = &comb[rem * 12];
        #pragma unroll
        for (int b = 0; b < 3; b++) {
            int h = hg * 3 + b;
            float4 v;
            v.x = acc[b][0] + c[b * 4 + 0];
            v.y = acc[b][1] + c[b * 4 + 1];
            v.z = acc[b][2] + c[b * 4 + 2];
            v.w = acc[b][3] + c[b * 4 + 3];
            *(float4*)&g_concat[(size_t)i * OUTD + 576 + h * CZd + zg * 4] = v;
        }
    }
}

// ---------------- o_v & o_pt ----------------
__global__ void ov_k() {
    __shared__ float As[64 * 33];
    __shared__ float Bs[32 * 49];
    int i0 = blockIdx.x * 64, h = blockIdx.y;
    int tid = threadIdx.x;
    int tr = tid / 16, tc = tid % 16;
    float acc[4][3];
    #pragma unroll
    for (int a = 0; a < 4; a++)
        #pragma unroll
        for (int b = 0; b < 3; b++) acc[a][b] = 0.f;
    for (int chunk = 0; chunk < 16; chunk++) {
        int j0 = chunk * 32;
        __syncthreads();
        for (int t = tid; t < 2048; t += 256) {
            int il = t >> 5, jl = t & 31;
            As[il * 33 + jl] = g_logits[((size_t)(i0 + il) * Hh + h) * Nn + j0 + jl];
        }
        for (int t = tid; t < 1536; t += 256) {
            int jl = t / 48, c = t % 48;
            float v = 0.f;
            if (c < 16)      v = g_proj[(size_t)(j0 + jl) * PROJD + OV + h * Cc + c];
            else if (c < 40) v = g_gv[(j0 + jl) * (Hh * 24) + h * 24 + (c - 16)];
            Bs[jl * 49 + c] = v;
        }
        __syncthreads();
        for (int jl = 0; jl < 32; jl++) {
            float ra[4], rb[3];
            #pragma unroll
            for (int a = 0; a < 4; a++) ra[a] = As[(tr * 4 + a) * 33 + jl];
            #pragma unroll
            for (int b = 0; b < 3; b++) rb[b] = Bs[jl * 49 + tc * 3 + b];
            #pragma unroll
            for (int a = 0; a < 4; a++)
                #pragma unroll
                for (int b = 0; b < 3; b++) acc[a][b] += ra[a] * rb[b];
        }
    }
    #pragma unroll
    for (int a = 0; a < 4; a++) {
        int i = i0 + tr * 4 + a;
        #pragma unroll
        for (int b = 0; b < 3; b++) {
            int c = tc * 3 + b;
            if (c < 16)      g_concat[(size_t)i * OUTD + h * Cc + c] = acc[a][b];
            else if (c < 40) g_opt[i * (Hh * 24) + h * 24 + (c - 16)] = acc[a][b];
        }
    }
}

__global__ void post_pt_k(const float* __restrict__ rot, const float* __restrict__ trans) {
    int idx = blockIdx.x * blockDim.x + threadIdx.x;
    if (idx >= Nn * Hh * PVd) return;
    int i = idx / (Hh * PVd), t = idx % (Hh * PVd);
    float b0 = g_opt[i * (Hh * 24) + t * 3 + 0] - trans[i * 3 + 0];
    float b1 = g_opt[i * (Hh * 24) + t * 3 + 1] - trans[i * 3 + 1];
    float b2 = g_opt[i * (Hh * 24) + t * 3 + 2] - trans[i * 3 + 2];
    float l0 = rot[i * 9 + 0] * b0 + rot[i * 9 + 3] * b1 + rot[i * 9 + 6] * b2;
    float l1 = rot[i * 9 + 1] * b0 + rot[i * 9 + 4] * b1 + rot[i * 9 + 7] * b2;
    float l2 = rot[i * 9 + 2] * b0 + rot[i * 9 + 5] * b1 + rot[i * 9 + 8] * b2;
    float* crow = &g_concat[(size_t)i * OUTD];
    crow[192 + t * 3 + 0] = l0;
    crow[192 + t * 3 + 1] = l1;
    crow[192 + t * 3 + 2] = l2;
    crow[480 + t] = sqrtf(l0 * l0 + l1 * l1 + l2 * l2 + 1e-8f);
}

// ---------------- layer norms ----------------
__device__ __forceinline__ float blockSum384(float v, float* red) {
    int tid = threadIdx.x;
    red[tid] = v;
    if (tid < 128) red[384 + tid] = 0.f;
    __syncthreads();
    for (int s = 256; s > 0; s >>= 1) {
        if (tid < s) red[tid] += red[tid + s];
        __syncthreads();
    }
    float r = red[0];
    __syncthreads();
    return r;
}

__global__ void ln1_k(const float* __restrict__ single_in, const float* __restrict__ bo,
                      const float* __restrict__ g, const float* __restrict__ b) {
    __shared__ float red[512];
    int row = blockIdx.x, tid = threadIdx.x;
    float x = single_in[row * CSd + tid] + bo[tid];
    #pragma unroll
    for (int z = 0; z < 4; z++) x += g_wop[(size_t)z * Nn * CSd + row * CSd + tid];
    float mean = blockSum384(x, red) * (1.f / CSd);
    float dx = x - mean;
    float var = blockSum384(dx * dx, red) * (1.f / CSd);
    g_s1[row * CSd + tid] = dx * rsqrtf(var + 1e-5f) * g[tid] + b[tid];
}

__global__ void ln2_k(const float* __restrict__ g, const float* __restrict__ b,
                      float* __restrict__ out) {
    __shared__ float red[512];
    int row = blockIdx.x, tid = threadIdx.x;
    float x = g_s1[row * CSd + tid] + g_h3[row * CSd + tid];
    float mean = blockSum384(x, red) * (1.f / CSd);
    float dx = x - mean;
    float var = blockSum384(dx * dx, red) * (1.f / CSd);
    float y = dx * rsqrtf(var + 1e-5f) * g[tid] + b[tid];
    out[row * CSd + tid] = y;
    g_s2[row * CSd + tid] = y;
}

// ---------------- backbone update: one warp per n ----------------
__global__ void update_k(const float* __restrict__ rot, const float* __restrict__ trans,
                         const float* __restrict__ Wbu, const float* __restrict__ bbu,
                         float* __restrict__ out) {
    int gtid = blockIdx.x * blockDim.x + threadIdx.x;
    int n = gtid >> 5, lane = gtid & 31;
    if (n >= Nn) return;
    float u[6] = {0, 0, 0, 0, 0, 0};
    for (int s = lane; s < CSd; s += 32) {
        float x = g_s2[n * CSd + s];
        #pragma unroll
        for (int j = 0; j < 6; j++) u[j] += x * Wbu[s * 6 + j];
    }
    #pragma unroll
    for (int j = 0; j < 6; j++)
        #pragma unroll
        for (int off = 16; off; off >>= 1) u[j] += __shfl_xor_sync(0xffffffffu, u[j], off);
    if (lane != 0) return;
    #pragma unroll
    for (int j = 0; j < 6; j++) u[j] += bbu[j];
    float b = u[0], c = u[1], d = u[2];
    float inq = rsqrtf(1.f + b * b + c * c + d * d);
    float a = inq; b *= inq; c *= inq; d *= inq;
    float R[9] = {
        a*a + b*b - c*c - d*d, 2.f*(b*c - a*d),       2.f*(b*d + a*c),
        2.f*(b*c + a*d),       a*a - b*b + c*c - d*d, 2.f*(c*d - a*b),
        2.f*(b*d - a*c),       2.f*(c*d + a*b),       a*a - b*b - c*c + d*d };
    float rn[9];
    #pragma unroll
    for (int aa = 0; aa < 3; aa++)
        #pragma unroll
        for (int cc = 0; cc < 3; cc++) {
            float s2 = 0.f;
            #pragma unroll
            for (int bx = 0; bx < 3; bx++) s2 += rot[n * 9 + aa * 3 + bx] * R[bx * 3 + cc];
            rn[aa * 3 + cc] = s2;
        }
    float t0 = u[3], t1 = u[4], t2 = u[5];
    float tn[3];
    #pragma unroll
    for (int aa = 0; aa < 3; aa++)
        tn[aa] = rot[n * 9 + aa * 3 + 0] * t0 + rot[n * 9 + aa * 3 + 1] * t1 +
                 rot[n * 9 + aa * 3 + 2] * t2 + trans[n * 3 + aa];
    #pragma unroll
    for (int e = 0; e < 9; e++) { g_rotn[n * 9 + e] = rn[e]; out[Nn * CSd + n * 9 + e] = rn[e]; }
    #pragma unroll
    for (int e = 0; e < 3; e++) { g_trn[n * 3 + e] = tn[e]; out[Nn * CSd + Nn * 9 + n * 3 + e] = tn[e]; }
}

// ---------------- loss ----------------
__global__ void loss_part_k(const float* __restrict__ rt, const float* __restrict__ tt) {
    int i = blockIdx.x, tid = threadIdx.x;
    __shared__ float red[256];
    float rn[9], rte[9], tni[3], tti[3];
    #pragma unroll
    for (int e = 0; e < 9; e++) { rn[e] = g_rotn[i * 9 + e]; rte[e] = rt[i * 9 + e]; }
    #pragma unroll
    for (int e = 0; e < 3; e++) { tni[e] = g_trn[i * 3 + e]; tti[e] = tt[i * 3 + e]; }
    float s = 0.f;
    for (int j = tid; j < Nn; j += 256) {
        float db0 = g_trn[j * 3 + 0] - tni[0];
        float db1 = g_trn[j * 3 + 1] - tni[1];
        float db2 = g_trn[j * 3 + 2] - tni[2];
        float dp0 = rn[0] * db0 + rn[3] * db1 + rn[6] * db2;
        float dp1 = rn[1] * db0 + rn[4] * db1 + rn[7] * db2;
        float dp2 = rn[2] * db0 + rn[5] * db1 + rn[8] * db2;
        float eb0 = tt[j * 3 + 0] - tti[0];
        float eb1 = tt[j * 3 + 1] - tti[1];
        float eb2 = tt[j * 3 + 2] - tti[2];
        float dt0 = rte[0] * eb0 + rte[3] * eb1 + rte[6] * eb2;
        float dt1 = rte[1] * eb0 + rte[4] * eb1 + rte[7] * eb2;
        float dt2 = rte[2] * eb0 + rte[5] * eb1 + rte[8] * eb2;
        float d0 = dp0 - dt0, d1 = dp1 - dt1, d2 = dp2 - dt2;
        float dd = sqrtf(d0 * d0 + d1 * d1 + d2 * d2 + 1e-12f);
        s += fminf(dd, 10.f);
    }
    red[tid] = s; __syncthreads();
    for (int st = 128; st > 0; st >>= 1) {
        if (tid < st) red[tid] += red[tid + st];
        __syncthreads();
    }
    if (tid == 0) g_partial[i] = red[0];
}

__global__ void loss_final_k(float* __restrict__ out) {
    __shared__ float red[512];
    int tid = threadIdx.x;
    red[tid] = g_partial[tid];
    __syncthreads();
    for (int s = 256; s > 0; s >>= 1) {
        if (tid < s) red[tid] += red[tid + s];
        __syncthreads();
    }
    if (tid == 0)
        out[Nn * CSd + Nn * 9 + Nn * 3] = red[0] / ((float)Nn * (float)Nn) * 0.1f;
}

// ---------------- host ----------------
template <typename T>
static float* symaddr(T& sym) {
    void* p = nullptr;
    cudaGetSymbolAddress(&p, sym);
    return (float*)p;
}

extern "C" void kernel_launch(void* const* d_in, const int* in_sizes, int n_in,
                              void* d_out, int out_size) {
    const float* single      = (const float*)d_in[0];
    const float* pair        = (const float*)d_in[1];
    const float* rot         = (const float*)d_in[2];
    const float* trans       = (const float*)d_in[3];
    const float* rot_truth   = (const float*)d_in[4];
    const float* trans_truth = (const float*)d_in[5];
    const float* Wq  = (const float*)d_in[6];
    const float* Wk  = (const float*)d_in[7];
    const float* Wv  = (const float*)d_in[8];
    const float* Wqp = (const float*)d_in[9];
    const float* Wkp = (const float*)d_in[10];
    const float* Wvp = (const float*)d_in[11];
    const float* Wb  = (const float*)d_in[12];
    const float* Wo  = (const float*)d_in[13];
    const float* bo  = (const float*)d_in[14];
    const float* gamma_raw = (const float*)d_in[15];
    const float* ln1_g = (const float*)d_in[16];
    const float* ln1_b = (const float*)d_in[17];
    const float* ln2_g = (const float*)d_in[18];
    const float* ln2_b = (const float*)d_in[19];
    const float* W1 = (const float*)d_in[20];
    const float* b1 = (const float*)d_in[21];
    const float* W2 = (const float*)d_in[22];
    const float* b2 = (const float*)d_in[23];
    const float* W3 = (const float*)d_in[24];
    const float* b3 = (const float*)d_in[25];
    const float* Wbu = (const float*)d_in[26];
    const float* bbu = (const float*)d_in[27];
    float* out = (float*)d_out;

    float* pWf     = symaddr(g_Wf);
    float* pProj   = symaddr(g_proj);
    float* pConcat = symaddr(g_concat);
    float* pWop    = symaddr(g_wop);
    float* pS1     = symaddr(g_s1);
    float* pH1     = symaddr(g_h1);
    float* pH2     = symaddr(g_h2);
    float* pH3     = symaddr(g_h3);

    cudaFuncSetAttribute(bias_softmax_k, cudaFuncAttributeMaxDynamicSharedMemorySize, 110000);

    fuse_w_k<<<(CSd * PROJD + 255) / 256, 256>>>(Wq, Wk, Wv, Wqp, Wkp, Wvp);

    sgemm_k<64,64,16,4,4,false,false,false><<<dim3(PROJD/64, Nn/64, 1), 256>>>(
        single, pWf, nullptr, pProj, Nn, PROJD, CSd, CSd);

    prep_k<<<Nn, 128>>>(rot, trans, gamma_raw);
    core_k<<<dim3(Nn/64, Nn/64, Hh), 256>>>();

    bias_softmax_k<<<Nn, 256, (1536 + 6240 + 16896 + 2304) * 4>>>(pair, Wb);
    accum_pair_k<<<Nn, 256>>>(pair);
    ov_k<<<dim3(Nn/64, Hh), 256>>>();
    post_pt_k<<<(Nn * Hh * PVd + 255) / 256, 256>>>(rot, trans);

    sgemm_k<128,64,16,8,4,false,false,true><<<dim3(CSd/64, Nn/128, 4), 256>>>(
        pConcat, Wo, nullptr, pWop, Nn, CSd, OUTD, OUTD/4);
    ln1_k<<<Nn, CSd>>>(single, bo, ln1_g, ln1_b);

    sgemm_k<64,64,16,4,4,true,true,false><<<dim3(CSd/64, Nn/64, 1), 256>>>(
        pS1, W1, b1, pH1, Nn, CSd, CSd, CSd);
    sgemm_k<64,64,16,4,4,true,true,false><<<dim3(CSd/64, Nn/64, 1), 256>>>(
        pH1, W2, b2, pH2, Nn, CSd, CSd, CSd);
    sgemm_k<64,64,16,4,4,true,false,false><<<dim3(CSd/64, Nn/64, 1), 256>>>(
        pH2, W3, b3, pH3, Nn, CSd, CSd, CSd);
    ln2_k<<<Nn, CSd>>>(ln2_g, ln2_b, out);

    update_k<<<(Nn * 32 + 127) / 128, 128>>>(rot, trans, Wbu, bbu, out);
    loss_part_k<<<Nn, 256>>>(rot_truth, trans_truth);
    loss_final_k<<<1, 512>>>(out);
}

// round 5
// speedup vs baseline: 2.6402x; 1.1542x over previous
#include <cuda_runtime.h>
#include <math.h>

#define Nn 512
#define CSd 384
#define CZd 128
#define Hh 12
#define Cc 16
#define PQd 4
#define PVd 8
#define OUTD 2112
#define PROJD 1152
#define OQ 0
#define OK0 192
#define OV 384
#define OQP 576
#define OKP 720
#define OVP 864

__device__ float g_Wf[CSd * PROJD];
__device__ float g_proj[Nn * PROJD];
__device__ float g_gv[Nn * Hh * PVd * 3];
__device__ float g_E[Hh * Nn * 32], g_F[Hh * Nn * 32];
__device__ float g_logits[Nn * Hh * Nn];
__device__ float g_concat[Nn * OUTD];
__device__ float g_opt[Nn * Hh * PVd * 3];
__device__ float g_wop[4 * Nn * CSd];
__device__ float g_s1[Nn * CSd], g_h1[Nn * CSd], g_h2[Nn * CSd], g_h3[Nn * CSd], g_s2[Nn * CSd];
__device__ float g_rotn[Nn * 9], g_trn[Nn * 3];
__device__ float g_partial[Nn];

#define WLc 0.5773502691896258f
#define WCc 0.23570226039551584f

__device__ __forceinline__ void cp16(void* smem_dst, const void* gmem_src) {
    unsigned s = (unsigned)__cvta_generic_to_shared(smem_dst);
    asm volatile("cp.async.cg.shared.global [%0], [%1], 16;" :: "r"(s), "l"(gmem_src));
}
__device__ __forceinline__ void cp_commit() { asm volatile("cp.async.commit_group;"); }
template<int N> __device__ __forceinline__ void cp_wait() {
    asm volatile("cp.async.wait_group %0;" :: "n"(N));
}

// ---------------- fuse weights ----------------
__global__ void fuse_w_k(const float* __restrict__ Wq, const float* __restrict__ Wk,
                         const float* __restrict__ Wv, const float* __restrict__ Wqp,
                         const float* __restrict__ Wkp, const float* __restrict__ Wvp) {
    int idx = blockIdx.x * blockDim.x + threadIdx.x;
    if (idx >= CSd * PROJD) return;
    int r = idx / PROJD, c = idx % PROJD;
    float v;
    if (c < 192)        v = Wq [r * 192 + c];
    else if (c < 384)   v = Wk [r * 192 + (c - 192)];
    else if (c < 576)   v = Wv [r * 192 + (c - 384)];
    else if (c < 720)   v = Wqp[r * 144 + (c - 576)];
    else if (c < 864)   v = Wkp[r * 144 + (c - 720)];
    else                v = Wvp[r * 288 + (c - 864)];
    g_Wf[idx] = v;
}

// ---------------- double-buffered tiled SGEMM ----------------
template<int BM, int BN, int BK, int TM, int TN, bool BIAS, bool RELU, bool SPLITK>
__global__ void sgemm_k(const float* __restrict__ A, const float* __restrict__ B,
                        const float* __restrict__ bias, float* __restrict__ C,
                        int M, int N, int K, int KC) {
    const int THREADS = (BM / TM) * (BN / TN);
    __shared__ float As[2][BK][BM];
    __shared__ float Bs[2][BK][BN + 4];
    int n0 = blockIdx.x * BN, m0 = blockIdx.y * BM;
    int kstart = SPLITK ? blockIdx.z * KC : 0;
    if (SPLITK) C += (size_t)blockIdx.z * M * N;
    int tid = threadIdx.x;
    int tr = tid / (BN / TN), tc = tid % (BN / TN);
    float acc[TM][TN];
    #pragma unroll
    for (int i = 0; i < TM; i++)
        #pragma unroll
        for (int j = 0; j < TN; j++) acc[i][j] = 0.f;
    int nsteps = KC / BK;

    auto loadA = [&](int kt, int buf) {
        #pragma unroll
        for (int r = tid; r < BM * BK / 4; r += THREADS) {
            int arow = r / (BK / 4), aq = r % (BK / 4);
            float4 v = *(const float4*)&A[(size_t)(m0 + arow) * K + kstart + kt * BK + aq * 4];
            As[buf][aq * 4 + 0][arow] = v.x; As[buf][aq * 4 + 1][arow] = v.y;
            As[buf][aq * 4 + 2][arow] = v.z; As[buf][aq * 4 + 3][arow] = v.w;
        }
    };
    auto loadB = [&](int kt, int buf) {
        #pragma unroll
        for (int r = tid; r < BK * BN / 4; r += THREADS) {
            int brow = r / (BN / 4), bq = r % (BN / 4);
            cp16(&Bs[buf][brow][bq * 4], &B[(size_t)(kstart + kt * BK + brow) * N + n0 + bq * 4]);
        }
    };
    loadA(0, 0); loadB(0, 0); cp_commit();
    for (int kt = 0; kt < nsteps; kt++) {
        int buf = kt & 1;
        if (kt + 1 < nsteps) {
            loadA(kt + 1, buf ^ 1); loadB(kt + 1, buf ^ 1); cp_commit();
            cp_wait<1>();
        } else cp_wait<0>();
        __syncthreads();
        #pragma unroll
        for (int k = 0; k < BK; k++) {
            float ra[TM], rb[TN];
            #pragma unroll
            for (int i = 0; i < TM; i += 4)
                *(float4*)&ra[i] = *(const float4*)&As[buf][k][tr * TM + i];
            #pragma unroll
            for (int j = 0; j < TN; j += 4)
                *(float4*)&rb[j] = *(const float4*)&Bs[buf][k][tc * TN + j];
            #pragma unroll
            for (int i = 0; i < TM; i++)
                #pragma unroll
                for (int j = 0; j < TN; j++) acc[i][j] += ra[i] * rb[j];
        }
        __syncthreads();
    }
    #pragma unroll
    for (int i = 0; i < TM; i++) {
        int m = m0 + tr * TM + i;
        #pragma unroll
        for (int j = 0; j < TN; j++) {
            int n = n0 + tc * TN + j;
            float v = acc[i][j];
            if (BIAS) v += bias[n];
            if (RELU) v = fmaxf(v, 0.f);
            C[(size_t)m * N + n] = v;
        }
    }
}

// ---------------- prep: frames + squared norms + E/F ----------------
__global__ void prep_k(const float* __restrict__ rot, const float* __restrict__ trans,
                       const float* __restrict__ gamma_raw) {
    __shared__ float R[9], T[3], gqS[144], gkS[144], sqqS[12], sqkS[12], wcgS[12];
    int n = blockIdx.x, tid = threadIdx.x;
    if (tid < 9) R[tid] = rot[n * 9 + tid];
    if (tid < 3) T[tid] = trans[n * 3 + tid];
    if (tid >= 16 && tid < 28) {
        int h = tid - 16;
        float x = gamma_raw[h];
        wcgS[h] = WCc * ((x > 20.f) ? x : log1pf(expf(x)));
    }
    __syncthreads();
    const float* base = &g_proj[(size_t)n * PROJD];
    for (int t = tid; t < 96; t += 128) {
        int which = t / 48, p = t % 48;
        const float* src = base + (which ? OKP : OQP) + p * 3;
        float b0 = src[0], b1 = src[1], b2 = src[2];
        float* dst = (which ? gkS : gqS) + p * 3;
        #pragma unroll
        for (int a = 0; a < 3; a++)
            dst[a] = R[a * 3 + 0] * b0 + R[a * 3 + 1] * b1 + R[a * 3 + 2] * b2 + T[a];
    }
    for (int t = tid; t < 96; t += 128) {
        const float* src = base + OVP + t * 3;
        float b0 = src[0], b1 = src[1], b2 = src[2];
        #pragma unroll
        for (int a = 0; a < 3; a++)
            g_gv[n * 288 + t * 3 + a] =
                R[a * 3 + 0] * b0 + R[a * 3 + 1] * b1 + R[a * 3 + 2] * b2 + T[a];
    }
    __syncthreads();
    if (tid < 24) {
        int h = tid >> 1, which = tid & 1;
        const float* g = (which ? gkS : gqS) + h * 12;
        float s = 0.f;
        #pragma unroll
        for (int e = 0; e < 12; e++) s += g[e] * g[e];
        (which ? sqkS : sqqS)[h] = s;
    }
    __syncthreads();
    for (int t = tid; t < Hh * 32; t += 128) {
        int h = t >> 5, c = t & 31;
        float wcg = wcgS[h];
        float e, f;
        if (c < 16)      { e = 0.25f * base[OQ + h * 16 + c]; f = base[OK0 + h * 16 + c]; }
        else if (c < 28) { e = wcg * gqS[h * 12 + c - 16];    f = gkS[h * 12 + c - 16]; }
        else if (c == 28){ e = sqqS[h];                        f = -0.5f * wcg; }
        else if (c == 29){ e = 1.f;                            f = -0.5f * wcg * sqkS[h]; }
        else             { e = 0.f;                            f = 0.f; }
        g_E[(size_t)((h << 9) | n) * 32 + c] = e;
        g_F[(size_t)((h << 9) | n) * 32 + c] = f;
    }
}

// ---------------- logit core ----------------
__global__ void core_k() {
    __shared__ float As[32][64], BsT[32][64];
    int h = blockIdx.z, i0 = blockIdx.y * 64, j0 = blockIdx.x * 64;
    int tid = threadIdx.x;
    const float* Eh = &g_E[((size_t)h * Nn + i0) * 32];
    const float* Fh = &g_F[((size_t)h * Nn + j0) * 32];
    for (int t = tid; t < 512; t += 256) {
        int row = t >> 3, d4 = t & 7;
        float4 v = *(const float4*)&Eh[row * 32 + d4 * 4];
        As[d4 * 4 + 0][row] = v.x; As[d4 * 4 + 1][row] = v.y;
        As[d4 * 4 + 2][row] = v.z; As[d4 * 4 + 3][row] = v.w;
        float4 w = *(const float4*)&Fh[row * 32 + d4 * 4];
        BsT[d4 * 4 + 0][row] = w.x; BsT[d4 * 4 + 1][row] = w.y;
        BsT[d4 * 4 + 2][row] = w.z; BsT[d4 * 4 + 3][row] = w.w;
    }
    __syncthreads();
    int tr = tid / 16, tc = tid % 16;
    float acc[4][4];
    #pragma unroll
    for (int i = 0; i < 4; i++)
        #pragma unroll
        for (int j = 0; j < 4; j++) acc[i][j] = 0.f;
    #pragma unroll
    for (int d = 0; d < 32; d++) {
        float ra[4], rb[4];
        *(float4*)ra = *(const float4*)&As[d][tr * 4];
        *(float4*)rb = *(const float4*)&BsT[d][tc * 4];
        #pragma unroll
        for (int i = 0; i < 4; i++)
            #pragma unroll
            for (int j = 0; j < 4; j++) acc[i][j] += ra[i] * rb[j];
    }
    #pragma unroll
    for (int i = 0; i < 4; i++)
        #pragma unroll
        for (int j = 0; j < 4; j++)
            g_logits[((size_t)(i0 + tr * 4 + i) * Hh + h) * Nn + j0 + tc * 4 + j] = WLc * acc[i][j];
}

// ---------------- FLASH: bias + online softmax + o_pair in ONE pair pass ----------------
// dyn smem: WbS[1536] logitS[12*520] pairS[2][32*132] comb[1536] attE[384] Mh[12] Sh[12] rS[12]
__global__ void __launch_bounds__(256, 3)
flash_k(const float* __restrict__ pair, const float* __restrict__ Wb) {
    extern __shared__ float sm[];
    float* WbS    = sm;                    // 1536
    float* logitS = WbS + 1536;            // 6240
    float* pairS  = logitS + 6240;         // 8448 (2 x 32 x 132)
    float* comb   = pairS + 8448;          // 1536
    float* attE   = comb + 1536;           // 384
    float* Mh     = attE + 384;            // 12
    float* Sh     = Mh + 12;               // 12
    float* rS     = Sh + 12;               // 12

    int i = blockIdx.x, tid = threadIdx.x;
    for (int t = tid; t < CZd * Hh; t += 256) WbS[t] = Wb[t];
    for (int t = tid; t < Hh * 128; t += 256) {
        int h = t >> 7, q = t & 127;
        *(float4*)&logitS[h * 520 + q * 4] =
            *(const float4*)&g_logits[((size_t)i * Hh + h) * Nn + q * 4];
    }
    if (tid < 12) { Mh[tid] = -1e30f; Sh[tid] = 0.f; }

    // decompositions
    int zq = tid >> 6, pos = tid & 63, hg = pos >> 4, jg = pos & 15;      // bias pass
    int jh = tid >> 7, rem = tid & 127, hg2 = rem >> 5, zg = rem & 31;    // o_pair pass
    int wid = tid >> 5, lane = tid & 31;

    float accP[3][4];
    #pragma unroll
    for (int b = 0; b < 3; b++)
        #pragma unroll
        for (int a = 0; a < 4; a++) accP[b][a] = 0.f;

    // prefetch chunk 0
    for (int r = tid; r < 1024; r += 256) {
        int row = r >> 5, q = r & 31;
        cp16(&pairS[row * 132 + q * 4], &pair[((size_t)i * Nn + row) * CZd + q * 4]);
    }
    cp_commit();

    for (int chunk = 0; chunk < 16; chunk++) {
        int buf = chunk & 1;
        float* pb = pairS + buf * 4224;
        int j0 = chunk * 32;
        if (chunk + 1 < 16) {
            float* pn = pairS + (buf ^ 1) * 4224;
            int j0n = j0 + 32;
            for (int r = tid; r < 1024; r += 256) {
                int row = r >> 5, q = r & 31;
                cp16(&pn[row * 132 + q * 4], &pair[((size_t)i * Nn + j0n + row) * CZd + q * 4]);
            }
            cp_commit();
            cp_wait<1>();
        } else cp_wait<0>();
        __syncthreads();

        // ---- bias GEMM: 32 j x 12 h (thread: 2 j x 3 h, zq-split over z) ----
        float acc2[2][3];
        #pragma unroll
        for (int a = 0; a < 2; a++)
            #pragma unroll
            for (int b = 0; b < 3; b++) acc2[a][b] = 0.f;
        int zbase = zq * 32;
        for (int z = zbase; z < zbase + 32; z++) {
            float pv0 = pb[(jg * 2 + 0) * 132 + z];
            float pv1 = pb[(jg * 2 + 1) * 132 + z];
            float wv0 = WbS[z * Hh + hg * 3 + 0];
            float wv1 = WbS[z * Hh + hg * 3 + 1];
            float wv2 = WbS[z * Hh + hg * 3 + 2];
            acc2[0][0] += pv0 * wv0; acc2[0][1] += pv0 * wv1; acc2[0][2] += pv0 * wv2;
            acc2[1][0] += pv1 * wv0; acc2[1][1] += pv1 * wv1; acc2[1][2] += pv1 * wv2;
        }
        if (zq > 0) {
            float* c = &comb[((zq - 1) * 64 + pos) * 6];
            #pragma unroll
            for (int a = 0; a < 2; a++)
                #pragma unroll
                for (int b = 0; b < 3; b++) c[a * 3 + b] = acc2[a][b];
        }
        __syncthreads();
        if (zq == 0) {
            #pragma unroll
            for (int a = 0; a < 2; a++)
                #pragma unroll
                for (int b = 0; b < 3; b++) {
                    float s = acc2[a][b] + comb[(0 * 64 + pos) * 6 + a * 3 + b]
                                         + comb[(1 * 64 + pos) * 6 + a * 3 + b]
                                         + comb[(2 * 64 + pos) * 6 + a * 3 + b];
                    logitS[(hg * 3 + b) * 520 + j0 + jg * 2 + a] += WLc * s;
                }
        }
        __syncthreads();

        // ---- online softmax state update: warp per head ----
        #pragma unroll
        for (int rep = 0; rep < 2; rep++) {
            int h = wid + rep * 8;
            if (h < Hh) {
                float l = logitS[h * 520 + j0 + lane];
                float cm = l;
                #pragma unroll
                for (int off = 16; off; off >>= 1)
                    cm = fmaxf(cm, __shfl_xor_sync(0xffffffffu, cm, off));
                float Mo = Mh[h];
                float Mn = fmaxf(Mo, cm);
                float e = __expf(l - Mn);
                float se = e;
                #pragma unroll
                for (int off = 16; off; off >>= 1)
                    se += __shfl_xor_sync(0xffffffffu, se, off);
                attE[h * 32 + lane] = e;
                if (lane == 0) {
                    float r = __expf(Mo - Mn);
                    Sh[h] = Sh[h] * r + se;
                    rS[h] = r;
                    Mh[h] = Mn;
                }
            }
        }
        __syncthreads();

        // ---- o_pair accumulate (rescale then add chunk) ----
        int jb = jh * 16;
        #pragma unroll
        for (int b = 0; b < 3; b++) {
            int h = hg2 * 3 + b;
            float r = rS[h];
            accP[b][0] *= r; accP[b][1] *= r; accP[b][2] *= r; accP[b][3] *= r;
            const float* eh = &attE[h * 32 + jb];
            #pragma unroll 4
            for (int l = 0; l < 16; l++) {
                float av = eh[l];
                float4 pv = *(const float4*)&pb[(jb + l) * 132 + zg * 4];
                accP[b][0] += av * pv.x; accP[b][1] += av * pv.y;
                accP[b][2] += av * pv.z; accP[b][3] += av * pv.w;
            }
        }
        __syncthreads();
    }

    // ---- combine halves & write o_pair ----
    if (jh == 1) {
        float* c = &comb[rem * 12];
        #pragma unroll
        for (int b = 0; b < 3; b++)
            #pragma unroll
            for (int a = 0; a < 4; a++) c[b * 4 + a] = accP[b][a];
    }
    __syncthreads();
    if (jh == 0) {
        const float* c = &comb[rem * 12];
        #pragma unroll
        for (int b = 0; b < 3; b++) {
            int h = hg2 * 3 + b;
            float invS = 1.f / Sh[h];
            float4 v;
            v.x = (accP[b][0] + c[b * 4 + 0]) * invS;
            v.y = (accP[b][1] + c[b * 4 + 1]) * invS;
            v.z = (accP[b][2] + c[b * 4 + 2]) * invS;
            v.w = (accP[b][3] + c[b * 4 + 3]) * invS;
            *(float4*)&g_concat[(size_t)i * OUTD + 576 + h * CZd + zg * 4] = v;
        }
    }
    // ---- write normalized attention for ov_k ----
    if (tid < 12) rS[tid] = 1.f / Sh[tid];
    __syncthreads();
    for (int t = tid; t < Hh * Nn; t += 256) {
        int h = t >> 9, j = t & 511;
        g_logits[((size_t)i * Hh + h) * Nn + j] =
            __expf(logitS[h * 520 + j] - Mh[h]) * rS[h];
    }
}

// ---------------- o_v & o_pt ----------------
__global__ void ov_k() {
    __shared__ float As[64 * 33];
    __shared__ float Bs[32 * 49];
    int i0 = blockIdx.x * 64, h = blockIdx.y;
    int tid = threadIdx.x;
    int tr = tid / 16, tc = tid % 16;
    float acc[4][3];
    #pragma unroll
    for (int a = 0; a < 4; a++)
        #pragma unroll
        for (int b = 0; b < 3; b++) acc[a][b] = 0.f;
    for (int chunk = 0; chunk < 16; chunk++) {
        int j0 = chunk * 32;
        __syncthreads();
        for (int t = tid; t < 2048; t += 256) {
            int il = t >> 5, jl = t & 31;
            As[il * 33 + jl] = g_logits[((size_t)(i0 + il) * Hh + h) * Nn + j0 + jl];
        }
        for (int t = tid; t < 1536; t += 256) {
            int jl = t / 48, c = t % 48;
            float v = 0.f;
            if (c < 16)      v = g_proj[(size_t)(j0 + jl) * PROJD + OV + h * Cc + c];
            else if (c < 40) v = g_gv[(j0 + jl) * (Hh * 24) + h * 24 + (c - 16)];
            Bs[jl * 49 + c] = v;
        }
        __syncthreads();
        for (int jl = 0; jl < 32; jl++) {
            float ra[4], rb[3];
            #pragma unroll
            for (int a = 0; a < 4; a++) ra[a] = As[(tr * 4 + a) * 33 + jl];
            #pragma unroll
            for (int b = 0; b < 3; b++) rb[b] = Bs[jl * 49 + tc * 3 + b];
            #pragma unroll
            for (int a = 0; a < 4; a++)
                #pragma unroll
                for (int b = 0; b < 3; b++) acc[a][b] += ra[a] * rb[b];
        }
    }
    #pragma unroll
    for (int a = 0; a < 4; a++) {
        int i = i0 + tr * 4 + a;
        #pragma unroll
        for (int b = 0; b < 3; b++) {
            int c = tc * 3 + b;
            if (c < 16)      g_concat[(size_t)i * OUTD + h * Cc + c] = acc[a][b];
            else if (c < 40) g_opt[i * (Hh * 24) + h * 24 + (c - 16)] = acc[a][b];
        }
    }
}

__global__ void post_pt_k(const float* __restrict__ rot, const float* __restrict__ trans) {
    int idx = blockIdx.x * blockDim.x + threadIdx.x;
    if (idx >= Nn * Hh * PVd) return;
    int i = idx / (Hh * PVd), t = idx % (Hh * PVd);
    float b0 = g_opt[i * (Hh * 24) + t * 3 + 0] - trans[i * 3 + 0];
    float b1 = g_opt[i * (Hh * 24) + t * 3 + 1] - trans[i * 3 + 1];
    float b2 = g_opt[i * (Hh * 24) + t * 3 + 2] - trans[i * 3 + 2];
    float l0 = rot[i * 9 + 0] * b0 + rot[i * 9 + 3] * b1 + rot[i * 9 + 6] * b2;
    float l1 = rot[i * 9 + 1] * b0 + rot[i * 9 + 4] * b1 + rot[i * 9 + 7] * b2;
    float l2 = rot[i * 9 + 2] * b0 + rot[i * 9 + 5] * b1 + rot[i * 9 + 8] * b2;
    float* crow = &g_concat[(size_t)i * OUTD];
    crow[192 + t * 3 + 0] = l0;
    crow[192 + t * 3 + 1] = l1;
    crow[192 + t * 3 + 2] = l2;
    crow[480 + t] = sqrtf(l0 * l0 + l1 * l1 + l2 * l2 + 1e-8f);
}

// ---------------- layer norms ----------------
__device__ __forceinline__ float blockSum384(float v, float* red) {
    int tid = threadIdx.x;
    red[tid] = v;
    if (tid < 128) red[384 + tid] = 0.f;
    __syncthreads();
    for (int s = 256; s > 0; s >>= 1) {
        if (tid < s) red[tid] += red[tid + s];
        __syncthreads();
    }
    float r = red[0];
    __syncthreads();
    return r;
}

__global__ void ln1_k(const float* __restrict__ single_in, const float* __restrict__ bo,
                      const float* __restrict__ g, const float* __restrict__ b) {
    __shared__ float red[512];
    int row = blockIdx.x, tid = threadIdx.x;
    float x = single_in[row * CSd + tid] + bo[tid];
    #pragma unroll
    for (int z = 0; z < 4; z++) x += g_wop[(size_t)z * Nn * CSd + row * CSd + tid];
    float mean = blockSum384(x, red) * (1.f / CSd);
    float dx = x - mean;
    float var = blockSum384(dx * dx, red) * (1.f / CSd);
    g_s1[row * CSd + tid] = dx * rsqrtf(var + 1e-5f) * g[tid] + b[tid];
}

__global__ void ln2_k(const float* __restrict__ g, const float* __restrict__ b,
                      float* __restrict__ out) {
    __shared__ float red[512];
    int row = blockIdx.x, tid = threadIdx.x;
    float x = g_s1[row * CSd + tid] + g_h3[row * CSd + tid];
    float mean = blockSum384(x, red) * (1.f / CSd);
    float dx = x - mean;
    float var = blockSum384(dx * dx, red) * (1.f / CSd);
    float y = dx * rsqrtf(var + 1e-5f) * g[tid] + b[tid];
    out[row * CSd + tid] = y;
    g_s2[row * CSd + tid] = y;
}

// ---------------- backbone update: one warp per n ----------------
__global__ void update_k(const float* __restrict__ rot, const float* __restrict__ trans,
                         const float* __restrict__ Wbu, const float* __restrict__ bbu,
                         float* __restrict__ out) {
    int gtid = blockIdx.x * blockDim.x + threadIdx.x;
    int n = gtid >> 5, lane = gtid & 31;
    if (n >= Nn) return;
    float u[6] = {0, 0, 0, 0, 0, 0};
    for (int s = lane; s < CSd; s += 32) {
        float x = g_s2[n * CSd + s];
        #pragma unroll
        for (int j = 0; j < 6; j++) u[j] += x * Wbu[s * 6 + j];
    }
    #pragma unroll
    for (int j = 0; j < 6; j++)
        #pragma unroll
        for (int off = 16; off; off >>= 1) u[j] += __shfl_xor_sync(0xffffffffu, u[j], off);
    if (lane != 0) return;
    #pragma unroll
    for (int j = 0; j < 6; j++) u[j] += bbu[j];
    float b = u[0], c = u[1], d = u[2];
    float inq = rsqrtf(1.f + b * b + c * c + d * d);
    float a = inq; b *= inq; c *= inq; d *= inq;
    float R[9] = {
        a*a + b*b - c*c - d*d, 2.f*(b*c - a*d),       2.f*(b*d + a*c),
        2.f*(b*c + a*d),       a*a - b*b + c*c - d*d, 2.f*(c*d - a*b),
        2.f*(b*d - a*c),       2.f*(c*d + a*b),       a*a - b*b - c*c + d*d };
    float rn[9];
    #pragma unroll
    for (int aa = 0; aa < 3; aa++)
        #pragma unroll
        for (int cc = 0; cc < 3; cc++) {
            float s2 = 0.f;
            #pragma unroll
            for (int bx = 0; bx < 3; bx++) s2 += rot[n * 9 + aa * 3 + bx] * R[bx * 3 + cc];
            rn[aa * 3 + cc] = s2;
        }
    float t0 = u[3], t1 = u[4], t2 = u[5];
    float tn[3];
    #pragma unroll
    for (int aa = 0; aa < 3; aa++)
        tn[aa] = rot[n * 9 + aa * 3 + 0] * t0 + rot[n * 9 + aa * 3 + 1] * t1 +
                 rot[n * 9 + aa * 3 + 2] * t2 + trans[n * 3 + aa];
    #pragma unroll
    for (int e = 0; e < 9; e++) { g_rotn[n * 9 + e] = rn[e]; out[Nn * CSd + n * 9 + e] = rn[e]; }
    #pragma unroll
    for (int e = 0; e < 3; e++) { g_trn[n * 3 + e] = tn[e]; out[Nn * CSd + Nn * 9 + n * 3 + e] = tn[e]; }
}

// ---------------- loss ----------------
__global__ void loss_part_k(const float* __restrict__ rt, const float* __restrict__ tt) {
    int i = blockIdx.x, tid = threadIdx.x;
    __shared__ float red[256];
    float rn[9], rte[9], tni[3], tti[3];
    #pragma unroll
    for (int e = 0; e < 9; e++) { rn[e] = g_rotn[i * 9 + e]; rte[e] = rt[i * 9 + e]; }
    #pragma unroll
    for (int e = 0; e < 3; e++) { tni[e] = g_trn[i * 3 + e]; tti[e] = tt[i * 3 + e]; }
    float s = 0.f;
    for (int j = tid; j < Nn; j += 256) {
        float db0 = g_trn[j * 3 + 0] - tni[0];
        float db1 = g_trn[j * 3 + 1] - tni[1];
        float db2 = g_trn[j * 3 + 2] - tni[2];
        float dp0 = rn[0] * db0 + rn[3] * db1 + rn[6] * db2;
        float dp1 = rn[1] * db0 + rn[4] * db1 + rn[7] * db2;
        float dp2 = rn[2] * db0 + rn[5] * db1 + rn[8] * db2;
        float eb0 = tt[j * 3 + 0] - tti[0];
        float eb1 = tt[j * 3 + 1] - tti[1];
        float eb2 = tt[j * 3 + 2] - tti[2];
        float dt0 = rte[0] * eb0 + rte[3] * eb1 + rte[6] * eb2;
        float dt1 = rte[1] * eb0 + rte[4] * eb1 + rte[7] * eb2;
        float dt2 = rte[2] * eb0 + rte[5] * eb1 + rte[8] * eb2;
        float d0 = dp0 - dt0, d1 = dp1 - dt1, d2 = dp2 - dt2;
        float dd = sqrtf(d0 * d0 + d1 * d1 + d2 * d2 + 1e-12f);
        s += fminf(dd, 10.f);
    }
    red[tid] = s; __syncthreads();
    for (int st = 128; st > 0; st >>= 1) {
        if (tid < st) red[tid] += red[tid + st];
        __syncthreads();
    }
    if (tid == 0) g_partial[i] = red[0];
}

__global__ void loss_final_k(float* __restrict__ out) {
    __shared__ float red[512];
    int tid = threadIdx.x;
    red[tid] = g_partial[tid];
    __syncthreads();
    for (int s = 256; s > 0; s >>= 1) {
        if (tid < s) red[tid] += red[tid + s];
        __syncthreads();
    }
    if (tid == 0)
        out[Nn * CSd + Nn * 9 + Nn * 3] = red[0] / ((float)Nn * (float)Nn) * 0.1f;
}

// ---------------- host ----------------
template <typename T>
static float* symaddr(T& sym) {
    void* p = nullptr;
    cudaGetSymbolAddress(&p, sym);
    return (float*)p;
}

extern "C" void kernel_launch(void* const* d_in, const int* in_sizes, int n_in,
                              void* d_out, int out_size) {
    const float* single      = (const float*)d_in[0];
    const float* pair        = (const float*)d_in[1];
    const float* rot         = (const float*)d_in[2];
    const float* trans       = (const float*)d_in[3];
    const float* rot_truth   = (const float*)d_in[4];
    const float* trans_truth = (const float*)d_in[5];
    const float* Wq  = (const float*)d_in[6];
    const float* Wk  = (const float*)d_in[7];
    const float* Wv  = (const float*)d_in[8];
    const float* Wqp = (const float*)d_in[9];
    const float* Wkp = (const float*)d_in[10];
    const float* Wvp = (const float*)d_in[11];
    const float* Wb  = (const float*)d_in[12];
    const float* Wo  = (const float*)d_in[13];
    const float* bo  = (const float*)d_in[14];
    const float* gamma_raw = (const float*)d_in[15];
    const float* ln1_g = (const float*)d_in[16];
    const float* ln1_b = (const float*)d_in[17];
    const float* ln2_g = (const float*)d_in[18];
    const float* ln2_b = (const float*)d_in[19];
    const float* W1 = (const float*)d_in[20];
    const float* b1 = (const float*)d_in[21];
    const float* W2 = (const float*)d_in[22];
    const float* b2 = (const float*)d_in[23];
    const float* W3 = (const float*)d_in[24];
    const float* b3 = (const float*)d_in[25];
    const float* Wbu = (const float*)d_in[26];
    const float* bbu = (const float*)d_in[27];
    float* out = (float*)d_out;

    float* pWf     = symaddr(g_Wf);
    float* pProj   = symaddr(g_proj);
    float* pConcat = symaddr(g_concat);
    float* pWop    = symaddr(g_wop);
    float* pS1     = symaddr(g_s1);
    float* pH1     = symaddr(g_h1);
    float* pH2     = symaddr(g_h2);
    float* pH3     = symaddr(g_h3);

    const int FLASH_SMEM = (1536 + 6240 + 8448 + 1536 + 384 + 36 + 12) * 4;
    cudaFuncSetAttribute(flash_k, cudaFuncAttributeMaxDynamicSharedMemorySize, FLASH_SMEM);

    fuse_w_k<<<(CSd * PROJD + 255) / 256, 256>>>(Wq, Wk, Wv, Wqp, Wkp, Wvp);

    sgemm_k<64,64,16,4,4,false,false,false><<<dim3(PROJD/64, Nn/64, 1), 256>>>(
        single, pWf, nullptr, pProj, Nn, PROJD, CSd, CSd);

    prep_k<<<Nn, 128>>>(rot, trans, gamma_raw);
    core_k<<<dim3(Nn/64, Nn/64, Hh), 256>>>();

    flash_k<<<Nn, 256, FLASH_SMEM>>>(pair, Wb);
    ov_k<<<dim3(Nn/64, Hh), 256>>>();
    post_pt_k<<<(Nn * Hh * PVd + 255) / 256, 256>>>(rot, trans);

    sgemm_k<128,64,16,8,4,false,false,true><<<dim3(CSd/64, Nn/128, 4), 256>>>(
        pConcat, Wo, nullptr, pWop, Nn, CSd, OUTD, OUTD/4);
    ln1_k<<<Nn, CSd>>>(single, bo, ln1_g, ln1_b);

    sgemm_k<64,64,16,4,4,true,true,false><<<dim3(CSd/64, Nn/64, 1), 256>>>(
        pS1, W1, b1, pH1, Nn, CSd, CSd, CSd);
    sgemm_k<64,64,16,4,4,true,true,false><<<dim3(CSd/64, Nn/64, 1), 256>>>(
        pH1, W2, b2, pH2, Nn, CSd, CSd, CSd);
    sgemm_k<64,64,16,4,4,true,false,false><<<dim3(CSd/64, Nn/64, 1), 256>>>(
        pH2, W3, b3, pH3, Nn, CSd, CSd, CSd);
    ln2_k<<<Nn, CSd>>>(ln2_g, ln2_b, out);

    update_k<<<(Nn * 32 + 127) / 128, 128>>>(rot, trans, Wbu, bbu, out);
    loss_part_k<<<Nn, 256>>>(rot_truth, trans_truth);
    loss_final_k<<<1, 512>>>(out);
}

// round 6
// speedup vs baseline: 2.9581x; 1.1204x over previous
#include <cuda_runtime.h>
#include <math.h>

#define Nn 512
#define CSd 384
#define CZd 128
#define Hh 12
#define Cc 16
#define PQd 4
#define PVd 8
#define OUTD 2112
#define PROJD 1152
#define OQ 0
#define OK0 192
#define OV 384
#define OQP 576
#define OKP 720
#define OVP 864

__device__ float g_Wf[CSd * PROJD];
__device__ float g_proj[Nn * PROJD];
__device__ float g_gv[Nn * Hh * PVd * 3];
__device__ float g_E[Hh * Nn * 32], g_F[Hh * Nn * 32];
__device__ float g_logits[Nn * Hh * Nn];
__device__ float g_opP[4 * Nn * Hh * CZd];
__device__ float g_concat[Nn * OUTD];
__device__ float g_opt[Nn * Hh * PVd * 3];
__device__ float g_wop[4 * Nn * CSd];
__device__ float g_s1[Nn * CSd], g_h1[Nn * CSd], g_h2[Nn * CSd], g_h3[Nn * CSd], g_s2[Nn * CSd];
__device__ float g_rotn[Nn * 9], g_trn[Nn * 3];
__device__ float g_partial[Nn];

#define WLc 0.5773502691896258f
#define WCc 0.23570226039551584f

__device__ __forceinline__ void cp16(void* smem_dst, const void* gmem_src) {
    unsigned s = (unsigned)__cvta_generic_to_shared(smem_dst);
    asm volatile("cp.async.cg.shared.global [%0], [%1], 16;" :: "r"(s), "l"(gmem_src));
}
__device__ __forceinline__ void cp_commit() { asm volatile("cp.async.commit_group;"); }
template<int N> __device__ __forceinline__ void cp_wait() {
    asm volatile("cp.async.wait_group %0;" :: "n"(N));
}

// ---------------- fuse weights ----------------
__global__ void fuse_w_k(const float* __restrict__ Wq, const float* __restrict__ Wk,
                         const float* __restrict__ Wv, const float* __restrict__ Wqp,
                         const float* __restrict__ Wkp, const float* __restrict__ Wvp) {
    int idx = blockIdx.x * blockDim.x + threadIdx.x;
    if (idx >= CSd * PROJD) return;
    int r = idx / PROJD, c = idx % PROJD;
    float v;
    if (c < 192)        v = Wq [r * 192 + c];
    else if (c < 384)   v = Wk [r * 192 + (c - 192)];
    else if (c < 576)   v = Wv [r * 192 + (c - 384)];
    else if (c < 720)   v = Wqp[r * 144 + (c - 576)];
    else if (c < 864)   v = Wkp[r * 144 + (c - 720)];
    else                v = Wvp[r * 288 + (c - 864)];
    g_Wf[idx] = v;
}

// ---------------- double-buffered tiled SGEMM ----------------
template<int BM, int BN, int BK, int TM, int TN, bool BIAS, bool RELU, bool SPLITK>
__global__ void sgemm_k(const float* __restrict__ A, const float* __restrict__ B,
                        const float* __restrict__ bias, float* __restrict__ C,
                        int M, int N, int K, int KC) {
    const int THREADS = (BM / TM) * (BN / TN);
    __shared__ float As[2][BK][BM];
    __shared__ float Bs[2][BK][BN + 4];
    int n0 = blockIdx.x * BN, m0 = blockIdx.y * BM;
    int kstart = SPLITK ? blockIdx.z * KC : 0;
    if (SPLITK) C += (size_t)blockIdx.z * M * N;
    int tid = threadIdx.x;
    int tr = tid / (BN / TN), tc = tid % (BN / TN);
    float acc[TM][TN];
    #pragma unroll
    for (int i = 0; i < TM; i++)
        #pragma unroll
        for (int j = 0; j < TN; j++) acc[i][j] = 0.f;
    int nsteps = KC / BK;

    auto loadA = [&](int kt, int buf) {
        #pragma unroll
        for (int r = tid; r < BM * BK / 4; r += THREADS) {
            int arow = r / (BK / 4), aq = r % (BK / 4);
            float4 v = *(const float4*)&A[(size_t)(m0 + arow) * K + kstart + kt * BK + aq * 4];
            As[buf][aq * 4 + 0][arow] = v.x; As[buf][aq * 4 + 1][arow] = v.y;
            As[buf][aq * 4 + 2][arow] = v.z; As[buf][aq * 4 + 3][arow] = v.w;
        }
    };
    auto loadB = [&](int kt, int buf) {
        #pragma unroll
        for (int r = tid; r < BK * BN / 4; r += THREADS) {
            int brow = r / (BN / 4), bq = r % (BN / 4);
            cp16(&Bs[buf][brow][bq * 4], &B[(size_t)(kstart + kt * BK + brow) * N + n0 + bq * 4]);
        }
    };
    loadA(0, 0); loadB(0, 0); cp_commit();
    for (int kt = 0; kt < nsteps; kt++) {
        int buf = kt & 1;
        if (kt + 1 < nsteps) {
            loadA(kt + 1, buf ^ 1); loadB(kt + 1, buf ^ 1); cp_commit();
            cp_wait<1>();
        } else cp_wait<0>();
        __syncthreads();
        #pragma unroll
        for (int k = 0; k < BK; k++) {
            float ra[TM], rb[TN];
            #pragma unroll
            for (int i = 0; i < TM; i += 4)
                *(float4*)&ra[i] = *(const float4*)&As[buf][k][tr * TM + i];
            #pragma unroll
            for (int j = 0; j < TN; j += 4)
                *(float4*)&rb[j] = *(const float4*)&Bs[buf][k][tc * TN + j];
            #pragma unroll
            for (int i = 0; i < TM; i++)
                #pragma unroll
                for (int j = 0; j < TN; j++) acc[i][j] += ra[i] * rb[j];
        }
        __syncthreads();
    }
    #pragma unroll
    for (int i = 0; i < TM; i++) {
        int m = m0 + tr * TM + i;
        #pragma unroll
        for (int j = 0; j < TN; j++) {
            int n = n0 + tc * TN + j;
            float v = acc[i][j];
            if (BIAS) v += bias[n];
            if (RELU) v = fmaxf(v, 0.f);
            C[(size_t)m * N + n] = v;
        }
    }
}

// ---------------- prep: frames + squared norms + E/F ----------------
__global__ void prep_k(const float* __restrict__ rot, const float* __restrict__ trans,
                       const float* __restrict__ gamma_raw) {
    __shared__ float R[9], T[3], gqS[144], gkS[144], sqqS[12], sqkS[12], wcgS[12];
    int n = blockIdx.x, tid = threadIdx.x;
    if (tid < 9) R[tid] = rot[n * 9 + tid];
    if (tid < 3) T[tid] = trans[n * 3 + tid];
    if (tid >= 16 && tid < 28) {
        int h = tid - 16;
        float x = gamma_raw[h];
        wcgS[h] = WCc * ((x > 20.f) ? x : log1pf(expf(x)));
    }
    __syncthreads();
    const float* base = &g_proj[(size_t)n * PROJD];
    for (int t = tid; t < 96; t += 128) {
        int which = t / 48, p = t % 48;
        const float* src = base + (which ? OKP : OQP) + p * 3;
        float b0 = src[0], b1 = src[1], b2 = src[2];
        float* dst = (which ? gkS : gqS) + p * 3;
        #pragma unroll
        for (int a = 0; a < 3; a++)
            dst[a] = R[a * 3 + 0] * b0 + R[a * 3 + 1] * b1 + R[a * 3 + 2] * b2 + T[a];
    }
    for (int t = tid; t < 96; t += 128) {
        const float* src = base + OVP + t * 3;
        float b0 = src[0], b1 = src[1], b2 = src[2];
        #pragma unroll
        for (int a = 0; a < 3; a++)
            g_gv[n * 288 + t * 3 + a] =
                R[a * 3 + 0] * b0 + R[a * 3 + 1] * b1 + R[a * 3 + 2] * b2 + T[a];
    }
    __syncthreads();
    if (tid < 24) {
        int h = tid >> 1, which = tid & 1;
        const float* g = (which ? gkS : gqS) + h * 12;
        float s = 0.f;
        #pragma unroll
        for (int e = 0; e < 12; e++) s += g[e] * g[e];
        (which ? sqkS : sqqS)[h] = s;
    }
    __syncthreads();
    for (int t = tid; t < Hh * 32; t += 128) {
        int h = t >> 5, c = t & 31;
        float wcg = wcgS[h];
        float e, f;
        if (c < 16)      { e = 0.25f * base[OQ + h * 16 + c]; f = base[OK0 + h * 16 + c]; }
        else if (c < 28) { e = wcg * gqS[h * 12 + c - 16];    f = gkS[h * 12 + c - 16]; }
        else if (c == 28){ e = sqqS[h];                        f = -0.5f * wcg; }
        else if (c == 29){ e = 1.f;                            f = -0.5f * wcg * sqkS[h]; }
        else             { e = 0.f;                            f = 0.f; }
        g_E[(size_t)((h << 9) | n) * 32 + c] = e;
        g_F[(size_t)((h << 9) | n) * 32 + c] = f;
    }
}

// ---------------- bias GEMM: g_logits[i][h][j] = WL * (pair[i,j,:] @ Wb[:,h]) ----------------
// grid 2048: block = (i, 128-j slice). Full 64KB pair tile in smem, float4 both operands.
__global__ void __launch_bounds__(256) bias_k(const float* __restrict__ pair,
                                              const float* __restrict__ Wb) {
    extern __shared__ float sm[];
    float* As   = sm;               // 128*132
    float* WbT  = As + 128 * 132;   // 12*132 (transposed: [h][z])
    float* comb = WbT + 12 * 132;   // 128*12
    int blk = blockIdx.x;
    int i = blk >> 2, j0 = (blk & 3) << 7;
    int tid = threadIdx.x;
    for (int t = tid; t < CZd * Hh; t += 256) WbT[(t % Hh) * 132 + (t / Hh)] = Wb[t];
    for (int r = tid; r < 128 * 32; r += 256) {
        int row = r >> 5, q = r & 31;
        cp16(&As[row * 132 + q * 4], &pair[((size_t)i * Nn + j0 + row) * CZd + q * 4]);
    }
    cp_commit(); cp_wait<0>();
    __syncthreads();
    int r = tid & 127, zh = tid >> 7;   // zh: z-half (64 z each)
    const float4* ap = (const float4*)&As[r * 132 + zh * 64];
    float acc[12];
    #pragma unroll
    for (int h = 0; h < Hh; h++) {
        const float4* wp = (const float4*)&WbT[h * 132 + zh * 64];
        float a = 0.f;
        #pragma unroll
        for (int z4 = 0; z4 < 16; z4++) {
            float4 p = ap[z4], w = wp[z4];
            a += p.x * w.x + p.y * w.y + p.z * w.z + p.w * w.w;
        }
        acc[h] = a;
    }
    if (zh == 1) {
        #pragma unroll
        for (int h = 0; h < Hh; h++) comb[r * 12 + h] = acc[h];
    }
    __syncthreads();
    if (zh == 0) {
        #pragma unroll
        for (int h = 0; h < Hh; h++)
            g_logits[((size_t)i * Hh + h) * Nn + j0 + r] = WLc * (acc[h] + comb[r * 12 + h]);
    }
}

// ---------------- logit core: ADDS WL*(E.F) on top of bias ----------------
__global__ void core_k() {
    __shared__ float As[32][64], BsT[32][64];
    int h = blockIdx.z, i0 = blockIdx.y * 64, j0 = blockIdx.x * 64;
    int tid = threadIdx.x;
    const float* Eh = &g_E[((size_t)h * Nn + i0) * 32];
    const float* Fh = &g_F[((size_t)h * Nn + j0) * 32];
    for (int t = tid; t < 512; t += 256) {
        int row = t >> 3, d4 = t & 7;
        float4 v = *(const float4*)&Eh[row * 32 + d4 * 4];
        As[d4 * 4 + 0][row] = v.x; As[d4 * 4 + 1][row] = v.y;
        As[d4 * 4 + 2][row] = v.z; As[d4 * 4 + 3][row] = v.w;
        float4 w = *(const float4*)&Fh[row * 32 + d4 * 4];
        BsT[d4 * 4 + 0][row] = w.x; BsT[d4 * 4 + 1][row] = w.y;
        BsT[d4 * 4 + 2][row] = w.z; BsT[d4 * 4 + 3][row] = w.w;
    }
    __syncthreads();
    int tr = tid / 16, tc = tid % 16;
    float acc[4][4];
    #pragma unroll
    for (int i = 0; i < 4; i++)
        #pragma unroll
        for (int j = 0; j < 4; j++) acc[i][j] = 0.f;
    #pragma unroll
    for (int d = 0; d < 32; d++) {
        float ra[4], rb[4];
        *(float4*)ra = *(const float4*)&As[d][tr * 4];
        *(float4*)rb = *(const float4*)&BsT[d][tc * 4];
        #pragma unroll
        for (int i = 0; i < 4; i++)
            #pragma unroll
            for (int j = 0; j < 4; j++) acc[i][j] += ra[i] * rb[j];
    }
    #pragma unroll
    for (int i = 0; i < 4; i++)
        #pragma unroll
        for (int j = 0; j < 4; j++) {
            size_t idx = ((size_t)(i0 + tr * 4 + i) * Hh + h) * Nn + j0 + tc * 4 + j;
            g_logits[idx] += WLc * acc[i][j];
        }
}

// ---------------- softmax: warp per head, register-resident ----------------
__global__ void softmax_k() {
    int i = blockIdx.x;
    int w = threadIdx.x >> 5, lane = threadIdx.x & 31;
    float* L = &g_logits[((size_t)i * Hh + w) * Nn];
    float x[16];
    float m = -1e30f;
    #pragma unroll
    for (int l = 0; l < 16; l++) { x[l] = L[l * 32 + lane]; m = fmaxf(m, x[l]); }
    #pragma unroll
    for (int off = 16; off; off >>= 1) m = fmaxf(m, __shfl_xor_sync(0xffffffffu, m, off));
    float s = 0.f;
    #pragma unroll
    for (int l = 0; l < 16; l++) { x[l] = __expf(x[l] - m); s += x[l]; }
    #pragma unroll
    for (int off = 16; off; off >>= 1) s += __shfl_xor_sync(0xffffffffu, s, off);
    float inv = 1.f / s;
    #pragma unroll
    for (int l = 0; l < 16; l++) L[l * 32 + lane] = x[l] * inv;
}

// ---------------- o_pair partials: grid (i, 4 j-splits) ----------------
__global__ void __launch_bounds__(256) opair_k(const float* __restrict__ pair) {
    extern __shared__ float sm[];
    float* pairS = sm;                 // 128*132
    float* attS  = pairS + 128 * 132;  // 12*128
    int i = blockIdx.x, js = blockIdx.y, j0 = js << 7;
    int tid = threadIdx.x;
    for (int t = tid; t < Hh * 128; t += 256) {
        int h = t >> 7, j = t & 127;
        attS[t] = g_logits[((size_t)i * Hh + h) * Nn + j0 + j];
    }
    for (int r = tid; r < 128 * 32; r += 256) {
        int row = r >> 5, q = r & 31;
        cp16(&pairS[row * 132 + q * 4], &pair[((size_t)i * Nn + j0 + row) * CZd + q * 4]);
    }
    cp_commit(); cp_wait<0>();
    __syncthreads();
    int ht = tid >> 6, zz = tid & 63;  // ht: 3 heads each; zz: 2 z each
    float a00 = 0.f, a01 = 0.f, a10 = 0.f, a11 = 0.f, a20 = 0.f, a21 = 0.f;
    const float* at0 = &attS[(ht * 3 + 0) * 128];
    const float* at1 = &attS[(ht * 3 + 1) * 128];
    const float* at2 = &attS[(ht * 3 + 2) * 128];
    #pragma unroll 4
    for (int j = 0; j < 128; j++) {
        float2 p = *(const float2*)&pairS[j * 132 + zz * 2];
        float v0 = at0[j], v1 = at1[j], v2 = at2[j];
        a00 += v0 * p.x; a01 += v0 * p.y;
        a10 += v1 * p.x; a11 += v1 * p.y;
        a20 += v2 * p.x; a21 += v2 * p.y;
    }
    float* dst = &g_opP[((size_t)js * Nn + i) * (Hh * CZd)];
    *(float2*)&dst[(ht * 3 + 0) * 128 + zz * 2] = make_float2(a00, a01);
    *(float2*)&dst[(ht * 3 + 1) * 128 + zz * 2] = make_float2(a10, a11);
    *(float2*)&dst[(ht * 3 + 2) * 128 + zz * 2] = make_float2(a20, a21);
}

__global__ void opair_combine_k() {
    int i = blockIdx.x, tid = threadIdx.x;
    const size_t S = (size_t)Nn * Hh * CZd;
    for (int c = tid; c < Hh * CZd; c += 256) {
        size_t base = (size_t)i * (Hh * CZd) + c;
        float s = g_opP[base] + g_opP[S + base] + g_opP[2 * S + base] + g_opP[3 * S + base];
        g_concat[(size_t)i * OUTD + 576 + c] = s;
    }
}

// ---------------- o_v & o_pt ----------------
__global__ void ov_k() {
    __shared__ float As[64 * 33];
    __shared__ float Bs[32 * 49];
    int i0 = blockIdx.x * 64, h = blockIdx.y;
    int tid = threadIdx.x;
    int tr = tid / 16, tc = tid % 16;
    float acc[4][3];
    #pragma unroll
    for (int a = 0; a < 4; a++)
        #pragma unroll
        for (int b = 0; b < 3; b++) acc[a][b] = 0.f;
    for (int chunk = 0; chunk < 16; chunk++) {
        int j0 = chunk * 32;
        __syncthreads();
        for (int t = tid; t < 2048; t += 256) {
            int il = t >> 5, jl = t & 31;
            As[il * 33 + jl] = g_logits[((size_t)(i0 + il) * Hh + h) * Nn + j0 + jl];
        }
        for (int t = tid; t < 1536; t += 256) {
            int jl = t / 48, c = t % 48;
            float v = 0.f;
            if (c < 16)      v = g_proj[(size_t)(j0 + jl) * PROJD + OV + h * Cc + c];
            else if (c < 40) v = g_gv[(j0 + jl) * (Hh * 24) + h * 24 + (c - 16)];
            Bs[jl * 49 + c] = v;
        }
        __syncthreads();
        for (int jl = 0; jl < 32; jl++) {
            float ra[4], rb[3];
            #pragma unroll
            for (int a = 0; a < 4; a++) ra[a] = As[(tr * 4 + a) * 33 + jl];
            #pragma unroll
            for (int b = 0; b < 3; b++) rb[b] = Bs[jl * 49 + tc * 3 + b];
            #pragma unroll
            for (int a = 0; a < 4; a++)
                #pragma unroll
                for (int b = 0; b < 3; b++) acc[a][b] += ra[a] * rb[b];
        }
    }
    #pragma unroll
    for (int a = 0; a < 4; a++) {
        int i = i0 + tr * 4 + a;
        #pragma unroll
        for (int b = 0; b < 3; b++) {
            int c = tc * 3 + b;
            if (c < 16)      g_concat[(size_t)i * OUTD + h * Cc + c] = acc[a][b];
            else if (c < 40) g_opt[i * (Hh * 24) + h * 24 + (c - 16)] = acc[a][b];
        }
    }
}

__global__ void post_pt_k(const float* __restrict__ rot, const float* __restrict__ trans) {
    int idx = blockIdx.x * blockDim.x + threadIdx.x;
    if (idx >= Nn * Hh * PVd) return;
    int i = idx / (Hh * PVd), t = idx % (Hh * PVd);
    float b0 = g_opt[i * (Hh * 24) + t * 3 + 0] - trans[i * 3 + 0];
    float b1 = g_opt[i * (Hh * 24) + t * 3 + 1] - trans[i * 3 + 1];
    float b2 = g_opt[i * (Hh * 24) + t * 3 + 2] - trans[i * 3 + 2];
    float l0 = rot[i * 9 + 0] * b0 + rot[i * 9 + 3] * b1 + rot[i * 9 + 6] * b2;
    float l1 = rot[i * 9 + 1] * b0 + rot[i * 9 + 4] * b1 + rot[i * 9 + 7] * b2;
    float l2 = rot[i * 9 + 2] * b0 + rot[i * 9 + 5] * b1 + rot[i * 9 + 8] * b2;
    float* crow = &g_concat[(size_t)i * OUTD];
    crow[192 + t * 3 + 0] = l0;
    crow[192 + t * 3 + 1] = l1;
    crow[192 + t * 3 + 2] = l2;
    crow[480 + t] = sqrtf(l0 * l0 + l1 * l1 + l2 * l2 + 1e-8f);
}

// ---------------- layer norms ----------------
__device__ __forceinline__ float blockSum384(float v, float* red) {
    int tid = threadIdx.x;
    red[tid] = v;
    if (tid < 128) red[384 + tid] = 0.f;
    __syncthreads();
    for (int s = 256; s > 0; s >>= 1) {
        if (tid < s) red[tid] += red[tid + s];
        __syncthreads();
    }
    float r = red[0];
    __syncthreads();
    return r;
}

__global__ void ln1_k(const float* __restrict__ single_in, const float* __restrict__ bo,
                      const float* __restrict__ g, const float* __restrict__ b) {
    __shared__ float red[512];
    int row = blockIdx.x, tid = threadIdx.x;
    float x = single_in[row * CSd + tid] + bo[tid];
    #pragma unroll
    for (int z = 0; z < 4; z++) x += g_wop[(size_t)z * Nn * CSd + row * CSd + tid];
    float mean = blockSum384(x, red) * (1.f / CSd);
    float dx = x - mean;
    float var = blockSum384(dx * dx, red) * (1.f / CSd);
    g_s1[row * CSd + tid] = dx * rsqrtf(var + 1e-5f) * g[tid] + b[tid];
}

__global__ void ln2_k(const float* __restrict__ g, const float* __restrict__ b,
                      float* __restrict__ out) {
    __shared__ float red[512];
    int row = blockIdx.x, tid = threadIdx.x;
    float x = g_s1[row * CSd + tid] + g_h3[row * CSd + tid];
    float mean = blockSum384(x, red) * (1.f / CSd);
    float dx = x - mean;
    float var = blockSum384(dx * dx, red) * (1.f / CSd);
    float y = dx * rsqrtf(var + 1e-5f) * g[tid] + b[tid];
    out[row * CSd + tid] = y;
    g_s2[row * CSd + tid] = y;
}

// ---------------- backbone update: one warp per n ----------------
__global__ void update_k(const float* __restrict__ rot, const float* __restrict__ trans,
                         const float* __restrict__ Wbu, const float* __restrict__ bbu,
                         float* __restrict__ out) {
    int gtid = blockIdx.x * blockDim.x + threadIdx.x;
    int n = gtid >> 5, lane = gtid & 31;
    if (n >= Nn) return;
    float u[6] = {0, 0, 0, 0, 0, 0};
    for (int s = lane; s < CSd; s += 32) {
        float x = g_s2[n * CSd + s];
        #pragma unroll
        for (int j = 0; j < 6; j++) u[j] += x * Wbu[s * 6 + j];
    }
    #pragma unroll
    for (int j = 0; j < 6; j++)
        #pragma unroll
        for (int off = 16; off; off >>= 1) u[j] += __shfl_xor_sync(0xffffffffu, u[j], off);
    if (lane != 0) return;
    #pragma unroll
    for (int j = 0; j < 6; j++) u[j] += bbu[j];
    float b = u[0], c = u[1], d = u[2];
    float inq = rsqrtf(1.f + b * b + c * c + d * d);
    float a = inq; b *= inq; c *= inq; d *= inq;
    float R[9] = {
        a*a + b*b - c*c - d*d, 2.f*(b*c - a*d),       2.f*(b*d + a*c),
        2.f*(b*c + a*d),       a*a - b*b + c*c - d*d, 2.f*(c*d - a*b),
        2.f*(b*d - a*c),       2.f*(c*d + a*b),       a*a - b*b - c*c + d*d };
    float rn[9];
    #pragma unroll
    for (int aa = 0; aa < 3; aa++)
        #pragma unroll
        for (int cc = 0; cc < 3; cc++) {
            float s2 = 0.f;
            #pragma unroll
            for (int bx = 0; bx < 3; bx++) s2 += rot[n * 9 + aa * 3 + bx] * R[bx * 3 + cc];
            rn[aa * 3 + cc] = s2;
        }
    float t0 = u[3], t1 = u[4], t2 = u[5];
    float tn[3];
    #pragma unroll
    for (int aa = 0; aa < 3; aa++)
        tn[aa] = rot[n * 9 + aa * 3 + 0] * t0 + rot[n * 9 + aa * 3 + 1] * t1 +
                 rot[n * 9 + aa * 3 + 2] * t2 + trans[n * 3 + aa];
    #pragma unroll
    for (int e = 0; e < 9; e++) { g_rotn[n * 9 + e] = rn[e]; out[Nn * CSd + n * 9 + e] = rn[e]; }
    #pragma unroll
    for (int e = 0; e < 3; e++) { g_trn[n * 3 + e] = tn[e]; out[Nn * CSd + Nn * 9 + n * 3 + e] = tn[e]; }
}

// ---------------- loss ----------------
__global__ void loss_part_k(const float* __restrict__ rt, const float* __restrict__ tt) {
    int i = blockIdx.x, tid = threadIdx.x;
    __shared__ float red[256];
    float rn[9], rte[9], tni[3], tti[3];
    #pragma unroll
    for (int e = 0; e < 9; e++) { rn[e] = g_rotn[i * 9 + e]; rte[e] = rt[i * 9 + e]; }
    #pragma unroll
    for (int e = 0; e < 3; e++) { tni[e] = g_trn[i * 3 + e]; tti[e] = tt[i * 3 + e]; }
    float s = 0.f;
    for (int j = tid; j < Nn; j += 256) {
        float db0 = g_trn[j * 3 + 0] - tni[0];
        float db1 = g_trn[j * 3 + 1] - tni[1];
        float db2 = g_trn[j * 3 + 2] - tni[2];
        float dp0 = rn[0] * db0 + rn[3] * db1 + rn[6] * db2;
        float dp1 = rn[1] * db0 + rn[4] * db1 + rn[7] * db2;
        float dp2 = rn[2] * db0 + rn[5] * db1 + rn[8] * db2;
        float eb0 = tt[j * 3 + 0] - tti[0];
        float eb1 = tt[j * 3 + 1] - tti[1];
        float eb2 = tt[j * 3 + 2] - tti[2];
        float dt0 = rte[0] * eb0 + rte[3] * eb1 + rte[6] * eb2;
        float dt1 = rte[1] * eb0 + rte[4] * eb1 + rte[7] * eb2;
        float dt2 = rte[2] * eb0 + rte[5] * eb1 + rte[8] * eb2;
        float d0 = dp0 - dt0, d1 = dp1 - dt1, d2 = dp2 - dt2;
        float dd = sqrtf(d0 * d0 + d1 * d1 + d2 * d2 + 1e-12f);
        s += fminf(dd, 10.f);
    }
    red[tid] = s; __syncthreads();
    for (int st = 128; st > 0; st >>= 1) {
        if (tid < st) red[tid] += red[tid + st];
        __syncthreads();
    }
    if (tid == 0) g_partial[i] = red[0];
}

__global__ void loss_final_k(float* __restrict__ out) {
    __shared__ float red[512];
    int tid = threadIdx.x;
    red[tid] = g_partial[tid];
    __syncthreads();
    for (int s = 256; s > 0; s >>= 1) {
        if (tid < s) red[tid] += red[tid + s];
        __syncthreads();
    }
    if (tid == 0)
        out[Nn * CSd + Nn * 9 + Nn * 3] = red[0] / ((float)Nn * (float)Nn) * 0.1f;
}

// ---------------- host ----------------
template <typename T>
static float* symaddr(T& sym) {
    void* p = nullptr;
    cudaGetSymbolAddress(&p, sym);
    return (float*)p;
}

extern "C" void kernel_launch(void* const* d_in, const int* in_sizes, int n_in,
                              void* d_out, int out_size) {
    const float* single      = (const float*)d_in[0];
    const float* pair        = (const float*)d_in[1];
    const float* rot         = (const float*)d_in[2];
    const float* trans       = (const float*)d_in[3];
    const float* rot_truth   = (const float*)d_in[4];
    const float* trans_truth = (const float*)d_in[5];
    const float* Wq  = (const float*)d_in[6];
    const float* Wk  = (const float*)d_in[7];
    const float* Wv  = (const float*)d_in[8];
    const float* Wqp = (const float*)d_in[9];
    const float* Wkp = (const float*)d_in[10];
    const float* Wvp = (const float*)d_in[11];
    const float* Wb  = (const float*)d_in[12];
    const float* Wo  = (const float*)d_in[13];
    const float* bo  = (const float*)d_in[14];
    const float* gamma_raw = (const float*)d_in[15];
    const float* ln1_g = (const float*)d_in[16];
    const float* ln1_b = (const float*)d_in[17];
    const float* ln2_g = (const float*)d_in[18];
    const float* ln2_b = (const float*)d_in[19];
    const float* W1 = (const float*)d_in[20];
    const float* b1 = (const float*)d_in[21];
    const float* W2 = (const float*)d_in[22];
    const float* b2 = (const float*)d_in[23];
    const float* W3 = (const float*)d_in[24];
    const float* b3 = (const float*)d_in[25];
    const float* Wbu = (const float*)d_in[26];
    const float* bbu = (const float*)d_in[27];
    float* out = (float*)d_out;

    float* pWf     = symaddr(g_Wf);
    float* pProj   = symaddr(g_proj);
    float* pConcat = symaddr(g_concat);
    float* pS1     = symaddr(g_s1);
    float* pH1     = symaddr(g_h1);
    float* pH2     = symaddr(g_h2);
    float* pH3     = symaddr(g_h3);

    const int BIAS_SMEM  = (128 * 132 + 12 * 132 + 128 * 12) * 4;   // 80064
    const int OPAIR_SMEM = (128 * 132 + 12 * 128) * 4;              // 73728
    cudaFuncSetAttribute(bias_k,  cudaFuncAttributeMaxDynamicSharedMemorySize, BIAS_SMEM);
    cudaFuncSetAttribute(opair_k, cudaFuncAttributeMaxDynamicSharedMemorySize, OPAIR_SMEM);

    fuse_w_k<<<(CSd * PROJD + 255) / 256, 256>>>(Wq, Wk, Wv, Wqp, Wkp, Wvp);

    sgemm_k<64,64,16,4,4,false,false,false><<<dim3(PROJD/64, Nn/64, 1), 256>>>(
        single, pWf, nullptr, pProj, Nn, PROJD, CSd, CSd);

    prep_k<<<Nn, 128>>>(rot, trans, gamma_raw);

    bias_k<<<Nn * 4, 256, BIAS_SMEM>>>(pair, Wb);       // writes WL*bias
    core_k<<<dim3(Nn/64, Nn/64, Hh), 256>>>();          // += WL*(E.F)
    softmax_k<<<Nn, Hh * 32>>>();
    opair_k<<<dim3(Nn, 4), 256, OPAIR_SMEM>>>(pair);
    opair_combine_k<<<Nn, 256>>>();
    ov_k<<<dim3(Nn/64, Hh), 256>>>();
    post_pt_k<<<(Nn * Hh * PVd + 255) / 256, 256>>>(rot, trans);

    sgemm_k<128,64,16,8,4,false,false,true><<<dim3(CSd/64, Nn/128, 4), 256>>>(
        pConcat, Wo, nullptr, symaddr(g_wop), Nn, CSd, OUTD, OUTD/4);
    ln1_k<<<Nn, CSd>>>(single, bo, ln1_g, ln1_b);

    sgemm_k<64,64,16,4,4,true,true,false><<<dim3(CSd/64, Nn/64, 1), 256>>>(
        pS1, W1, b1, pH1, Nn, CSd, CSd, CSd);
    sgemm_k<64,64,16,4,4,true,true,false><<<dim3(CSd/64, Nn/64, 1), 256>>>(
        pH1, W2, b2, pH2, Nn, CSd, CSd, CSd);
    sgemm_k<64,64,16,4,4,true,false,false><<<dim3(CSd/64, Nn/64, 1), 256>>>(
        pH2, W3, b3, pH3, Nn, CSd, CSd, CSd);
    ln2_k<<<Nn, CSd>>>(ln2_g, ln2_b, out);

    update_k<<<(Nn * 32 + 127) / 128, 128>>>(rot, trans, Wbu, bbu, out);
    loss_part_k<<<Nn, 256>>>(rot_truth, trans_truth);
    loss_final_k<<<1, 512>>>(out);
}

// round 7
// speedup vs baseline: 3.4669x; 1.1720x over previous
#include <cuda_runtime.h>
#include <math.h>

#define Nn 512
#define CSd 384
#define CZd 128
#define Hh 12
#define Cc 16
#define PQd 4
#define PVd 8
#define OUTD 2112
#define PROJD 1152
#define OQ 0
#define OK0 192
#define OV 384
#define OQP 576
#define OKP 720
#define OVP 864

__device__ float g_Wf[CSd * PROJD];
__device__ float g_proj[Nn * PROJD];
__device__ float g_gv[Nn * Hh * PVd * 3];
__device__ float g_B2[Nn * Hh * 48];
__device__ float g_E[Hh * Nn * 32], g_F[Hh * Nn * 32];
__device__ float g_logits[Nn * Hh * Nn];
__device__ float g_opP[8 * Nn * Hh * CZd];
__device__ float g_concat[Nn * OUTD];
__device__ float g_opt[Nn * Hh * PVd * 3];
__device__ float g_wop[4 * Nn * CSd];
__device__ float g_s1[Nn * CSd], g_h1[Nn * CSd], g_h2[Nn * CSd], g_h3[Nn * CSd], g_s2[Nn * CSd];
__device__ float g_rotn[Nn * 9], g_trn[Nn * 3];
__device__ float g_partial[Nn];

#define WLc 0.5773502691896258f
#define WCc 0.23570226039551584f

__device__ __forceinline__ void cp16(void* smem_dst, const void* gmem_src) {
    unsigned s = (unsigned)__cvta_generic_to_shared(smem_dst);
    asm volatile("cp.async.cg.shared.global [%0], [%1], 16;" :: "r"(s), "l"(gmem_src));
}
__device__ __forceinline__ void cp_commit() { asm volatile("cp.async.commit_group;"); }
template<int N> __device__ __forceinline__ void cp_wait() {
    asm volatile("cp.async.wait_group %0;" :: "n"(N));
}

// ---------------- fuse weights ----------------
__global__ void fuse_w_k(const float* __restrict__ Wq, const float* __restrict__ Wk,
                         const float* __restrict__ Wv, const float* __restrict__ Wqp,
                         const float* __restrict__ Wkp, const float* __restrict__ Wvp) {
    int idx = blockIdx.x * blockDim.x + threadIdx.x;
    if (idx >= CSd * PROJD) return;
    int r = idx / PROJD, c = idx % PROJD;
    float v;
    if (c < 192)        v = Wq [r * 192 + c];
    else if (c < 384)   v = Wk [r * 192 + (c - 192)];
    else if (c < 576)   v = Wv [r * 192 + (c - 384)];
    else if (c < 720)   v = Wqp[r * 144 + (c - 576)];
    else if (c < 864)   v = Wkp[r * 144 + (c - 720)];
    else                v = Wvp[r * 288 + (c - 864)];
    g_Wf[idx] = v;
}

// ---------------- double-buffered tiled SGEMM ----------------
template<int BM, int BN, int BK, int TM, int TN, bool BIAS, bool RELU, bool SPLITK>
__global__ void sgemm_k(const float* __restrict__ A, const float* __restrict__ B,
                        const float* __restrict__ bias, float* __restrict__ C,
                        int M, int N, int K, int KC) {
    const int THREADS = (BM / TM) * (BN / TN);
    __shared__ float As[2][BK][BM];
    __shared__ float Bs[2][BK][BN + 4];
    int n0 = blockIdx.x * BN, m0 = blockIdx.y * BM;
    int kstart = SPLITK ? blockIdx.z * KC : 0;
    if (SPLITK) C += (size_t)blockIdx.z * M * N;
    int tid = threadIdx.x;
    int tr = tid / (BN / TN), tc = tid % (BN / TN);
    float acc[TM][TN];
    #pragma unroll
    for (int i = 0; i < TM; i++)
        #pragma unroll
        for (int j = 0; j < TN; j++) acc[i][j] = 0.f;
    int nsteps = KC / BK;

    auto loadA = [&](int kt, int buf) {
        #pragma unroll
        for (int r = tid; r < BM * BK / 4; r += THREADS) {
            int arow = r / (BK / 4), aq = r % (BK / 4);
            float4 v = *(const float4*)&A[(size_t)(m0 + arow) * K + kstart + kt * BK + aq * 4];
            As[buf][aq * 4 + 0][arow] = v.x; As[buf][aq * 4 + 1][arow] = v.y;
            As[buf][aq * 4 + 2][arow] = v.z; As[buf][aq * 4 + 3][arow] = v.w;
        }
    };
    auto loadB = [&](int kt, int buf) {
        #pragma unroll
        for (int r = tid; r < BK * BN / 4; r += THREADS) {
            int brow = r / (BN / 4), bq = r % (BN / 4);
            cp16(&Bs[buf][brow][bq * 4], &B[(size_t)(kstart + kt * BK + brow) * N + n0 + bq * 4]);
        }
    };
    loadA(0, 0); loadB(0, 0); cp_commit();
    for (int kt = 0; kt < nsteps; kt++) {
        int buf = kt & 1;
        if (kt + 1 < nsteps) {
            loadA(kt + 1, buf ^ 1); loadB(kt + 1, buf ^ 1); cp_commit();
            cp_wait<1>();
        } else cp_wait<0>();
        __syncthreads();
        #pragma unroll
        for (int k = 0; k < BK; k++) {
            float ra[TM], rb[TN];
            #pragma unroll
            for (int i = 0; i < TM; i += 4)
                *(float4*)&ra[i] = *(const float4*)&As[buf][k][tr * TM + i];
            #pragma unroll
            for (int j = 0; j < TN; j += 4)
                *(float4*)&rb[j] = *(const float4*)&Bs[buf][k][tc * TN + j];
            #pragma unroll
            for (int i = 0; i < TM; i++)
                #pragma unroll
                for (int j = 0; j < TN; j++) acc[i][j] += ra[i] * rb[j];
        }
        __syncthreads();
    }
    #pragma unroll
    for (int i = 0; i < TM; i++) {
        int m = m0 + tr * TM + i;
        #pragma unroll
        for (int j = 0; j < TN; j++) {
            int n = n0 + tc * TN + j;
            float v = acc[i][j];
            if (BIAS) v += bias[n];
            if (RELU) v = fmaxf(v, 0.f);
            C[(size_t)m * N + n] = v;
        }
    }
}

// ---------------- prep: frames + E/F + packed B2 ----------------
__global__ void prep_k(const float* __restrict__ rot, const float* __restrict__ trans,
                       const float* __restrict__ gamma_raw) {
    __shared__ float R[9], T[3], gqS[144], gkS[144], sqqS[12], sqkS[12], wcgS[12];
    int n = blockIdx.x, tid = threadIdx.x;
    if (tid < 9) R[tid] = rot[n * 9 + tid];
    if (tid < 3) T[tid] = trans[n * 3 + tid];
    if (tid >= 16 && tid < 28) {
        int h = tid - 16;
        float x = gamma_raw[h];
        wcgS[h] = WCc * ((x > 20.f) ? x : log1pf(expf(x)));
    }
    __syncthreads();
    const float* base = &g_proj[(size_t)n * PROJD];
    for (int t = tid; t < 96; t += 128) {
        int which = t / 48, p = t % 48;
        const float* src = base + (which ? OKP : OQP) + p * 3;
        float b0 = src[0], b1 = src[1], b2 = src[2];
        float* dst = (which ? gkS : gqS) + p * 3;
        #pragma unroll
        for (int a = 0; a < 3; a++)
            dst[a] = R[a * 3 + 0] * b0 + R[a * 3 + 1] * b1 + R[a * 3 + 2] * b2 + T[a];
    }
    // gv -> g_gv AND packed g_B2
    for (int t = tid; t < 96; t += 128) {
        int h = t >> 3, p = t & 7;
        const float* src = base + OVP + t * 3;
        float b0 = src[0], b1 = src[1], b2 = src[2];
        #pragma unroll
        for (int a = 0; a < 3; a++) {
            float v = R[a * 3 + 0] * b0 + R[a * 3 + 1] * b1 + R[a * 3 + 2] * b2 + T[a];
            g_gv[n * 288 + t * 3 + a] = v;
            g_B2[n * 576 + h * 48 + 16 + p * 3 + a] = v;
        }
    }
    // v part of B2 + pad
    for (int t = tid; t < 192; t += 128) {
        int h = t >> 4, c = t & 15;
        g_B2[n * 576 + h * 48 + c] = base[OV + t];
    }
    for (int t = tid; t < 96; t += 128) {
        int h = t / 8, c = 40 + (t % 8);
        g_B2[n * 576 + h * 48 + c] = 0.f;
    }
    __syncthreads();
    if (tid < 24) {
        int h = tid >> 1, which = tid & 1;
        const float* g = (which ? gkS : gqS) + h * 12;
        float s = 0.f;
        #pragma unroll
        for (int e = 0; e < 12; e++) s += g[e] * g[e];
        (which ? sqkS : sqqS)[h] = s;
    }
    __syncthreads();
    for (int t = tid; t < Hh * 32; t += 128) {
        int h = t >> 5, c = t & 31;
        float wcg = wcgS[h];
        float e, f;
        if (c < 16)      { e = 0.25f * base[OQ + h * 16 + c]; f = base[OK0 + h * 16 + c]; }
        else if (c < 28) { e = wcg * gqS[h * 12 + c - 16];    f = gkS[h * 12 + c - 16]; }
        else if (c == 28){ e = sqqS[h];                        f = -0.5f * wcg; }
        else if (c == 29){ e = 1.f;                            f = -0.5f * wcg * sqkS[h]; }
        else             { e = 0.f;                            f = 0.f; }
        g_E[(size_t)((h << 9) | n) * 32 + c] = e;
        g_F[(size_t)((h << 9) | n) * 32 + c] = f;
    }
}

// ---------------- bias GEMM: register-tiled, broadcast Wb, 2-phase overlap ----------------
// thread: 2 j (jq, jq+64) x 12 h; zq quarter of z. smem comb across zq.
__global__ void __launch_bounds__(256) bias_k(const float* __restrict__ pair,
                                              const float* __restrict__ Wb) {
    extern __shared__ float sm[];
    float* As   = sm;                 // 128*132
    float* WbT  = As + 128 * 132;     // 12*132
    float* comb = WbT + 12 * 132;     // 3*64*24
    int blk = blockIdx.x;
    int i = blk >> 2, j0 = (blk & 3) << 7;
    int tid = threadIdx.x;
    // group 1: rows 0..63
    for (int r = tid; r < 64 * 32; r += 256) {
        int row = r >> 5, q = r & 31;
        cp16(&As[row * 132 + q * 4], &pair[((size_t)i * Nn + j0 + row) * CZd + q * 4]);
    }
    cp_commit();
    // group 2: rows 64..127
    for (int r = tid; r < 64 * 32; r += 256) {
        int row = 64 + (r >> 5), q = r & 31;
        cp16(&As[row * 132 + q * 4], &pair[((size_t)i * Nn + j0 + row) * CZd + q * 4]);
    }
    cp_commit();
    for (int t = tid; t < CZd * Hh; t += 256) WbT[(t % Hh) * 132 + (t / Hh)] = Wb[t];

    int zq = tid >> 6;      // 0..3 (32 z each)
    int jq = tid & 63;
    float acc[2][12];
    #pragma unroll
    for (int j2 = 0; j2 < 2; j2++)
        #pragma unroll
        for (int h = 0; h < 12; h++) acc[j2][h] = 0.f;

    cp_wait<1>();
    __syncthreads();
    {   // phase 1: j = jq (rows 0..63)
        const float4* ap = (const float4*)&As[jq * 132 + zq * 32];
        #pragma unroll
        for (int z4 = 0; z4 < 8; z4++) {
            float4 p = ap[z4];
            #pragma unroll
            for (int h = 0; h < 12; h++) {
                float4 w = *(const float4*)&WbT[h * 132 + zq * 32 + z4 * 4];
                acc[0][h] += p.x * w.x + p.y * w.y + p.z * w.z + p.w * w.w;
            }
        }
    }
    cp_wait<0>();
    __syncthreads();
    {   // phase 2: j = jq + 64
        const float4* ap = (const float4*)&As[(jq + 64) * 132 + zq * 32];
        #pragma unroll
        for (int z4 = 0; z4 < 8; z4++) {
            float4 p = ap[z4];
            #pragma unroll
            for (int h = 0; h < 12; h++) {
                float4 w = *(const float4*)&WbT[h * 132 + zq * 32 + z4 * 4];
                acc[1][h] += p.x * w.x + p.y * w.y + p.z * w.z + p.w * w.w;
            }
        }
    }
    if (zq > 0) {
        float* c = &comb[((zq - 1) * 64 + jq) * 24];
        #pragma unroll
        for (int h = 0; h < 12; h++) { c[h] = acc[0][h]; c[12 + h] = acc[1][h]; }
    }
    __syncthreads();
    if (zq == 0) {
        #pragma unroll
        for (int h = 0; h < 12; h++) {
            float s0 = acc[0][h], s1 = acc[1][h];
            #pragma unroll
            for (int g = 0; g < 3; g++) {
                s0 += comb[(g * 64 + jq) * 24 + h];
                s1 += comb[(g * 64 + jq) * 24 + 12 + h];
            }
            size_t rowb = ((size_t)i * Hh + h) * Nn + j0;
            g_logits[rowb + jq]      = WLc * s0;
            g_logits[rowb + 64 + jq] = WLc * s1;
        }
    }
}

// ---------------- logit core: ADDS WL*(E.F) on top of bias ----------------
__global__ void core_k() {
    __shared__ float As[32][64], BsT[32][64];
    int h = blockIdx.z, i0 = blockIdx.y * 64, j0 = blockIdx.x * 64;
    int tid = threadIdx.x;
    const float* Eh = &g_E[((size_t)h * Nn + i0) * 32];
    const float* Fh = &g_F[((size_t)h * Nn + j0) * 32];
    for (int t = tid; t < 512; t += 256) {
        int row = t >> 3, d4 = t & 7;
        float4 v = *(const float4*)&Eh[row * 32 + d4 * 4];
        As[d4 * 4 + 0][row] = v.x; As[d4 * 4 + 1][row] = v.y;
        As[d4 * 4 + 2][row] = v.z; As[d4 * 4 + 3][row] = v.w;
        float4 w = *(const float4*)&Fh[row * 32 + d4 * 4];
        BsT[d4 * 4 + 0][row] = w.x; BsT[d4 * 4 + 1][row] = w.y;
        BsT[d4 * 4 + 2][row] = w.z; BsT[d4 * 4 + 3][row] = w.w;
    }
    __syncthreads();
    int tr = tid / 16, tc = tid % 16;
    float acc[4][4];
    #pragma unroll
    for (int i = 0; i < 4; i++)
        #pragma unroll
        for (int j = 0; j < 4; j++) acc[i][j] = 0.f;
    #pragma unroll
    for (int d = 0; d < 32; d++) {
        float ra[4], rb[4];
        *(float4*)ra = *(const float4*)&As[d][tr * 4];
        *(float4*)rb = *(const float4*)&BsT[d][tc * 4];
        #pragma unroll
        for (int i = 0; i < 4; i++)
            #pragma unroll
            for (int j = 0; j < 4; j++) acc[i][j] += ra[i] * rb[j];
    }
    #pragma unroll
    for (int i = 0; i < 4; i++)
        #pragma unroll
        for (int j = 0; j < 4; j++) {
            size_t idx = ((size_t)(i0 + tr * 4 + i) * Hh + h) * Nn + j0 + tc * 4 + j;
            g_logits[idx] += WLc * acc[i][j];
        }
}

// ---------------- softmax: warp per head ----------------
__global__ void softmax_k() {
    int i = blockIdx.x;
    int w = threadIdx.x >> 5, lane = threadIdx.x & 31;
    float* L = &g_logits[((size_t)i * Hh + w) * Nn];
    float x[16];
    float m = -1e30f;
    #pragma unroll
    for (int l = 0; l < 16; l++) { x[l] = L[l * 32 + lane]; m = fmaxf(m, x[l]); }
    #pragma unroll
    for (int off = 16; off; off >>= 1) m = fmaxf(m, __shfl_xor_sync(0xffffffffu, m, off));
    float s = 0.f;
    #pragma unroll
    for (int l = 0; l < 16; l++) { x[l] = __expf(x[l] - m); s += x[l]; }
    #pragma unroll
    for (int off = 16; off; off >>= 1) s += __shfl_xor_sync(0xffffffffu, s, off);
    float inv = 1.f / s;
    #pragma unroll
    for (int l = 0; l < 16; l++) L[l * 32 + lane] = x[l] * inv;
}

// ---------------- o_pair partials: grid (i, 8 j-splits of 64), 128 thr ----------------
__global__ void __launch_bounds__(128) opair_k(const float* __restrict__ pair) {
    extern __shared__ float sm[];
    float* pairS = sm;                // 64*132
    float* attS  = pairS + 64 * 132;  // 12*64
    int i = blockIdx.x, js = blockIdx.y, j0 = js << 6;
    int tid = threadIdx.x;
    // group 1: rows 0..31
    for (int r = tid; r < 32 * 32; r += 128) {
        int row = r >> 5, q = r & 31;
        cp16(&pairS[row * 132 + q * 4], &pair[((size_t)i * Nn + j0 + row) * CZd + q * 4]);
    }
    cp_commit();
    // group 2: rows 32..63
    for (int r = tid; r < 32 * 32; r += 128) {
        int row = 32 + (r >> 5), q = r & 31;
        cp16(&pairS[row * 132 + q * 4], &pair[((size_t)i * Nn + j0 + row) * CZd + q * 4]);
    }
    cp_commit();
    for (int t = tid; t < Hh * 64; t += 128) {
        int h = t >> 6, j = t & 63;
        attS[t] = g_logits[((size_t)i * Hh + h) * Nn + j0 + j];
    }
    int ht = tid >> 5;   // 4 groups x 3 h
    int zq = tid & 31;   // 4 z each
    float acc[3][4];
    #pragma unroll
    for (int b = 0; b < 3; b++)
        #pragma unroll
        for (int a = 0; a < 4; a++) acc[b][a] = 0.f;
    const float* A0 = &attS[(ht * 3 + 0) * 64];
    const float* A1 = &attS[(ht * 3 + 1) * 64];
    const float* A2 = &attS[(ht * 3 + 2) * 64];

    cp_wait<1>();
    __syncthreads();
    #pragma unroll 4
    for (int j = 0; j < 32; j++) {
        float4 p = *(const float4*)&pairS[j * 132 + zq * 4];
        float v0 = A0[j], v1 = A1[j], v2 = A2[j];
        acc[0][0] += v0 * p.x; acc[0][1] += v0 * p.y; acc[0][2] += v0 * p.z; acc[0][3] += v0 * p.w;
        acc[1][0] += v1 * p.x; acc[1][1] += v1 * p.y; acc[1][2] += v1 * p.z; acc[1][3] += v1 * p.w;
        acc[2][0] += v2 * p.x; acc[2][1] += v2 * p.y; acc[2][2] += v2 * p.z; acc[2][3] += v2 * p.w;
    }
    cp_wait<0>();
    __syncthreads();
    #pragma unroll 4
    for (int j = 32; j < 64; j++) {
        float4 p = *(const float4*)&pairS[j * 132 + zq * 4];
        float v0 = A0[j], v1 = A1[j], v2 = A2[j];
        acc[0][0] += v0 * p.x; acc[0][1] += v0 * p.y; acc[0][2] += v0 * p.z; acc[0][3] += v0 * p.w;
        acc[1][0] += v1 * p.x; acc[1][1] += v1 * p.y; acc[1][2] += v1 * p.z; acc[1][3] += v1 * p.w;
        acc[2][0] += v2 * p.x; acc[2][1] += v2 * p.y; acc[2][2] += v2 * p.z; acc[2][3] += v2 * p.w;
    }
    float* dst = &g_opP[((size_t)js * Nn + i) * (Hh * CZd)];
    #pragma unroll
    for (int b = 0; b < 3; b++)
        *(float4*)&dst[(ht * 3 + b) * CZd + zq * 4] =
            make_float4(acc[b][0], acc[b][1], acc[b][2], acc[b][3]);
}

__global__ void opair_combine_k() {
    int i = blockIdx.x, tid = threadIdx.x;
    const size_t S = (size_t)Nn * Hh * CZd;
    for (int c = tid; c < Hh * CZd; c += 256) {
        size_t base = (size_t)i * (Hh * CZd) + c;
        float s = 0.f;
        #pragma unroll
        for (int g = 0; g < 8; g++) s += g_opP[g * S + base];
        g_concat[(size_t)i * OUTD + 576 + c] = s;
    }
}

// ---------------- o_v & o_pt: packed B2, double-buffered ----------------
__global__ void ov_k() {
    __shared__ float As[2][64 * 36];
    __shared__ float Bs[2][32 * 48];
    int i0 = blockIdx.x * 64, h = blockIdx.y;
    int tid = threadIdx.x;
    int tr = tid / 16, tc = tid % 16;
    float acc[4][3];
    #pragma unroll
    for (int a = 0; a < 4; a++)
        #pragma unroll
        for (int b = 0; b < 3; b++) acc[a][b] = 0.f;

    auto loadA = [&](int chunk, int buf) {
        int j0 = chunk * 32;
        for (int t = tid; t < 512; t += 256) {
            int row = t >> 3, q = t & 7;
            cp16(&As[buf][row * 36 + q * 4],
                 &g_logits[((size_t)(i0 + row) * Hh + h) * Nn + j0 + q * 4]);
        }
    };
    auto loadB = [&](int chunk, int buf) {
        int j0 = chunk * 32;
        for (int t = tid; t < 384; t += 256) {
            int row = t / 12, q = t % 12;
            cp16(&Bs[buf][row * 48 + q * 4], &g_B2[(size_t)(j0 + row) * 576 + h * 48 + q * 4]);
        }
    };
    loadA(0, 0); loadB(0, 0); cp_commit();
    for (int chunk = 0; chunk < 16; chunk++) {
        int buf = chunk & 1;
        if (chunk + 1 < 16) {
            loadA(chunk + 1, buf ^ 1); loadB(chunk + 1, buf ^ 1); cp_commit();
            cp_wait<1>();
        } else cp_wait<0>();
        __syncthreads();
        #pragma unroll 8
        for (int jl = 0; jl < 32; jl++) {
            float ra[4], rb[3];
            #pragma unroll
            for (int a = 0; a < 4; a++) ra[a] = As[buf][(tr * 4 + a) * 36 + jl];
            #pragma unroll
            for (int b = 0; b < 3; b++) rb[b] = Bs[buf][jl * 48 + tc * 3 + b];
            #pragma unroll
            for (int a = 0; a < 4; a++)
                #pragma unroll
                for (int b = 0; b < 3; b++) acc[a][b] += ra[a] * rb[b];
        }
        __syncthreads();
    }
    #pragma unroll
    for (int a = 0; a < 4; a++) {
        int i = i0 + tr * 4 + a;
        #pragma unroll
        for (int b = 0; b < 3; b++) {
            int c = tc * 3 + b;
            if (c < 16)      g_concat[(size_t)i * OUTD + h * Cc + c] = acc[a][b];
            else if (c < 40) g_opt[i * (Hh * 24) + h * 24 + (c - 16)] = acc[a][b];
        }
    }
}

__global__ void post_pt_k(const float* __restrict__ rot, const float* __restrict__ trans) {
    int idx = blockIdx.x * blockDim.x + threadIdx.x;
    if (idx >= Nn * Hh * PVd) return;
    int i = idx / (Hh * PVd), t = idx % (Hh * PVd);
    float b0 = g_opt[i * (Hh * 24) + t * 3 + 0] - trans[i * 3 + 0];
    float b1 = g_opt[i * (Hh * 24) + t * 3 + 1] - trans[i * 3 + 1];
    float b2 = g_opt[i * (Hh * 24) + t * 3 + 2] - trans[i * 3 + 2];
    float l0 = rot[i * 9 + 0] * b0 + rot[i * 9 + 3] * b1 + rot[i * 9 + 6] * b2;
    float l1 = rot[i * 9 + 1] * b0 + rot[i * 9 + 4] * b1 + rot[i * 9 + 7] * b2;
    float l2 = rot[i * 9 + 2] * b0 + rot[i * 9 + 5] * b1 + rot[i * 9 + 8] * b2;
    float* crow = &g_concat[(size_t)i * OUTD];
    crow[192 + t * 3 + 0] = l0;
    crow[192 + t * 3 + 1] = l1;
    crow[192 + t * 3 + 2] = l2;
    crow[480 + t] = sqrtf(l0 * l0 + l1 * l1 + l2 * l2 + 1e-8f);
}

// ---------------- layer norms ----------------
__device__ __forceinline__ float blockSum384(float v, float* red) {
    int tid = threadIdx.x;
    red[tid] = v;
    if (tid < 128) red[384 + tid] = 0.f;
    __syncthreads();
    for (int s = 256; s > 0; s >>= 1) {
        if (tid < s) red[tid] += red[tid + s];
        __syncthreads();
    }
    float r = red[0];
    __syncthreads();
    return r;
}

__global__ void ln1_k(const float* __restrict__ single_in, const float* __restrict__ bo,
                      const float* __restrict__ g, const float* __restrict__ b) {
    __shared__ float red[512];
    int row = blockIdx.x, tid = threadIdx.x;
    float x = single_in[row * CSd + tid] + bo[tid];
    #pragma unroll
    for (int z = 0; z < 4; z++) x += g_wop[(size_t)z * Nn * CSd + row * CSd + tid];
    float mean = blockSum384(x, red) * (1.f / CSd);
    float dx = x - mean;
    float var = blockSum384(dx * dx, red) * (1.f / CSd);
    g_s1[row * CSd + tid] = dx * rsqrtf(var + 1e-5f) * g[tid] + b[tid];
}

__global__ void ln2_k(const float* __restrict__ g, const float* __restrict__ b,
                      float* __restrict__ out) {
    __shared__ float red[512];
    int row = blockIdx.x, tid = threadIdx.x;
    float x = g_s1[row * CSd + tid] + g_h3[row * CSd + tid];
    float mean = blockSum384(x, red) * (1.f / CSd);
    float dx = x - mean;
    float var = blockSum384(dx * dx, red) * (1.f / CSd);
    float y = dx * rsqrtf(var + 1e-5f) * g[tid] + b[tid];
    out[row * CSd + tid] = y;
    g_s2[row * CSd + tid] = y;
}

// ---------------- backbone update ----------------
__global__ void update_k(const float* __restrict__ rot, const float* __restrict__ trans,
                         const float* __restrict__ Wbu, const float* __restrict__ bbu,
                         float* __restrict__ out) {
    int gtid = blockIdx.x * blockDim.x + threadIdx.x;
    int n = gtid >> 5, lane = gtid & 31;
    if (n >= Nn) return;
    float u[6] = {0, 0, 0, 0, 0, 0};
    for (int s = lane; s < CSd; s += 32) {
        float x = g_s2[n * CSd + s];
        #pragma unroll
        for (int j = 0; j < 6; j++) u[j] += x * Wbu[s * 6 + j];
    }
    #pragma unroll
    for (int j = 0; j < 6; j++)
        #pragma unroll
        for (int off = 16; off; off >>= 1) u[j] += __shfl_xor_sync(0xffffffffu, u[j], off);
    if (lane != 0) return;
    #pragma unroll
    for (int j = 0; j < 6; j++) u[j] += bbu[j];
    float b = u[0], c = u[1], d = u[2];
    float inq = rsqrtf(1.f + b * b + c * c + d * d);
    float a = inq; b *= inq; c *= inq; d *= inq;
    float R[9] = {
        a*a + b*b - c*c - d*d, 2.f*(b*c - a*d),       2.f*(b*d + a*c),
        2.f*(b*c + a*d),       a*a - b*b + c*c - d*d, 2.f*(c*d - a*b),
        2.f*(b*d - a*c),       2.f*(c*d + a*b),       a*a - b*b - c*c + d*d };
    float rn[9];
    #pragma unroll
    for (int aa = 0; aa < 3; aa++)
        #pragma unroll
        for (int cc = 0; cc < 3; cc++) {
            float s2 = 0.f;
            #pragma unroll
            for (int bx = 0; bx < 3; bx++) s2 += rot[n * 9 + aa * 3 + bx] * R[bx * 3 + cc];
            rn[aa * 3 + cc] = s2;
        }
    float t0 = u[3], t1 = u[4], t2 = u[5];
    float tn[3];
    #pragma unroll
    for (int aa = 0; aa < 3; aa++)
        tn[aa] = rot[n * 9 + aa * 3 + 0] * t0 + rot[n * 9 + aa * 3 + 1] * t1 +
                 rot[n * 9 + aa * 3 + 2] * t2 + trans[n * 3 + aa];
    #pragma unroll
    for (int e = 0; e < 9; e++) { g_rotn[n * 9 + e] = rn[e]; out[Nn * CSd + n * 9 + e] = rn[e]; }
    #pragma unroll
    for (int e = 0; e < 3; e++) { g_trn[n * 3 + e] = tn[e]; out[Nn * CSd + Nn * 9 + n * 3 + e] = tn[e]; }
}

// ---------------- loss ----------------
__global__ void loss_part_k(const float* __restrict__ rt, const float* __restrict__ tt) {
    int i = blockIdx.x, tid = threadIdx.x;
    __shared__ float red[256];
    float rn[9], rte[9], tni[3], tti[3];
    #pragma unroll
    for (int e = 0; e < 9; e++) { rn[e] = g_rotn[i * 9 + e]; rte[e] = rt[i * 9 + e]; }
    #pragma unroll
    for (int e = 0; e < 3; e++) { tni[e] = g_trn[i * 3 + e]; tti[e] = tt[i * 3 + e]; }
    float s = 0.f;
    for (int j = tid; j < Nn; j += 256) {
        float db0 = g_trn[j * 3 + 0] - tni[0];
        float db1 = g_trn[j * 3 + 1] - tni[1];
        float db2 = g_trn[j * 3 + 2] - tni[2];
        float dp0 = rn[0] * db0 + rn[3] * db1 + rn[6] * db2;
        float dp1 = rn[1] * db0 + rn[4] * db1 + rn[7] * db2;
        float dp2 = rn[2] * db0 + rn[5] * db1 + rn[8] * db2;
        float eb0 = tt[j * 3 + 0] - tti[0];
        float eb1 = tt[j * 3 + 1] - tti[1];
        float eb2 = tt[j * 3 + 2] - tti[2];
        float dt0 = rte[0] * eb0 + rte[3] * eb1 + rte[6] * eb2;
        float dt1 = rte[1] * eb0 + rte[4] * eb1 + rte[7] * eb2;
        float dt2 = rte[2] * eb0 + rte[5] * eb1 + rte[8] * eb2;
        float d0 = dp0 - dt0, d1 = dp1 - dt1, d2 = dp2 - dt2;
        float dd = sqrtf(d0 * d0 + d1 * d1 + d2 * d2 + 1e-12f);
        s += fminf(dd, 10.f);
    }
    red[tid] = s; __syncthreads();
    for (int st = 128; st > 0; st >>= 1) {
        if (tid < st) red[tid] += red[tid + st];
        __syncthreads();
    }
    if (tid == 0) g_partial[i] = red[0];
}

__global__ void loss_final_k(float* __restrict__ out) {
    __shared__ float red[512];
    int tid = threadIdx.x;
    red[tid] = g_partial[tid];
    __syncthreads();
    for (int s = 256; s > 0; s >>= 1) {
        if (tid < s) red[tid] += red[tid + s];
        __syncthreads();
    }
    if (tid == 0)
        out[Nn * CSd + Nn * 9 + Nn * 3] = red[0] / ((float)Nn * (float)Nn) * 0.1f;
}

// ---------------- host ----------------
template <typename T>
static float* symaddr(T& sym) {
    void* p = nullptr;
    cudaGetSymbolAddress(&p, sym);
    return (float*)p;
}

extern "C" void kernel_launch(void* const* d_in, const int* in_sizes, int n_in,
                              void* d_out, int out_size) {
    const float* single      = (const float*)d_in[0];
    const float* pair        = (const float*)d_in[1];
    const float* rot         = (const float*)d_in[2];
    const float* trans       = (const float*)d_in[3];
    const float* rot_truth   = (const float*)d_in[4];
    const float* trans_truth = (const float*)d_in[5];
    const float* Wq  = (const float*)d_in[6];
    const float* Wk  = (const float*)d_in[7];
    const float* Wv  = (const float*)d_in[8];
    const float* Wqp = (const float*)d_in[9];
    const float* Wkp = (const float*)d_in[10];
    const float* Wvp = (const float*)d_in[11];
    const float* Wb  = (const float*)d_in[12];
    const float* Wo  = (const float*)d_in[13];
    const float* bo  = (const float*)d_in[14];
    const float* gamma_raw = (const float*)d_in[15];
    const float* ln1_g = (const float*)d_in[16];
    const float* ln1_b = (const float*)d_in[17];
    const float* ln2_g = (const float*)d_in[18];
    const float* ln2_b = (const float*)d_in[19];
    const float* W1 = (const float*)d_in[20];
    const float* b1 = (const float*)d_in[21];
    const float* W2 = (const float*)d_in[22];
    const float* b2 = (const float*)d_in[23];
    const float* W3 = (const float*)d_in[24];
    const float* b3 = (const float*)d_in[25];
    const float* Wbu = (const float*)d_in[26];
    const float* bbu = (const float*)d_in[27];
    float* out = (float*)d_out;

    float* pWf     = symaddr(g_Wf);
    float* pProj   = symaddr(g_proj);
    float* pConcat = symaddr(g_concat);
    float* pS1     = symaddr(g_s1);
    float* pH1     = symaddr(g_h1);
    float* pH2     = symaddr(g_h2);
    float* pH3     = symaddr(g_h3);

    const int BIAS_SMEM  = (128 * 132 + 12 * 132 + 3 * 64 * 24) * 4;  // 92352
    const int OPAIR_SMEM = (64 * 132 + 12 * 64) * 4;                  // 36864
    cudaFuncSetAttribute(bias_k,  cudaFuncAttributeMaxDynamicSharedMemorySize, BIAS_SMEM);
    cudaFuncSetAttribute(opair_k, cudaFuncAttributeMaxDynamicSharedMemorySize, OPAIR_SMEM);

    fuse_w_k<<<(CSd * PROJD + 255) / 256, 256>>>(Wq, Wk, Wv, Wqp, Wkp, Wvp);

    sgemm_k<64,64,16,4,4,false,false,false><<<dim3(PROJD/64, Nn/64, 1), 256>>>(
        single, pWf, nullptr, pProj, Nn, PROJD, CSd, CSd);

    prep_k<<<Nn, 128>>>(rot, trans, gamma_raw);

    bias_k<<<Nn * 4, 256, BIAS_SMEM>>>(pair, Wb);
    core_k<<<dim3(Nn/64, Nn/64, Hh), 256>>>();
    softmax_k<<<Nn, Hh * 32>>>();
    opair_k<<<dim3(Nn, 8), 128, OPAIR_SMEM>>>(pair);
    opair_combine_k<<<Nn, 256>>>();
    ov_k<<<dim3(Nn/64, Hh), 256>>>();
    post_pt_k<<<(Nn * Hh * PVd + 255) / 256, 256>>>(rot, trans);

    sgemm_k<128,64,16,8,4,false,false,true><<<dim3(CSd/64, Nn/128, 4), 256>>>(
        pConcat, Wo, nullptr, symaddr(g_wop), Nn, CSd, OUTD, OUTD/4);
    ln1_k<<<Nn, CSd>>>(single, bo, ln1_g, ln1_b);

    sgemm_k<64,64,16,4,4,true,true,false><<<dim3(CSd/64, Nn/64, 1), 256>>>(
        pS1, W1, b1, pH1, Nn, CSd, CSd, CSd);
    sgemm_k<64,64,16,4,4,true,true,false><<<dim3(CSd/64, Nn/64, 1), 256>>>(
        pH1, W2, b2, pH2, Nn, CSd, CSd, CSd);
    sgemm_k<64,64,16,4,4,true,false,false><<<dim3(CSd/64, Nn/64, 1), 256>>>(
        pH2, W3, b3, pH3, Nn, CSd, CSd, CSd);
    ln2_k<<<Nn, CSd>>>(ln2_g, ln2_b, out);

    update_k<<<(Nn * 32 + 127) / 128, 128>>>(rot, trans, Wbu, bbu, out);
    loss_part_k<<<Nn, 256>>>(rot_truth, trans_truth);
    loss_final_k<<<1, 512>>>(out);
}

// round 8
// speedup vs baseline: 3.4773x; 1.0030x over previous
#include <cuda_runtime.h>
#include <math.h>

#define Nn 512
#define CSd 384
#define CZd 128
#define Hh 12
#define Cc 16
#define PQd 4
#define PVd 8
#define OUTD 2112
#define PROJD 1152
#define OQ 0
#define OK0 192
#define OV 384
#define OQP 576
#define OKP 720
#define OVP 864

__device__ float g_Wf[CSd * PROJD];
__device__ float g_proj[Nn * PROJD];
__device__ float g_gv[Nn * Hh * PVd * 3];
__device__ float g_B2[Nn * Hh * 48];
__device__ float g_E[Hh * Nn * 32], g_F[Hh * Nn * 32];
__device__ float g_logits[Nn * Hh * Nn];      // core logits -> e (unnormalized) -> attention
__device__ float g_opP[8 * Nn * Hh * CZd];    // o_pair partials per j-slice
__device__ float g_ms[Nn * Hh * 8 * 2];       // per (i,h,js): m, s
__device__ float g_fct[Nn * Hh * 8];          // per (i,h,js): exp(m_js-m_g)/s_g
__device__ float g_concat[Nn * OUTD];
__device__ float g_opt[Nn * Hh * PVd * 3];
__device__ float g_wop[4 * Nn * CSd];
__device__ float g_s1[Nn * CSd], g_h1[Nn * CSd], g_h2[Nn * CSd], g_h3[Nn * CSd], g_s2[Nn * CSd];
__device__ float g_rotn[Nn * 9], g_trn[Nn * 3];
__device__ float g_partial[Nn];

#define WLc 0.5773502691896258f
#define WCc 0.23570226039551584f

__device__ __forceinline__ void cp16(void* smem_dst, const void* gmem_src) {
    unsigned s = (unsigned)__cvta_generic_to_shared(smem_dst);
    asm volatile("cp.async.cg.shared.global [%0], [%1], 16;" :: "r"(s), "l"(gmem_src));
}
__device__ __forceinline__ void cp_commit() { asm volatile("cp.async.commit_group;"); }
template<int N> __device__ __forceinline__ void cp_wait() {
    asm volatile("cp.async.wait_group %0;" :: "n"(N));
}

// ---------------- fuse weights ----------------
__global__ void fuse_w_k(const float* __restrict__ Wq, const float* __restrict__ Wk,
                         const float* __restrict__ Wv, const float* __restrict__ Wqp,
                         const float* __restrict__ Wkp, const float* __restrict__ Wvp) {
    int idx = blockIdx.x * blockDim.x + threadIdx.x;
    if (idx >= CSd * PROJD) return;
    int r = idx / PROJD, c = idx % PROJD;
    float v;
    if (c < 192)        v = Wq [r * 192 + c];
    else if (c < 384)   v = Wk [r * 192 + (c - 192)];
    else if (c < 576)   v = Wv [r * 192 + (c - 384)];
    else if (c < 720)   v = Wqp[r * 144 + (c - 576)];
    else if (c < 864)   v = Wkp[r * 144 + (c - 720)];
    else                v = Wvp[r * 288 + (c - 864)];
    g_Wf[idx] = v;
}

// ---------------- double-buffered tiled SGEMM ----------------
template<int BM, int BN, int BK, int TM, int TN, bool BIAS, bool RELU, bool SPLITK>
__global__ void sgemm_k(const float* __restrict__ A, const float* __restrict__ B,
                        const float* __restrict__ bias, float* __restrict__ C,
                        int M, int N, int K, int KC) {
    const int THREADS = (BM / TM) * (BN / TN);
    __shared__ float As[2][BK][BM];
    __shared__ float Bs[2][BK][BN + 4];
    int n0 = blockIdx.x * BN, m0 = blockIdx.y * BM;
    int kstart = SPLITK ? blockIdx.z * KC : 0;
    if (SPLITK) C += (size_t)blockIdx.z * M * N;
    int tid = threadIdx.x;
    int tr = tid / (BN / TN), tc = tid % (BN / TN);
    float acc[TM][TN];
    #pragma unroll
    for (int i = 0; i < TM; i++)
        #pragma unroll
        for (int j = 0; j < TN; j++) acc[i][j] = 0.f;
    int nsteps = KC / BK;

    auto loadA = [&](int kt, int buf) {
        #pragma unroll
        for (int r = tid; r < BM * BK / 4; r += THREADS) {
            int arow = r / (BK / 4), aq = r % (BK / 4);
            float4 v = *(const float4*)&A[(size_t)(m0 + arow) * K + kstart + kt * BK + aq * 4];
            As[buf][aq * 4 + 0][arow] = v.x; As[buf][aq * 4 + 1][arow] = v.y;
            As[buf][aq * 4 + 2][arow] = v.z; As[buf][aq * 4 + 3][arow] = v.w;
        }
    };
    auto loadB = [&](int kt, int buf) {
        #pragma unroll
        for (int r = tid; r < BK * BN / 4; r += THREADS) {
            int brow = r / (BN / 4), bq = r % (BN / 4);
            cp16(&Bs[buf][brow][bq * 4], &B[(size_t)(kstart + kt * BK + brow) * N + n0 + bq * 4]);
        }
    };
    loadA(0, 0); loadB(0, 0); cp_commit();
    for (int kt = 0; kt < nsteps; kt++) {
        int buf = kt & 1;
        if (kt + 1 < nsteps) {
            loadA(kt + 1, buf ^ 1); loadB(kt + 1, buf ^ 1); cp_commit();
            cp_wait<1>();
        } else cp_wait<0>();
        __syncthreads();
        #pragma unroll
        for (int k = 0; k < BK; k++) {
            float ra[TM], rb[TN];
            #pragma unroll
            for (int i = 0; i < TM; i += 4)
                *(float4*)&ra[i] = *(const float4*)&As[buf][k][tr * TM + i];
            #pragma unroll
            for (int j = 0; j < TN; j += 4)
                *(float4*)&rb[j] = *(const float4*)&Bs[buf][k][tc * TN + j];
            #pragma unroll
            for (int i = 0; i < TM; i++)
                #pragma unroll
                for (int j = 0; j < TN; j++) acc[i][j] += ra[i] * rb[j];
        }
        __syncthreads();
    }
    #pragma unroll
    for (int i = 0; i < TM; i++) {
        int m = m0 + tr * TM + i;
        #pragma unroll
        for (int j = 0; j < TN; j++) {
            int n = n0 + tc * TN + j;
            float v = acc[i][j];
            if (BIAS) v += bias[n];
            if (RELU) v = fmaxf(v, 0.f);
            C[(size_t)m * N + n] = v;
        }
    }
}

// ---------------- prep: frames + E/F + packed B2 ----------------
__global__ void prep_k(const float* __restrict__ rot, const float* __restrict__ trans,
                       const float* __restrict__ gamma_raw) {
    __shared__ float R[9], T[3], gqS[144], gkS[144], sqqS[12], sqkS[12], wcgS[12];
    int n = blockIdx.x, tid = threadIdx.x;
    if (tid < 9) R[tid] = rot[n * 9 + tid];
    if (tid < 3) T[tid] = trans[n * 3 + tid];
    if (tid >= 16 && tid < 28) {
        int h = tid - 16;
        float x = gamma_raw[h];
        wcgS[h] = WCc * ((x > 20.f) ? x : log1pf(expf(x)));
    }
    __syncthreads();
    const float* base = &g_proj[(size_t)n * PROJD];
    for (int t = tid; t < 96; t += 128) {
        int which = t / 48, p = t % 48;
        const float* src = base + (which ? OKP : OQP) + p * 3;
        float b0 = src[0], b1 = src[1], b2 = src[2];
        float* dst = (which ? gkS : gqS) + p * 3;
        #pragma unroll
        for (int a = 0; a < 3; a++)
            dst[a] = R[a * 3 + 0] * b0 + R[a * 3 + 1] * b1 + R[a * 3 + 2] * b2 + T[a];
    }
    for (int t = tid; t < 96; t += 128) {
        int h = t >> 3, p = t & 7;
        const float* src = base + OVP + t * 3;
        float b0 = src[0], b1 = src[1], b2 = src[2];
        #pragma unroll
        for (int a = 0; a < 3; a++) {
            float v = R[a * 3 + 0] * b0 + R[a * 3 + 1] * b1 + R[a * 3 + 2] * b2 + T[a];
            g_gv[n * 288 + t * 3 + a] = v;
            g_B2[n * 576 + h * 48 + 16 + p * 3 + a] = v;
        }
    }
    for (int t = tid; t < 192; t += 128) {
        int h = t >> 4, c = t & 15;
        g_B2[n * 576 + h * 48 + c] = base[OV + t];
    }
    for (int t = tid; t < 96; t += 128) {
        int h = t / 8, c = 40 + (t % 8);
        g_B2[n * 576 + h * 48 + c] = 0.f;
    }
    __syncthreads();
    if (tid < 24) {
        int h = tid >> 1, which = tid & 1;
        const float* g = (which ? gkS : gqS) + h * 12;
        float s = 0.f;
        #pragma unroll
        for (int e = 0; e < 12; e++) s += g[e] * g[e];
        (which ? sqkS : sqqS)[h] = s;
    }
    __syncthreads();
    for (int t = tid; t < Hh * 32; t += 128) {
        int h = t >> 5, c = t & 31;
        float wcg = wcgS[h];
        float e, f;
        if (c < 16)      { e = 0.25f * base[OQ + h * 16 + c]; f = base[OK0 + h * 16 + c]; }
        else if (c < 28) { e = wcg * gqS[h * 12 + c - 16];    f = gkS[h * 12 + c - 16]; }
        else if (c == 28){ e = sqqS[h];                        f = -0.5f * wcg; }
        else if (c == 29){ e = 1.f;                            f = -0.5f * wcg * sqkS[h]; }
        else             { e = 0.f;                            f = 0.f; }
        g_E[(size_t)((h << 9) | n) * 32 + c] = e;
        g_F[(size_t)((h << 9) | n) * 32 + c] = f;
    }
}

// ---------------- logit core: WRITES WL*(E.F) ----------------
__global__ void core_k() {
    __shared__ float As[32][64], BsT[32][64];
    int h = blockIdx.z, i0 = blockIdx.y * 64, j0 = blockIdx.x * 64;
    int tid = threadIdx.x;
    const float* Eh = &g_E[((size_t)h * Nn + i0) * 32];
    const float* Fh = &g_F[((size_t)h * Nn + j0) * 32];
    for (int t = tid; t < 512; t += 256) {
        int row = t >> 3, d4 = t & 7;
        float4 v = *(const float4*)&Eh[row * 32 + d4 * 4];
        As[d4 * 4 + 0][row] = v.x; As[d4 * 4 + 1][row] = v.y;
        As[d4 * 4 + 2][row] = v.z; As[d4 * 4 + 3][row] = v.w;
        float4 w = *(const float4*)&Fh[row * 32 + d4 * 4];
        BsT[d4 * 4 + 0][row] = w.x; BsT[d4 * 4 + 1][row] = w.y;
        BsT[d4 * 4 + 2][row] = w.z; BsT[d4 * 4 + 3][row] = w.w;
    }
    __syncthreads();
    int tr = tid / 16, tc = tid % 16;
    float acc[4][4];
    #pragma unroll
    for (int i = 0; i < 4; i++)
        #pragma unroll
        for (int j = 0; j < 4; j++) acc[i][j] = 0.f;
    #pragma unroll
    for (int d = 0; d < 32; d++) {
        float ra[4], rb[4];
        *(float4*)ra = *(const float4*)&As[d][tr * 4];
        *(float4*)rb = *(const float4*)&BsT[d][tc * 4];
        #pragma unroll
        for (int i = 0; i < 4; i++)
            #pragma unroll
            for (int j = 0; j < 4; j++) acc[i][j] += ra[i] * rb[j];
    }
    #pragma unroll
    for (int i = 0; i < 4; i++)
        #pragma unroll
        for (int j = 0; j < 4; j++) {
            size_t idx = ((size_t)(i0 + tr * 4 + i) * Hh + h) * Nn + j0 + tc * 4 + j;
            g_logits[idx] = WLc * acc[i][j];
        }
}

// ---------------- FLASH2: bias + local softmax + o_pair partial, ONE pair pass ----------------
// grid (Nn, 8), 128 threads. j-slice of 64.
// smem: pairS[64*132] | WbT[12*132] | lS[12*64] | comb[3*32*24]
__global__ void __launch_bounds__(128) flash2_k(const float* __restrict__ pair,
                                                const float* __restrict__ Wb) {
    extern __shared__ float sm[];
    float* pairS = sm;                  // 8448
    float* WbT   = pairS + 8448;        // 1584
    float* lS    = WbT + 1584;          // 768
    float* comb  = lS + 768;            // 2304
    int i = blockIdx.x, js = blockIdx.y, j0 = js << 6;
    int tid = threadIdx.x;

    // pair rows 0..31
    for (int r = tid; r < 32 * 32; r += 128) {
        int row = r >> 5, q = r & 31;
        cp16(&pairS[row * 132 + q * 4], &pair[((size_t)i * Nn + j0 + row) * CZd + q * 4]);
    }
    cp_commit();
    // pair rows 32..63
    for (int r = tid; r < 32 * 32; r += 128) {
        int row = 32 + (r >> 5), q = r & 31;
        cp16(&pairS[row * 132 + q * 4], &pair[((size_t)i * Nn + j0 + row) * CZd + q * 4]);
    }
    cp_commit();
    // Wb transpose + core logits
    for (int t = tid; t < CZd * Hh; t += 128) WbT[(t % Hh) * 132 + (t / Hh)] = Wb[t];
    for (int t = tid; t < 192; t += 128) {
        int h = t >> 4, q = t & 15;
        *(float4*)&lS[h * 64 + q * 4] =
            *(const float4*)&g_logits[((size_t)i * Hh + h) * Nn + j0 + q * 4];
    }

    int zq = tid >> 5;      // 0..3, 32 z each (warp-uniform)
    int jq = tid & 31;      // thread j's: jq and jq+32
    float acc[2][12];
    #pragma unroll
    for (int j2 = 0; j2 < 2; j2++)
        #pragma unroll
        for (int h = 0; h < 12; h++) acc[j2][h] = 0.f;

    cp_wait<1>();
    __syncthreads();
    {   // phase 1: j = jq (rows 0..31)
        const float4* ap = (const float4*)&pairS[jq * 132 + zq * 32];
        #pragma unroll
        for (int z4 = 0; z4 < 8; z4++) {
            float4 p = ap[z4];
            #pragma unroll
            for (int h = 0; h < 12; h++) {
                float4 w = *(const float4*)&WbT[h * 132 + zq * 32 + z4 * 4];
                acc[0][h] += p.x * w.x + p.y * w.y + p.z * w.z + p.w * w.w;
            }
        }
    }
    cp_wait<0>();
    __syncthreads();
    {   // phase 2: j = jq + 32
        const float4* ap = (const float4*)&pairS[(jq + 32) * 132 + zq * 32];
        #pragma unroll
        for (int z4 = 0; z4 < 8; z4++) {
            float4 p = ap[z4];
            #pragma unroll
            for (int h = 0; h < 12; h++) {
                float4 w = *(const float4*)&WbT[h * 132 + zq * 32 + z4 * 4];
                acc[1][h] += p.x * w.x + p.y * w.y + p.z * w.z + p.w * w.w;
            }
        }
    }
    if (zq > 0) {
        float* c = &comb[((zq - 1) * 32 + jq) * 24];
        #pragma unroll
        for (int h = 0; h < 12; h++) { c[h] = acc[0][h]; c[12 + h] = acc[1][h]; }
    }
    __syncthreads();
    if (zq == 0) {
        #pragma unroll
        for (int h = 0; h < 12; h++) {
            float s0 = acc[0][h], s1 = acc[1][h];
            #pragma unroll
            for (int g = 0; g < 3; g++) {
                s0 += comb[(g * 32 + jq) * 24 + h];
                s1 += comb[(g * 32 + jq) * 24 + 12 + h];
            }
            lS[h * 64 + jq]      += WLc * s0;
            lS[h * 64 + 32 + jq] += WLc * s1;
        }
    }
    __syncthreads();

    // ---- local softmax per head: warp w handles heads 3w..3w+2 ----
    int w = tid >> 5, lane = tid & 31;
    #pragma unroll
    for (int hr = 0; hr < 3; hr++) {
        int h = w * 3 + hr;
        float l0 = lS[h * 64 + lane], l1 = lS[h * 64 + 32 + lane];
        float m = fmaxf(l0, l1);
        #pragma unroll
        for (int off = 16; off; off >>= 1) m = fmaxf(m, __shfl_xor_sync(0xffffffffu, m, off));
        float e0 = __expf(l0 - m), e1 = __expf(l1 - m);
        float s = e0 + e1;
        #pragma unroll
        for (int off = 16; off; off >>= 1) s += __shfl_xor_sync(0xffffffffu, s, off);
        lS[h * 64 + lane] = e0;
        lS[h * 64 + 32 + lane] = e1;
        size_t gb = ((size_t)i * Hh + h) * Nn + j0;
        g_logits[gb + lane] = e0;
        g_logits[gb + 32 + lane] = e1;
        if (lane == 0) {
            int msb = (((i * Hh) + h) * 8 + js) * 2;
            g_ms[msb] = m;
            g_ms[msb + 1] = s;
        }
    }
    __syncthreads();

    // ---- o_pair partial: thread = (ht: 3 heads) x (zq2: 4 z) over 64 j ----
    int ht = tid >> 5, zq2 = tid & 31;
    float a3[3][4];
    #pragma unroll
    for (int b = 0; b < 3; b++)
        #pragma unroll
        for (int a = 0; a < 4; a++) a3[b][a] = 0.f;
    const float* E0 = &lS[(ht * 3 + 0) * 64];
    const float* E1 = &lS[(ht * 3 + 1) * 64];
    const float* E2 = &lS[(ht * 3 + 2) * 64];
    #pragma unroll 4
    for (int j = 0; j < 64; j++) {
        float4 p = *(const float4*)&pairS[j * 132 + zq2 * 4];
        float v0 = E0[j], v1 = E1[j], v2 = E2[j];
        a3[0][0] += v0 * p.x; a3[0][1] += v0 * p.y; a3[0][2] += v0 * p.z; a3[0][3] += v0 * p.w;
        a3[1][0] += v1 * p.x; a3[1][1] += v1 * p.y; a3[1][2] += v1 * p.z; a3[1][3] += v1 * p.w;
        a3[2][0] += v2 * p.x; a3[2][1] += v2 * p.y; a3[2][2] += v2 * p.z; a3[2][3] += v2 * p.w;
    }
    float* dst = &g_opP[((size_t)js * Nn + i) * (Hh * CZd)];
    #pragma unroll
    for (int b = 0; b < 3; b++)
        *(float4*)&dst[(ht * 3 + b) * CZd + zq2 * 4] =
            make_float4(a3[b][0], a3[b][1], a3[b][2], a3[b][3]);
}

// ---------------- combine: global softmax stats + o_pair ----------------
__global__ void combine_k() {
    __shared__ float fctS[96];
    int i = blockIdx.x, tid = threadIdx.x;
    if (tid < 96) {
        int h = tid >> 3, js = tid & 7;
        float mv[8], sv[8];
        float mg = -1e30f;
        #pragma unroll
        for (int k = 0; k < 8; k++) {
            int b = ((i * Hh + h) * 8 + k) * 2;
            mv[k] = g_ms[b]; sv[k] = g_ms[b + 1];
            mg = fmaxf(mg, mv[k]);
        }
        float sg = 0.f;
        #pragma unroll
        for (int k = 0; k < 8; k++) sg += sv[k] * __expf(mv[k] - mg);
        float f = __expf(mv[js] - mg) / sg;
        fctS[tid] = f;
        g_fct[i * 96 + tid] = f;
    }
    __syncthreads();
    const size_t S = (size_t)Nn * Hh * CZd;
    for (int c = tid; c < Hh * CZd; c += 256) {
        int h = c >> 7;
        float s = 0.f;
        #pragma unroll
        for (int js = 0; js < 8; js++)
            s += fctS[h * 8 + js] * g_opP[js * S + (size_t)i * (Hh * CZd) + c];
        g_concat[(size_t)i * OUTD + 576 + c] = s;
    }
}

// ---------------- normalize: e -> attention ----------------
__global__ void normalize_k() {
    __shared__ float fctS[96];
    int i = blockIdx.x, tid = threadIdx.x;
    if (tid < 96) fctS[tid] = g_fct[i * 96 + tid];
    __syncthreads();
    for (int t = tid; t < Hh * 128; t += 256) {
        int h = t >> 7, q = t & 127;
        int js = q >> 4;
        size_t idx = ((size_t)i * Hh + h) * Nn + q * 4;
        float4 e = *(const float4*)&g_logits[idx];
        float f = fctS[h * 8 + js];
        e.x *= f; e.y *= f; e.z *= f; e.w *= f;
        *(float4*)&g_logits[idx] = e;
    }
}

// ---------------- o_v & o_pt: packed B2, double-buffered ----------------
__global__ void ov_k() {
    __shared__ float As[2][64 * 36];
    __shared__ float Bs[2][32 * 48];
    int i0 = blockIdx.x * 64, h = blockIdx.y;
    int tid = threadIdx.x;
    int tr = tid / 16, tc = tid % 16;
    float acc[4][3];
    #pragma unroll
    for (int a = 0; a < 4; a++)
        #pragma unroll
        for (int b = 0; b < 3; b++) acc[a][b] = 0.f;

    auto loadA = [&](int chunk, int buf) {
        int j0 = chunk * 32;
        for (int t = tid; t < 512; t += 256) {
            int row = t >> 3, q = t & 7;
            cp16(&As[buf][row * 36 + q * 4],
                 &g_logits[((size_t)(i0 + row) * Hh + h) * Nn + j0 + q * 4]);
        }
    };
    auto loadB = [&](int chunk, int buf) {
        int j0 = chunk * 32;
        for (int t = tid; t < 384; t += 256) {
            int row = t / 12, q = t % 12;
            cp16(&Bs[buf][row * 48 + q * 4], &g_B2[(size_t)(j0 + row) * 576 + h * 48 + q * 4]);
        }
    };
    loadA(0, 0); loadB(0, 0); cp_commit();
    for (int chunk = 0; chunk < 16; chunk++) {
        int buf = chunk & 1;
        if (chunk + 1 < 16) {
            loadA(chunk + 1, buf ^ 1); loadB(chunk + 1, buf ^ 1); cp_commit();
            cp_wait<1>();
        } else cp_wait<0>();
        __syncthreads();
        #pragma unroll 8
        for (int jl = 0; jl < 32; jl++) {
            float ra[4], rb[3];
            #pragma unroll
            for (int a = 0; a < 4; a++) ra[a] = As[buf][(tr * 4 + a) * 36 + jl];
            #pragma unroll
            for (int b = 0; b < 3; b++) rb[b] = Bs[buf][jl * 48 + tc * 3 + b];
            #pragma unroll
            for (int a = 0; a < 4; a++)
                #pragma unroll
                for (int b = 0; b < 3; b++) acc[a][b] += ra[a] * rb[b];
        }
        __syncthreads();
    }
    #pragma unroll
    for (int a = 0; a < 4; a++) {
        int i = i0 + tr * 4 + a;
        #pragma unroll
        for (int b = 0; b < 3; b++) {
            int c = tc * 3 + b;
            if (c < 16)      g_concat[(size_t)i * OUTD + h * Cc + c] = acc[a][b];
            else if (c < 40) g_opt[i * (Hh * 24) + h * 24 + (c - 16)] = acc[a][b];
        }
    }
}

__global__ void post_pt_k(const float* __restrict__ rot, const float* __restrict__ trans) {
    int idx = blockIdx.x * blockDim.x + threadIdx.x;
    if (idx >= Nn * Hh * PVd) return;
    int i = idx / (Hh * PVd), t = idx % (Hh * PVd);
    float b0 = g_opt[i * (Hh * 24) + t * 3 + 0] - trans[i * 3 + 0];
    float b1 = g_opt[i * (Hh * 24) + t * 3 + 1] - trans[i * 3 + 1];
    float b2 = g_opt[i * (Hh * 24) + t * 3 + 2] - trans[i * 3 + 2];
    float l0 = rot[i * 9 + 0] * b0 + rot[i * 9 + 3] * b1 + rot[i * 9 + 6] * b2;
    float l1 = rot[i * 9 + 1] * b0 + rot[i * 9 + 4] * b1 + rot[i * 9 + 7] * b2;
    float l2 = rot[i * 9 + 2] * b0 + rot[i * 9 + 5] * b1 + rot[i * 9 + 8] * b2;
    float* crow = &g_concat[(size_t)i * OUTD];
    crow[192 + t * 3 + 0] = l0;
    crow[192 + t * 3 + 1] = l1;
    crow[192 + t * 3 + 2] = l2;
    crow[480 + t] = sqrtf(l0 * l0 + l1 * l1 + l2 * l2 + 1e-8f);
}

// ---------------- layer norms ----------------
__device__ __forceinline__ float blockSum384(float v, float* red) {
    int tid = threadIdx.x;
    red[tid] = v;
    if (tid < 128) red[384 + tid] = 0.f;
    __syncthreads();
    for (int s = 256; s > 0; s >>= 1) {
        if (tid < s) red[tid] += red[tid + s];
        __syncthreads();
    }
    float r = red[0];
    __syncthreads();
    return r;
}

__global__ void ln1_k(const float* __restrict__ single_in, const float* __restrict__ bo,
                      const float* __restrict__ g, const float* __restrict__ b) {
    __shared__ float red[512];
    int row = blockIdx.x, tid = threadIdx.x;
    float x = single_in[row * CSd + tid] + bo[tid];
    #pragma unroll
    for (int z = 0; z < 4; z++) x += g_wop[(size_t)z * Nn * CSd + row * CSd + tid];
    float mean = blockSum384(x, red) * (1.f / CSd);
    float dx = x - mean;
    float var = blockSum384(dx * dx, red) * (1.f / CSd);
    g_s1[row * CSd + tid] = dx * rsqrtf(var + 1e-5f) * g[tid] + b[tid];
}

__global__ void ln2_k(const float* __restrict__ g, const float* __restrict__ b,
                      float* __restrict__ out) {
    __shared__ float red[512];
    int row = blockIdx.x, tid = threadIdx.x;
    float x = g_s1[row * CSd + tid] + g_h3[row * CSd + tid];
    float mean = blockSum384(x, red) * (1.f / CSd);
    float dx = x - mean;
    float var = blockSum384(dx * dx, red) * (1.f / CSd);
    float y = dx * rsqrtf(var + 1e-5f) * g[tid] + b[tid];
    out[row * CSd + tid] = y;
    g_s2[row * CSd + tid] = y;
}

// ---------------- backbone update ----------------
__global__ void update_k(const float* __restrict__ rot, const float* __restrict__ trans,
                         const float* __restrict__ Wbu, const float* __restrict__ bbu,
                         float* __restrict__ out) {
    int gtid = blockIdx.x * blockDim.x + threadIdx.x;
    int n = gtid >> 5, lane = gtid & 31;
    if (n >= Nn) return;
    float u[6] = {0, 0, 0, 0, 0, 0};
    for (int s = lane; s < CSd; s += 32) {
        float x = g_s2[n * CSd + s];
        #pragma unroll
        for (int j = 0; j < 6; j++) u[j] += x * Wbu[s * 6 + j];
    }
    #pragma unroll
    for (int j = 0; j < 6; j++)
        #pragma unroll
        for (int off = 16; off; off >>= 1) u[j] += __shfl_xor_sync(0xffffffffu, u[j], off);
    if (lane != 0) return;
    #pragma unroll
    for (int j = 0; j < 6; j++) u[j] += bbu[j];
    float b = u[0], c = u[1], d = u[2];
    float inq = rsqrtf(1.f + b * b + c * c + d * d);
    float a = inq; b *= inq; c *= inq; d *= inq;
    float R[9] = {
        a*a + b*b - c*c - d*d, 2.f*(b*c - a*d),       2.f*(b*d + a*c),
        2.f*(b*c + a*d),       a*a - b*b + c*c - d*d, 2.f*(c*d - a*b),
        2.f*(b*d - a*c),       2.f*(c*d + a*b),       a*a - b*b - c*c + d*d };
    float rn[9];
    #pragma unroll
    for (int aa = 0; aa < 3; aa++)
        #pragma unroll
        for (int cc = 0; cc < 3; cc++) {
            float s2 = 0.f;
            #pragma unroll
            for (int bx = 0; bx < 3; bx++) s2 += rot[n * 9 + aa * 3 + bx] * R[bx * 3 + cc];
            rn[aa * 3 + cc] = s2;
        }
    float t0 = u[3], t1 = u[4], t2 = u[5];
    float tn[3];
    #pragma unroll
    for (int aa = 0; aa < 3; aa++)
        tn[aa] = rot[n * 9 + aa * 3 + 0] * t0 + rot[n * 9 + aa * 3 + 1] * t1 +
                 rot[n * 9 + aa * 3 + 2] * t2 + trans[n * 3 + aa];
    #pragma unroll
    for (int e = 0; e < 9; e++) { g_rotn[n * 9 + e] = rn[e]; out[Nn * CSd + n * 9 + e] = rn[e]; }
    #pragma unroll
    for (int e = 0; e < 3; e++) { g_trn[n * 3 + e] = tn[e]; out[Nn * CSd + Nn * 9 + n * 3 + e] = tn[e]; }
}

// ---------------- loss ----------------
__global__ void loss_part_k(const float* __restrict__ rt, const float* __restrict__ tt) {
    int i = blockIdx.x, tid = threadIdx.x;
    __shared__ float red[256];
    float rn[9], rte[9], tni[3], tti[3];
    #pragma unroll
    for (int e = 0; e < 9; e++) { rn[e] = g_rotn[i * 9 + e]; rte[e] = rt[i * 9 + e]; }
    #pragma unroll
    for (int e = 0; e < 3; e++) { tni[e] = g_trn[i * 3 + e]; tti[e] = tt[i * 3 + e]; }
    float s = 0.f;
    for (int j = tid; j < Nn; j += 256) {
        float db0 = g_trn[j * 3 + 0] - tni[0];
        float db1 = g_trn[j * 3 + 1] - tni[1];
        float db2 = g_trn[j * 3 + 2] - tni[2];
        float dp0 = rn[0] * db0 + rn[3] * db1 + rn[6] * db2;
        float dp1 = rn[1] * db0 + rn[4] * db1 + rn[7] * db2;
        float dp2 = rn[2] * db0 + rn[5] * db1 + rn[8] * db2;
        float eb0 = tt[j * 3 + 0] - tti[0];
        float eb1 = tt[j * 3 + 1] - tti[1];
        float eb2 = tt[j * 3 + 2] - tti[2];
        float dt0 = rte[0] * eb0 + rte[3] * eb1 + rte[6] * eb2;
        float dt1 = rte[1] * eb0 + rte[4] * eb1 + rte[7] * eb2;
        float dt2 = rte[2] * eb0 + rte[5] * eb1 + rte[8] * eb2;
        float d0 = dp0 - dt0, d1 = dp1 - dt1, d2 = dp2 - dt2;
        float dd = sqrtf(d0 * d0 + d1 * d1 + d2 * d2 + 1e-12f);
        s += fminf(dd, 10.f);
    }
    red[tid] = s; __syncthreads();
    for (int st = 128; st > 0; st >>= 1) {
        if (tid < st) red[tid] += red[tid + st];
        __syncthreads();
    }
    if (tid == 0) g_partial[i] = red[0];
}

__global__ void loss_final_k(float* __restrict__ out) {
    __shared__ float red[512];
    int tid = threadIdx.x;
    red[tid] = g_partial[tid];
    __syncthreads();
    for (int s = 256; s > 0; s >>= 1) {
        if (tid < s) red[tid] += red[tid + s];
        __syncthreads();
    }
    if (tid == 0)
        out[Nn * CSd + Nn * 9 + Nn * 3] = red[0] / ((float)Nn * (float)Nn) * 0.1f;
}

// ---------------- host ----------------
template <typename T>
static float* symaddr(T& sym) {
    void* p = nullptr;
    cudaGetSymbolAddress(&p, sym);
    return (float*)p;
}

extern "C" void kernel_launch(void* const* d_in, const int* in_sizes, int n_in,
                              void* d_out, int out_size) {
    const float* single      = (const float*)d_in[0];
    const float* pair        = (const float*)d_in[1];
    const float* rot         = (const float*)d_in[2];
    const float* trans       = (const float*)d_in[3];
    const float* rot_truth   = (const float*)d_in[4];
    const float* trans_truth = (const float*)d_in[5];
    const float* Wq  = (const float*)d_in[6];
    const float* Wk  = (const float*)d_in[7];
    const float* Wv  = (const float*)d_in[8];
    const float* Wqp = (const float*)d_in[9];
    const float* Wkp = (const float*)d_in[10];
    const float* Wvp = (const float*)d_in[11];
    const float* Wb  = (const float*)d_in[12];
    const float* Wo  = (const float*)d_in[13];
    const float* bo  = (const float*)d_in[14];
    const float* gamma_raw = (const float*)d_in[15];
    const float* ln1_g = (const float*)d_in[16];
    const float* ln1_b = (const float*)d_in[17];
    const float* ln2_g = (const float*)d_in[18];
    const float* ln2_b = (const float*)d_in[19];
    const float* W1 = (const float*)d_in[20];
    const float* b1 = (const float*)d_in[21];
    const float* W2 = (const float*)d_in[22];
    const float* b2 = (const float*)d_in[23];
    const float* W3 = (const float*)d_in[24];
    const float* b3 = (const float*)d_in[25];
    const float* Wbu = (const float*)d_in[26];
    const float* bbu = (const float*)d_in[27];
    float* out = (float*)d_out;

    float* pWf     = symaddr(g_Wf);
    float* pProj   = symaddr(g_proj);
    float* pConcat = symaddr(g_concat);
    float* pS1     = symaddr(g_s1);
    float* pH1     = symaddr(g_h1);
    float* pH2     = symaddr(g_h2);
    float* pH3     = symaddr(g_h3);

    const int FLASH2_SMEM = (8448 + 1584 + 768 + 2304) * 4;   // 52416
    cudaFuncSetAttribute(flash2_k, cudaFuncAttributeMaxDynamicSharedMemorySize, FLASH2_SMEM);

    fuse_w_k<<<(CSd * PROJD + 255) / 256, 256>>>(Wq, Wk, Wv, Wqp, Wkp, Wvp);

    sgemm_k<64,64,16,4,4,false,false,false><<<dim3(PROJD/64, Nn/64, 1), 256>>>(
        single, pWf, nullptr, pProj, Nn, PROJD, CSd, CSd);

    prep_k<<<Nn, 128>>>(rot, trans, gamma_raw);
    core_k<<<dim3(Nn/64, Nn/64, Hh), 256>>>();

    flash2_k<<<dim3(Nn, 8), 128, FLASH2_SMEM>>>(pair, Wb);
    combine_k<<<Nn, 256>>>();
    normalize_k<<<Nn, 256>>>();
    ov_k<<<dim3(Nn/64, Hh), 256>>>();
    post_pt_k<<<(Nn * Hh * PVd + 255) / 256, 256>>>(rot, trans);

    sgemm_k<128,64,16,8,4,false,false,true><<<dim3(CSd/64, Nn/128, 4), 256>>>(
        pConcat, Wo, nullptr, symaddr(g_wop), Nn, CSd, OUTD, OUTD/4);
    ln1_k<<<Nn, CSd>>>(single, bo, ln1_g, ln1_b);

    sgemm_k<64,64,16,4,4,true,true,false><<<dim3(CSd/64, Nn/64, 1), 256>>>(
        pS1, W1, b1, pH1, Nn, CSd, CSd, CSd);
    sgemm_k<64,64,16,4,4,true,true,false><<<dim3(CSd/64, Nn/64, 1), 256>>>(
        pH1, W2, b2, pH2, Nn, CSd, CSd, CSd);
    sgemm_k<64,64,16,4,4,true,false,false><<<dim3(CSd/64, Nn/64, 1), 256>>>(
        pH2, W3, b3, pH3, Nn, CSd, CSd, CSd);
    ln2_k<<<Nn, CSd>>>(ln2_g, ln2_b, out);

    update_k<<<(Nn * 32 + 127) / 128, 128>>>(rot, trans, Wbu, bbu, out);
    loss_part_k<<<Nn, 256>>>(rot_truth, trans_truth);
    loss_final_k<<<1, 512>>>(out);
}

// round 9
// speedup vs baseline: 3.8699x; 1.1129x over previous
#include <cuda_runtime.h>
#include <math.h>

#define Nn 512
#define CSd 384
#define CZd 128
#define Hh 12
#define Cc 16
#define PQd 4
#define PVd 8
#define OUTD 2112
#define PROJD 1152
#define OQ 0
#define OK0 192
#define OV 384
#define OQP 576
#define OKP 720
#define OVP 864

__device__ float g_proj[Nn * PROJD];
__device__ float g_gv[Nn * Hh * PVd * 3];
__device__ float g_B2[Nn * Hh * 48];
__device__ float g_E[Hh * Nn * 32], g_F[Hh * Nn * 32];
__device__ float g_logits[Nn * Hh * Nn];
__device__ float g_opP[8 * Nn * Hh * CZd];
__device__ float g_ms[Nn * Hh * 8 * 2];
__device__ float g_concat[Nn * OUTD];
__device__ float g_opt[Nn * Hh * PVd * 3];
__device__ float g_wop[4 * Nn * CSd];
__device__ float g_s1[Nn * CSd], g_h1[Nn * CSd], g_h2[Nn * CSd], g_h3[Nn * CSd], g_s2[Nn * CSd];
__device__ float g_rotn[Nn * 9], g_trn[Nn * 3];
__device__ float g_partial[Nn];

#define WLc 0.5773502691896258f
#define WCc 0.23570226039551584f

__device__ __forceinline__ void cp16(void* smem_dst, const void* gmem_src) {
    unsigned s = (unsigned)__cvta_generic_to_shared(smem_dst);
    asm volatile("cp.async.cg.shared.global [%0], [%1], 16;" :: "r"(s), "l"(gmem_src));
}
__device__ __forceinline__ void cp_commit() { asm volatile("cp.async.commit_group;"); }
template<int N> __device__ __forceinline__ void cp_wait() {
    asm volatile("cp.async.wait_group %0;" :: "n"(N));
}

// ---------------- generic double-buffered tiled SGEMM ----------------
template<int BM, int BN, int BK, int TM, int TN, bool BIAS, bool RELU, bool SPLITK>
__global__ void sgemm_k(const float* __restrict__ A, const float* __restrict__ B,
                        const float* __restrict__ bias, float* __restrict__ C,
                        int M, int N, int K, int KC) {
    const int THREADS = (BM / TM) * (BN / TN);
    __shared__ float As[2][BK][BM];
    __shared__ float Bs[2][BK][BN + 4];
    int n0 = blockIdx.x * BN, m0 = blockIdx.y * BM;
    int kstart = SPLITK ? blockIdx.z * KC : 0;
    if (SPLITK) C += (size_t)blockIdx.z * M * N;
    int tid = threadIdx.x;
    int tr = tid / (BN / TN), tc = tid % (BN / TN);
    float acc[TM][TN];
    #pragma unroll
    for (int i = 0; i < TM; i++)
        #pragma unroll
        for (int j = 0; j < TN; j++) acc[i][j] = 0.f;
    int nsteps = KC / BK;

    auto loadA = [&](int kt, int buf) {
        #pragma unroll
        for (int r = tid; r < BM * BK / 4; r += THREADS) {
            int arow = r / (BK / 4), aq = r % (BK / 4);
            float4 v = *(const float4*)&A[(size_t)(m0 + arow) * K + kstart + kt * BK + aq * 4];
            As[buf][aq * 4 + 0][arow] = v.x; As[buf][aq * 4 + 1][arow] = v.y;
            As[buf][aq * 4 + 2][arow] = v.z; As[buf][aq * 4 + 3][arow] = v.w;
        }
    };
    auto loadB = [&](int kt, int buf) {
        #pragma unroll
        for (int r = tid; r < BK * BN / 4; r += THREADS) {
            int brow = r / (BN / 4), bq = r % (BN / 4);
            cp16(&Bs[buf][brow][bq * 4], &B[(size_t)(kstart + kt * BK + brow) * N + n0 + bq * 4]);
        }
    };
    loadA(0, 0); loadB(0, 0); cp_commit();
    for (int kt = 0; kt < nsteps; kt++) {
        int buf = kt & 1;
        if (kt + 1 < nsteps) {
            loadA(kt + 1, buf ^ 1); loadB(kt + 1, buf ^ 1); cp_commit();
            cp_wait<1>();
        } else cp_wait<0>();
        __syncthreads();
        #pragma unroll
        for (int k = 0; k < BK; k++) {
            float ra[TM], rb[TN];
            if constexpr (TM % 4 == 0) {
                #pragma unroll
                for (int i = 0; i < TM; i += 4)
                    *(float4*)&ra[i] = *(const float4*)&As[buf][k][tr * TM + i];
            } else {
                #pragma unroll
                for (int i = 0; i < TM; i++) ra[i] = As[buf][k][tr * TM + i];
            }
            #pragma unroll
            for (int j = 0; j < TN; j += 4)
                *(float4*)&rb[j] = *(const float4*)&Bs[buf][k][tc * TN + j];
            #pragma unroll
            for (int i = 0; i < TM; i++)
                #pragma unroll
                for (int j = 0; j < TN; j++) acc[i][j] += ra[i] * rb[j];
        }
        __syncthreads();
    }
    #pragma unroll
    for (int i = 0; i < TM; i++) {
        int m = m0 + tr * TM + i;
        #pragma unroll
        for (int j = 0; j < TN; j++) {
            int n = n0 + tc * TN + j;
            float v = acc[i][j];
            if (BIAS) v += bias[n];
            if (RELU) v = fmaxf(v, 0.f);
            C[(size_t)m * N + n] = v;
        }
    }
}

// ---------------- projection GEMM with fused 6-way weight gather ----------------
__device__ __forceinline__ const float* wf_ptr(
    const float* Wq, const float* Wk, const float* Wv,
    const float* Wqp, const float* Wkp, const float* Wvp, int kk, int n) {
    if (n < 192) return Wq  + kk * 192 + n;
    if (n < 384) return Wk  + kk * 192 + (n - 192);
    if (n < 576) return Wv  + kk * 192 + (n - 384);
    if (n < 720) return Wqp + kk * 144 + (n - 576);
    if (n < 864) return Wkp + kk * 144 + (n - 720);
    return Wvp + kk * 288 + (n - 864);
}

__global__ void proj_gemm_k(const float* __restrict__ A,
                            const float* __restrict__ Wq, const float* __restrict__ Wk,
                            const float* __restrict__ Wv, const float* __restrict__ Wqp,
                            const float* __restrict__ Wkp, const float* __restrict__ Wvp,
                            float* __restrict__ C) {
    const int BM = 64, BN = 64, BK = 16, TM = 4, TN = 4;
    __shared__ float As[2][BK][BM];
    __shared__ float Bs[2][BK][BN + 4];
    int n0 = blockIdx.x * BN, m0 = blockIdx.y * BM;
    int tid = threadIdx.x;
    int tr = tid / 16, tc = tid % 16;
    float acc[TM][TN];
    #pragma unroll
    for (int i = 0; i < TM; i++)
        #pragma unroll
        for (int j = 0; j < TN; j++) acc[i][j] = 0.f;
    auto loadA = [&](int kt, int buf) {
        for (int r = tid; r < BM * BK / 4; r += 256) {
            int arow = r / 4, aq = r % 4;
            float4 v = *(const float4*)&A[(size_t)(m0 + arow) * CSd + kt * BK + aq * 4];
            As[buf][aq * 4 + 0][arow] = v.x; As[buf][aq * 4 + 1][arow] = v.y;
            As[buf][aq * 4 + 2][arow] = v.z; As[buf][aq * 4 + 3][arow] = v.w;
        }
    };
    auto loadB = [&](int kt, int buf) {
        for (int r = tid; r < BK * BN / 4; r += 256) {
            int brow = r / 16, bq = r % 16;
            cp16(&Bs[buf][brow][bq * 4],
                 wf_ptr(Wq, Wk, Wv, Wqp, Wkp, Wvp, kt * BK + brow, n0 + bq * 4));
        }
    };
    loadA(0, 0); loadB(0, 0); cp_commit();
    const int nsteps = CSd / BK;
    for (int kt = 0; kt < nsteps; kt++) {
        int buf = kt & 1;
        if (kt + 1 < nsteps) {
            loadA(kt + 1, buf ^ 1); loadB(kt + 1, buf ^ 1); cp_commit();
            cp_wait<1>();
        } else cp_wait<0>();
        __syncthreads();
        #pragma unroll
        for (int k = 0; k < BK; k++) {
            float ra[4], rb[4];
            *(float4*)ra = *(const float4*)&As[buf][k][tr * 4];
            *(float4*)rb = *(const float4*)&Bs[buf][k][tc * 4];
            #pragma unroll
            for (int i = 0; i < 4; i++)
                #pragma unroll
                for (int j = 0; j < 4; j++) acc[i][j] += ra[i] * rb[j];
        }
        __syncthreads();
    }
    #pragma unroll
    for (int i = 0; i < 4; i++)
        #pragma unroll
        for (int j = 0; j < 4; j++)
            C[(size_t)(m0 + tr * 4 + i) * PROJD + n0 + tc * 4 + j] = acc[i][j];
}

// ---------------- prep: frames + E/F + packed B2 ----------------
__global__ void prep_k(const float* __restrict__ rot, const float* __restrict__ trans,
                       const float* __restrict__ gamma_raw) {
    __shared__ float R[9], T[3], gqS[144], gkS[144], sqqS[12], sqkS[12], wcgS[12];
    int n = blockIdx.x, tid = threadIdx.x;
    if (tid < 9) R[tid] = rot[n * 9 + tid];
    if (tid < 3) T[tid] = trans[n * 3 + tid];
    if (tid >= 16 && tid < 28) {
        int h = tid - 16;
        float x = gamma_raw[h];
        wcgS[h] = WCc * ((x > 20.f) ? x : log1pf(expf(x)));
    }
    __syncthreads();
    const float* base = &g_proj[(size_t)n * PROJD];
    for (int t = tid; t < 96; t += 128) {
        int which = t / 48, p = t % 48;
        const float* src = base + (which ? OKP : OQP) + p * 3;
        float b0 = src[0], b1 = src[1], b2 = src[2];
        float* dst = (which ? gkS : gqS) + p * 3;
        #pragma unroll
        for (int a = 0; a < 3; a++)
            dst[a] = R[a * 3 + 0] * b0 + R[a * 3 + 1] * b1 + R[a * 3 + 2] * b2 + T[a];
    }
    for (int t = tid; t < 96; t += 128) {
        int h = t >> 3, p = t & 7;
        const float* src = base + OVP + t * 3;
        float b0 = src[0], b1 = src[1], b2 = src[2];
        #pragma unroll
        for (int a = 0; a < 3; a++) {
            float v = R[a * 3 + 0] * b0 + R[a * 3 + 1] * b1 + R[a * 3 + 2] * b2 + T[a];
            g_gv[n * 288 + t * 3 + a] = v;
            g_B2[n * 576 + h * 48 + 16 + p * 3 + a] = v;
        }
    }
    for (int t = tid; t < 192; t += 128) {
        int h = t >> 4, c = t & 15;
        g_B2[n * 576 + h * 48 + c] = base[OV + t];
    }
    for (int t = tid; t < 96; t += 128) {
        int h = t / 8, c = 40 + (t % 8);
        g_B2[n * 576 + h * 48 + c] = 0.f;
    }
    __syncthreads();
    if (tid < 24) {
        int h = tid >> 1, which = tid & 1;
        const float* g = (which ? gkS : gqS) + h * 12;
        float s = 0.f;
        #pragma unroll
        for (int e = 0; e < 12; e++) s += g[e] * g[e];
        (which ? sqkS : sqqS)[h] = s;
    }
    __syncthreads();
    for (int t = tid; t < Hh * 32; t += 128) {
        int h = t >> 5, c = t & 31;
        float wcg = wcgS[h];
        float e, f;
        if (c < 16)      { e = 0.25f * base[OQ + h * 16 + c]; f = base[OK0 + h * 16 + c]; }
        else if (c < 28) { e = wcg * gqS[h * 12 + c - 16];    f = gkS[h * 12 + c - 16]; }
        else if (c == 28){ e = sqqS[h];                        f = -0.5f * wcg; }
        else if (c == 29){ e = 1.f;                            f = -0.5f * wcg * sqkS[h]; }
        else             { e = 0.f;                            f = 0.f; }
        g_E[(size_t)((h << 9) | n) * 32 + c] = e;
        g_F[(size_t)((h << 9) | n) * 32 + c] = f;
    }
}

// ---------------- logit core: writes WL*(E.F) ----------------
__global__ void core_k() {
    __shared__ float As[32][64], BsT[32][64];
    int h = blockIdx.z, i0 = blockIdx.y * 64, j0 = blockIdx.x * 64;
    int tid = threadIdx.x;
    const float* Eh = &g_E[((size_t)h * Nn + i0) * 32];
    const float* Fh = &g_F[((size_t)h * Nn + j0) * 32];
    for (int t = tid; t < 512; t += 256) {
        int row = t >> 3, d4 = t & 7;
        float4 v = *(const float4*)&Eh[row * 32 + d4 * 4];
        As[d4 * 4 + 0][row] = v.x; As[d4 * 4 + 1][row] = v.y;
        As[d4 * 4 + 2][row] = v.z; As[d4 * 4 + 3][row] = v.w;
        float4 w = *(const float4*)&Fh[row * 32 + d4 * 4];
        BsT[d4 * 4 + 0][row] = w.x; BsT[d4 * 4 + 1][row] = w.y;
        BsT[d4 * 4 + 2][row] = w.z; BsT[d4 * 4 + 3][row] = w.w;
    }
    __syncthreads();
    int tr = tid / 16, tc = tid % 16;
    float acc[4][4];
    #pragma unroll
    for (int i = 0; i < 4; i++)
        #pragma unroll
        for (int j = 0; j < 4; j++) acc[i][j] = 0.f;
    #pragma unroll
    for (int d = 0; d < 32; d++) {
        float ra[4], rb[4];
        *(float4*)ra = *(const float4*)&As[d][tr * 4];
        *(float4*)rb = *(const float4*)&BsT[d][tc * 4];
        #pragma unroll
        for (int i = 0; i < 4; i++)
            #pragma unroll
            for (int j = 0; j < 4; j++) acc[i][j] += ra[i] * rb[j];
    }
    #pragma unroll
    for (int i = 0; i < 4; i++)
        #pragma unroll
        for (int j = 0; j < 4; j++) {
            size_t idx = ((size_t)(i0 + tr * 4 + i) * Hh + h) * Nn + j0 + tc * 4 + j;
            g_logits[idx] = WLc * acc[i][j];
        }
}

// ---------------- FLASH2 (256 threads): bias + local softmax + o_pair, ONE pair pass ----
// grid (Nn, 8). smem: pairS[64*132] WbT[12*132] lS[12*64] comb[3*64*12]
__global__ void __launch_bounds__(256) flash2_k(const float* __restrict__ pair,
                                                const float* __restrict__ Wb) {
    extern __shared__ float sm[];
    float* pairS = sm;                  // 8448
    float* WbT   = pairS + 8448;        // 1584
    float* lS    = WbT + 1584;          // 768
    float* comb  = lS + 768;            // 2304
    int i = blockIdx.x, js = blockIdx.y, j0 = js << 6;
    int tid = threadIdx.x;

    for (int r = tid; r < 64 * 32; r += 256) {
        int row = r >> 5, q = r & 31;
        cp16(&pairS[row * 132 + q * 4], &pair[((size_t)i * Nn + j0 + row) * CZd + q * 4]);
    }
    cp_commit();
    for (int t = tid; t < CZd * Hh; t += 256) WbT[(t % Hh) * 132 + (t / Hh)] = Wb[t];
    if (tid < 192) {
        int h = tid >> 4, q = tid & 15;
        *(float4*)&lS[h * 64 + q * 4] =
            *(const float4*)&g_logits[((size_t)i * Hh + h) * Nn + j0 + q * 4];
    }

    int zq = tid >> 6;      // 0..3 (32 z each, warp-pair-uniform)
    int jq = tid & 63;      // 1 j per thread
    float acc[12];
    #pragma unroll
    for (int h = 0; h < 12; h++) acc[h] = 0.f;

    cp_wait<0>();
    __syncthreads();
    {
        const float4* ap = (const float4*)&pairS[jq * 132 + zq * 32];
        #pragma unroll
        for (int z4 = 0; z4 < 8; z4++) {
            float4 p = ap[z4];
            #pragma unroll
            for (int h = 0; h < 12; h++) {
                float4 w = *(const float4*)&WbT[h * 132 + zq * 32 + z4 * 4];
                acc[h] += p.x * w.x + p.y * w.y + p.z * w.z + p.w * w.w;
            }
        }
    }
    if (zq > 0) {
        float* c = &comb[((zq - 1) * 64 + jq) * 12];
        #pragma unroll
        for (int h = 0; h < 12; h++) c[h] = acc[h];
    }
    __syncthreads();
    if (zq == 0) {
        #pragma unroll
        for (int h = 0; h < 12; h++) {
            float s0 = acc[h];
            #pragma unroll
            for (int g = 0; g < 3; g++) s0 += comb[(g * 64 + jq) * 12 + h];
            lS[h * 64 + jq] += WLc * s0;
        }
    }
    __syncthreads();

    // local softmax: warp w -> head w; warps 0..3 also head 8+w
    int w = tid >> 5, lane = tid & 31;
    #pragma unroll
    for (int rep = 0; rep < 2; rep++) {
        int h = w + rep * 8;
        if (h < Hh) {
            float l0 = lS[h * 64 + lane], l1 = lS[h * 64 + 32 + lane];
            float m = fmaxf(l0, l1);
            #pragma unroll
            for (int off = 16; off; off >>= 1) m = fmaxf(m, __shfl_xor_sync(0xffffffffu, m, off));
            float e0 = __expf(l0 - m), e1 = __expf(l1 - m);
            float s = e0 + e1;
            #pragma unroll
            for (int off = 16; off; off >>= 1) s += __shfl_xor_sync(0xffffffffu, s, off);
            lS[h * 64 + lane] = e0;
            lS[h * 64 + 32 + lane] = e1;
            size_t gb = ((size_t)i * Hh + h) * Nn + j0;
            g_logits[gb + lane] = e0;
            g_logits[gb + 32 + lane] = e1;
            if (lane == 0) {
                int msb = (((i * Hh) + h) * 8 + js) * 2;
                g_ms[msb] = m;
                g_ms[msb + 1] = s;
            }
        }
    }
    __syncthreads();

    // o_pair partial: thread = (ht: 3 heads) x (zz: 2 z) over 64 j
    int ht = tid >> 6, zz = tid & 63;
    float a00 = 0.f, a01 = 0.f, a10 = 0.f, a11 = 0.f, a20 = 0.f, a21 = 0.f;
    const float* E0 = &lS[(ht * 3 + 0) * 64];
    const float* E1 = &lS[(ht * 3 + 1) * 64];
    const float* E2 = &lS[(ht * 3 + 2) * 64];
    #pragma unroll 8
    for (int j = 0; j < 64; j++) {
        float2 p = *(const float2*)&pairS[j * 132 + zz * 2];
        float v0 = E0[j], v1 = E1[j], v2 = E2[j];
        a00 += v0 * p.x; a01 += v0 * p.y;
        a10 += v1 * p.x; a11 += v1 * p.y;
        a20 += v2 * p.x; a21 += v2 * p.y;
    }
    float* dst = &g_opP[((size_t)js * Nn + i) * (Hh * CZd)];
    *(float2*)&dst[(ht * 3 + 0) * CZd + zz * 2] = make_float2(a00, a01);
    *(float2*)&dst[(ht * 3 + 1) * CZd + zz * 2] = make_float2(a10, a11);
    *(float2*)&dst[(ht * 3 + 2) * CZd + zz * 2] = make_float2(a20, a21);
}

// ---------------- combine: global stats + o_pair + normalize attention ----------------
__global__ void combine_k() {
    __shared__ float fctS[96];
    int i = blockIdx.x, tid = threadIdx.x;
    if (tid < 96) {
        int h = tid >> 3, js = tid & 7;
        float mv[8], sv[8];
        float mg = -1e30f;
        #pragma unroll
        for (int k = 0; k < 8; k++) {
            int b = ((i * Hh + h) * 8 + k) * 2;
            mv[k] = g_ms[b]; sv[k] = g_ms[b + 1];
            mg = fmaxf(mg, mv[k]);
        }
        float sg = 0.f;
        #pragma unroll
        for (int k = 0; k < 8; k++) sg += sv[k] * __expf(mv[k] - mg);
        fctS[tid] = __expf(mv[js] - mg) / sg;
    }
    __syncthreads();
    const size_t S = (size_t)Nn * Hh * CZd;
    for (int c = tid; c < Hh * CZd; c += 256) {
        int h = c >> 7;
        float s = 0.f;
        #pragma unroll
        for (int js = 0; js < 8; js++)
            s += fctS[h * 8 + js] * g_opP[js * S + (size_t)i * (Hh * CZd) + c];
        g_concat[(size_t)i * OUTD + 576 + c] = s;
    }
    // normalize attention in place
    for (int t = tid; t < Hh * 128; t += 256) {
        int h = t >> 7, q = t & 127;
        int js = q >> 4;
        size_t idx = ((size_t)i * Hh + h) * Nn + q * 4;
        float4 e = *(const float4*)&g_logits[idx];
        float f = fctS[h * 8 + js];
        e.x *= f; e.y *= f; e.z *= f; e.w *= f;
        *(float4*)&g_logits[idx] = e;
    }
}

// ---------------- o_v & o_pt: 32-row tiles, packed B2, double-buffered ----------------
__global__ void ov_k() {
    __shared__ float As[2][32 * 36];
    __shared__ float Bs[2][32 * 48];
    int i0 = blockIdx.x * 32, h = blockIdx.y;
    int tid = threadIdx.x;
    int tr = tid / 16, tc = tid % 16;
    float acc[2][3];
    #pragma unroll
    for (int a = 0; a < 2; a++)
        #pragma unroll
        for (int b = 0; b < 3; b++) acc[a][b] = 0.f;

    auto loadA = [&](int chunk, int buf) {
        int j0 = chunk * 32;
        int row = tid >> 3, q = tid & 7;
        cp16(&As[buf][row * 36 + q * 4],
             &g_logits[((size_t)(i0 + row) * Hh + h) * Nn + j0 + q * 4]);
    };
    auto loadB = [&](int chunk, int buf) {
        int j0 = chunk * 32;
        for (int t = tid; t < 384; t += 256) {
            int row = t / 12, q = t % 12;
            cp16(&Bs[buf][row * 48 + q * 4], &g_B2[(size_t)(j0 + row) * 576 + h * 48 + q * 4]);
        }
    };
    loadA(0, 0); loadB(0, 0); cp_commit();
    for (int chunk = 0; chunk < 16; chunk++) {
        int buf = chunk & 1;
        if (chunk + 1 < 16) {
            loadA(chunk + 1, buf ^ 1); loadB(chunk + 1, buf ^ 1); cp_commit();
            cp_wait<1>();
        } else cp_wait<0>();
        __syncthreads();
        #pragma unroll 8
        for (int jl = 0; jl < 32; jl++) {
            float ra[2], rb[3];
            #pragma unroll
            for (int a = 0; a < 2; a++) ra[a] = As[buf][(tr * 2 + a) * 36 + jl];
            #pragma unroll
            for (int b = 0; b < 3; b++) rb[b] = Bs[buf][jl * 48 + tc * 3 + b];
            #pragma unroll
            for (int a = 0; a < 2; a++)
                #pragma unroll
                for (int b = 0; b < 3; b++) acc[a][b] += ra[a] * rb[b];
        }
        __syncthreads();
    }
    #pragma unroll
    for (int a = 0; a < 2; a++) {
        int i = i0 + tr * 2 + a;
        #pragma unroll
        for (int b = 0; b < 3; b++) {
            int c = tc * 3 + b;
            if (c < 16)      g_concat[(size_t)i * OUTD + h * Cc + c] = acc[a][b];
            else if (c < 40) g_opt[i * (Hh * 24) + h * 24 + (c - 16)] = acc[a][b];
        }
    }
}

__global__ void post_pt_k(const float* __restrict__ rot, const float* __restrict__ trans) {
    int idx = blockIdx.x * blockDim.x + threadIdx.x;
    if (idx >= Nn * Hh * PVd) return;
    int i = idx / (Hh * PVd), t = idx % (Hh * PVd);
    float b0 = g_opt[i * (Hh * 24) + t * 3 + 0] - trans[i * 3 + 0];
    float b1 = g_opt[i * (Hh * 24) + t * 3 + 1] - trans[i * 3 + 1];
    float b2 = g_opt[i * (Hh * 24) + t * 3 + 2] - trans[i * 3 + 2];
    float l0 = rot[i * 9 + 0] * b0 + rot[i * 9 + 3] * b1 + rot[i * 9 + 6] * b2;
    float l1 = rot[i * 9 + 1] * b0 + rot[i * 9 + 4] * b1 + rot[i * 9 + 7] * b2;
    float l2 = rot[i * 9 + 2] * b0 + rot[i * 9 + 5] * b1 + rot[i * 9 + 8] * b2;
    float* crow = &g_concat[(size_t)i * OUTD];
    crow[192 + t * 3 + 0] = l0;
    crow[192 + t * 3 + 1] = l1;
    crow[192 + t * 3 + 2] = l2;
    crow[480 + t] = sqrtf(l0 * l0 + l1 * l1 + l2 * l2 + 1e-8f);
}

// ---------------- layer norms ----------------
__device__ __forceinline__ float blockSum384(float v, float* red) {
    int tid = threadIdx.x;
    red[tid] = v;
    if (tid < 128) red[384 + tid] = 0.f;
    __syncthreads();
    for (int s = 256; s > 0; s >>= 1) {
        if (tid < s) red[tid] += red[tid + s];
        __syncthreads();
    }
    float r = red[0];
    __syncthreads();
    return r;
}

__global__ void ln1_k(const float* __restrict__ single_in, const float* __restrict__ bo,
                      const float* __restrict__ g, const float* __restrict__ b) {
    __shared__ float red[512];
    int row = blockIdx.x, tid = threadIdx.x;
    float x = single_in[row * CSd + tid] + bo[tid];
    #pragma unroll
    for (int z = 0; z < 4; z++) x += g_wop[(size_t)z * Nn * CSd + row * CSd + tid];
    float mean = blockSum384(x, red) * (1.f / CSd);
    float dx = x - mean;
    float var = blockSum384(dx * dx, red) * (1.f / CSd);
    g_s1[row * CSd + tid] = dx * rsqrtf(var + 1e-5f) * g[tid] + b[tid];
}

__global__ void ln2_k(const float* __restrict__ g, const float* __restrict__ b,
                      float* __restrict__ out) {
    __shared__ float red[512];
    int row = blockIdx.x, tid = threadIdx.x;
    float x = g_s1[row * CSd + tid] + g_h3[row * CSd + tid];
    float mean = blockSum384(x, red) * (1.f / CSd);
    float dx = x - mean;
    float var = blockSum384(dx * dx, red) * (1.f / CSd);
    float y = dx * rsqrtf(var + 1e-5f) * g[tid] + b[tid];
    out[row * CSd + tid] = y;
    g_s2[row * CSd + tid] = y;
}

// ---------------- backbone update ----------------
__global__ void update_k(const float* __restrict__ rot, const float* __restrict__ trans,
                         const float* __restrict__ Wbu, const float* __restrict__ bbu,
                         float* __restrict__ out) {
    int gtid = blockIdx.x * blockDim.x + threadIdx.x;
    int n = gtid >> 5, lane = gtid & 31;
    if (n >= Nn) return;
    float u[6] = {0, 0, 0, 0, 0, 0};
    for (int s = lane; s < CSd; s += 32) {
        float x = g_s2[n * CSd + s];
        #pragma unroll
        for (int j = 0; j < 6; j++) u[j] += x * Wbu[s * 6 + j];
    }
    #pragma unroll
    for (int j = 0; j < 6; j++)
        #pragma unroll
        for (int off = 16; off; off >>= 1) u[j] += __shfl_xor_sync(0xffffffffu, u[j], off);
    if (lane != 0) return;
    #pragma unroll
    for (int j = 0; j < 6; j++) u[j] += bbu[j];
    float b = u[0], c = u[1], d = u[2];
    float inq = rsqrtf(1.f + b * b + c * c + d * d);
    float a = inq; b *= inq; c *= inq; d *= inq;
    float R[9] = {
        a*a + b*b - c*c - d*d, 2.f*(b*c - a*d),       2.f*(b*d + a*c),
        2.f*(b*c + a*d),       a*a - b*b + c*c - d*d, 2.f*(c*d - a*b),
        2.f*(b*d - a*c),       2.f*(c*d + a*b),       a*a - b*b - c*c + d*d };
    float rn[9];
    #pragma unroll
    for (int aa = 0; aa < 3; aa++)
        #pragma unroll
        for (int cc = 0; cc < 3; cc++) {
            float s2 = 0.f;
            #pragma unroll
            for (int bx = 0; bx < 3; bx++) s2 += rot[n * 9 + aa * 3 + bx] * R[bx * 3 + cc];
            rn[aa * 3 + cc] = s2;
        }
    float t0 = u[3], t1 = u[4], t2 = u[5];
    float tn[3];
    #pragma unroll
    for (int aa = 0; aa < 3; aa++)
        tn[aa] = rot[n * 9 + aa * 3 + 0] * t0 + rot[n * 9 + aa * 3 + 1] * t1 +
                 rot[n * 9 + aa * 3 + 2] * t2 + trans[n * 3 + aa];
    #pragma unroll
    for (int e = 0; e < 9; e++) { g_rotn[n * 9 + e] = rn[e]; out[Nn * CSd + n * 9 + e] = rn[e]; }
    #pragma unroll
    for (int e = 0; e < 3; e++) { g_trn[n * 3 + e] = tn[e]; out[Nn * CSd + Nn * 9 + n * 3 + e] = tn[e]; }
}

// ---------------- loss ----------------
__global__ void loss_part_k(const float* __restrict__ rt, const float* __restrict__ tt) {
    int i = blockIdx.x, tid = threadIdx.x;
    __shared__ float red[256];
    float rn[9], rte[9], tni[3], tti[3];
    #pragma unroll
    for (int e = 0; e < 9; e++) { rn[e] = g_rotn[i * 9 + e]; rte[e] = rt[i * 9 + e]; }
    #pragma unroll
    for (int e = 0; e < 3; e++) { tni[e] = g_trn[i * 3 + e]; tti[e] = tt[i * 3 + e]; }
    float s = 0.f;
    for (int j = tid; j < Nn; j += 256) {
        float db0 = g_trn[j * 3 + 0] - tni[0];
        float db1 = g_trn[j * 3 + 1] - tni[1];
        float db2 = g_trn[j * 3 + 2] - tni[2];
        float dp0 = rn[0] * db0 + rn[3] * db1 + rn[6] * db2;
        float dp1 = rn[1] * db0 + rn[4] * db1 + rn[7] * db2;
        float dp2 = rn[2] * db0 + rn[5] * db1 + rn[8] * db2;
        float eb0 = tt[j * 3 + 0] - tti[0];
        float eb1 = tt[j * 3 + 1] - tti[1];
        float eb2 = tt[j * 3 + 2] - tti[2];
        float dt0 = rte[0] * eb0 + rte[3] * eb1 + rte[6] * eb2;
        float dt1 = rte[1] * eb0 + rte[4] * eb1 + rte[7] * eb2;
        float dt2 = rte[2] * eb0 + rte[5] * eb1 + rte[8] * eb2;
        float d0 = dp0 - dt0, d1 = dp1 - dt1, d2 = dp2 - dt2;
        float dd = sqrtf(d0 * d0 + d1 * d1 + d2 * d2 + 1e-12f);
        s += fminf(dd, 10.f);
    }
    red[tid] = s; __syncthreads();
    for (int st = 128; st > 0; st >>= 1) {
        if (tid < st) red[tid] += red[tid + st];
        __syncthreads();
    }
    if (tid == 0) g_partial[i] = red[0];
}

__global__ void loss_final_k(float* __restrict__ out) {
    __shared__ float red[512];
    int tid = threadIdx.x;
    red[tid] = g_partial[tid];
    __syncthreads();
    for (int s = 256; s > 0; s >>= 1) {
        if (tid < s) red[tid] += red[tid + s];
        __syncthreads();
    }
    if (tid == 0)
        out[Nn * CSd + Nn * 9 + Nn * 3] = red[0] / ((float)Nn * (float)Nn) * 0.1f;
}

// ---------------- host ----------------
template <typename T>
static float* symaddr(T& sym) {
    void* p = nullptr;
    cudaGetSymbolAddress(&p, sym);
    return (float*)p;
}

extern "C" void kernel_launch(void* const* d_in, const int* in_sizes, int n_in,
                              void* d_out, int out_size) {
    const float* single      = (const float*)d_in[0];
    const float* pair        = (const float*)d_in[1];
    const float* rot         = (const float*)d_in[2];
    const float* trans       = (const float*)d_in[3];
    const float* rot_truth   = (const float*)d_in[4];
    const float* trans_truth = (const float*)d_in[5];
    const float* Wq  = (const float*)d_in[6];
    const float* Wk  = (const float*)d_in[7];
    const float* Wv  = (const float*)d_in[8];
    const float* Wqp = (const float*)d_in[9];
    const float* Wkp = (const float*)d_in[10];
    const float* Wvp = (const float*)d_in[11];
    const float* Wb  = (const float*)d_in[12];
    const float* Wo  = (const float*)d_in[13];
    const float* bo  = (const float*)d_in[14];
    const float* gamma_raw = (const float*)d_in[15];
    const float* ln1_g = (const float*)d_in[16];
    const float* ln1_b = (const float*)d_in[17];
    const float* ln2_g = (const float*)d_in[18];
    const float* ln2_b = (const float*)d_in[19];
    const float* W1 = (const float*)d_in[20];
    const float* b1 = (const float*)d_in[21];
    const float* W2 = (const float*)d_in[22];
    const float* b2 = (const float*)d_in[23];
    const float* W3 = (const float*)d_in[24];
    const float* b3 = (const float*)d_in[25];
    const float* Wbu = (const float*)d_in[26];
    const float* bbu = (const float*)d_in[27];
    float* out = (float*)d_out;

    float* pProj   = symaddr(g_proj);
    float* pConcat = symaddr(g_concat);
    float* pS1     = symaddr(g_s1);
    float* pH1     = symaddr(g_h1);
    float* pH2     = symaddr(g_h2);
    float* pH3     = symaddr(g_h3);

    const int FLASH2_SMEM = (8448 + 1584 + 768 + 2304) * 4;   // 52416
    cudaFuncSetAttribute(flash2_k, cudaFuncAttributeMaxDynamicSharedMemorySize, FLASH2_SMEM);

    proj_gemm_k<<<dim3(PROJD/64, Nn/64), 256>>>(single, Wq, Wk, Wv, Wqp, Wkp, Wvp, pProj);
    prep_k<<<Nn, 128>>>(rot, trans, gamma_raw);
    core_k<<<dim3(Nn/64, Nn/64, Hh), 256>>>();

    flash2_k<<<dim3(Nn, 8), 256, FLASH2_SMEM>>>(pair, Wb);   // profiler slot 4
    combine_k<<<Nn, 256>>>();
    ov_k<<<dim3(Nn/32, Hh), 256>>>();
    post_pt_k<<<(Nn * Hh * PVd + 255) / 256, 256>>>(rot, trans);

    sgemm_k<64,64,16,4,4,false,false,true><<<dim3(CSd/64, Nn/64, 4), 256>>>(
        pConcat, Wo, nullptr, symaddr(g_wop), Nn, CSd, OUTD, OUTD/4);
    ln1_k<<<Nn, CSd>>>(single, bo, ln1_g, ln1_b);

    sgemm_k<32,64,16,2,4,true,true,false><<<dim3(CSd/64, Nn/32, 1), 256>>>(
        pS1, W1, b1, pH1, Nn, CSd, CSd, CSd);
    sgemm_k<32,64,16,2,4,true,true,false><<<dim3(CSd/64, Nn/32, 1), 256>>>(
        pH1, W2, b2, pH2, Nn, CSd, CSd, CSd);
    sgemm_k<32,64,16,2,4,true,false,false><<<dim3(CSd/64, Nn/32, 1), 256>>>(
        pH2, W3, b3, pH3, Nn, CSd, CSd, CSd);
    ln2_k<<<Nn, CSd>>>(ln2_g, ln2_b, out);

    update_k<<<(Nn * 32 + 127) / 128, 128>>>(rot, trans, Wbu, bbu, out);
    loss_part_k<<<Nn, 256>>>(rot_truth, trans_truth);
    loss_final_k<<<1, 512>>>(out);
}

// round 10
// speedup vs baseline: 4.0071x; 1.0355x over previous
#include <cuda_runtime.h>
#include <math.h>

#define Nn 512
#define CSd 384
#define CZd 128
#define Hh 12
#define Cc 16
#define PQd 4
#define PVd 8
#define OUTD 2112
#define PROJD 1152
#define OQ 0
#define OK0 192
#define OV 384
#define OQP 576
#define OKP 720
#define OVP 864

__device__ float g_proj[Nn * PROJD];
__device__ float g_gv[Nn * Hh * PVd * 3];
__device__ float g_B2[Nn * Hh * 48];
__device__ float g_E[Hh * Nn * 32], g_F[Hh * Nn * 32];
__device__ float g_logits[Nn * Hh * Nn];
__device__ float g_opP[8 * Nn * Hh * CZd];
__device__ float g_ms[Nn * Hh * 8 * 2];
__device__ float g_fct[Nn * 96];
__device__ float g_concat[Nn * OUTD];
__device__ float g_opt[Nn * Hh * PVd * 3];
__device__ float g_wop[4 * Nn * CSd];
__device__ float g_s1[Nn * CSd], g_h1[Nn * CSd], g_h2[Nn * CSd], g_h3[Nn * CSd], g_s2[Nn * CSd];
__device__ float g_rotn[Nn * 9], g_trn[Nn * 3];
__device__ float g_partial[Nn];

#define WLc 0.5773502691896258f
#define WCc 0.23570226039551584f

__device__ __forceinline__ void cp16(void* smem_dst, const void* gmem_src) {
    unsigned s = (unsigned)__cvta_generic_to_shared(smem_dst);
    asm volatile("cp.async.cg.shared.global [%0], [%1], 16;" :: "r"(s), "l"(gmem_src));
}
__device__ __forceinline__ void cp_commit() { asm volatile("cp.async.commit_group;"); }
template<int N> __device__ __forceinline__ void cp_wait() {
    asm volatile("cp.async.wait_group %0;" :: "n"(N));
}

// ---------------- generic double-buffered tiled SGEMM ----------------
template<int BM, int BN, int BK, int TM, int TN, bool BIAS, bool RELU, bool SPLITK>
__global__ void sgemm_k(const float* __restrict__ A, const float* __restrict__ B,
                        const float* __restrict__ bias, float* __restrict__ C,
                        int M, int N, int K, int KC) {
    const int THREADS = (BM / TM) * (BN / TN);
    __shared__ float As[2][BK][BM];
    __shared__ float Bs[2][BK][BN + 4];
    int n0 = blockIdx.x * BN, m0 = blockIdx.y * BM;
    int kstart = SPLITK ? blockIdx.z * KC : 0;
    if (SPLITK) C += (size_t)blockIdx.z * M * N;
    int tid = threadIdx.x;
    int tr = tid / (BN / TN), tc = tid % (BN / TN);
    float acc[TM][TN];
    #pragma unroll
    for (int i = 0; i < TM; i++)
        #pragma unroll
        for (int j = 0; j < TN; j++) acc[i][j] = 0.f;
    int nsteps = KC / BK;

    auto loadA = [&](int kt, int buf) {
        #pragma unroll
        for (int r = tid; r < BM * BK / 4; r += THREADS) {
            int arow = r / (BK / 4), aq = r % (BK / 4);
            float4 v = *(const float4*)&A[(size_t)(m0 + arow) * K + kstart + kt * BK + aq * 4];
            As[buf][aq * 4 + 0][arow] = v.x; As[buf][aq * 4 + 1][arow] = v.y;
            As[buf][aq * 4 + 2][arow] = v.z; As[buf][aq * 4 + 3][arow] = v.w;
        }
    };
    auto loadB = [&](int kt, int buf) {
        #pragma unroll
        for (int r = tid; r < BK * BN / 4; r += THREADS) {
            int brow = r / (BN / 4), bq = r % (BN / 4);
            cp16(&Bs[buf][brow][bq * 4], &B[(size_t)(kstart + kt * BK + brow) * N + n0 + bq * 4]);
        }
    };
    loadA(0, 0); loadB(0, 0); cp_commit();
    for (int kt = 0; kt < nsteps; kt++) {
        int buf = kt & 1;
        if (kt + 1 < nsteps) {
            loadA(kt + 1, buf ^ 1); loadB(kt + 1, buf ^ 1); cp_commit();
            cp_wait<1>();
        } else cp_wait<0>();
        __syncthreads();
        #pragma unroll
        for (int k = 0; k < BK; k++) {
            float ra[TM], rb[TN];
            if constexpr (TM % 4 == 0) {
                #pragma unroll
                for (int i = 0; i < TM; i += 4)
                    *(float4*)&ra[i] = *(const float4*)&As[buf][k][tr * TM + i];
            } else {
                #pragma unroll
                for (int i = 0; i < TM; i++) ra[i] = As[buf][k][tr * TM + i];
            }
            #pragma unroll
            for (int j = 0; j < TN; j += 4)
                *(float4*)&rb[j] = *(const float4*)&Bs[buf][k][tc * TN + j];
            #pragma unroll
            for (int i = 0; i < TM; i++)
                #pragma unroll
                for (int j = 0; j < TN; j++) acc[i][j] += ra[i] * rb[j];
        }
        __syncthreads();
    }
    #pragma unroll
    for (int i = 0; i < TM; i++) {
        int m = m0 + tr * TM + i;
        #pragma unroll
        for (int j = 0; j < TN; j++) {
            int n = n0 + tc * TN + j;
            float v = acc[i][j];
            if (BIAS) v += bias[n];
            if (RELU) v = fmaxf(v, 0.f);
            C[(size_t)m * N + n] = v;
        }
    }
}

// ---------------- projection GEMM with fused 6-way weight gather ----------------
__device__ __forceinline__ const float* wf_ptr(
    const float* Wq, const float* Wk, const float* Wv,
    const float* Wqp, const float* Wkp, const float* Wvp, int kk, int n) {
    if (n < 192) return Wq  + kk * 192 + n;
    if (n < 384) return Wk  + kk * 192 + (n - 192);
    if (n < 576) return Wv  + kk * 192 + (n - 384);
    if (n < 720) return Wqp + kk * 144 + (n - 576);
    if (n < 864) return Wkp + kk * 144 + (n - 720);
    return Wvp + kk * 288 + (n - 864);
}

__global__ void proj_gemm_k(const float* __restrict__ A,
                            const float* __restrict__ Wq, const float* __restrict__ Wk,
                            const float* __restrict__ Wv, const float* __restrict__ Wqp,
                            const float* __restrict__ Wkp, const float* __restrict__ Wvp,
                            float* __restrict__ C) {
    const int BM = 64, BN = 64, BK = 16;
    __shared__ float As[2][BK][BM];
    __shared__ float Bs[2][BK][BN + 4];
    int n0 = blockIdx.x * BN, m0 = blockIdx.y * BM;
    int tid = threadIdx.x;
    int tr = tid / 16, tc = tid % 16;
    float acc[4][4];
    #pragma unroll
    for (int i = 0; i < 4; i++)
        #pragma unroll
        for (int j = 0; j < 4; j++) acc[i][j] = 0.f;
    auto loadA = [&](int kt, int buf) {
        for (int r = tid; r < BM * BK / 4; r += 256) {
            int arow = r / 4, aq = r % 4;
            float4 v = *(const float4*)&A[(size_t)(m0 + arow) * CSd + kt * BK + aq * 4];
            As[buf][aq * 4 + 0][arow] = v.x; As[buf][aq * 4 + 1][arow] = v.y;
            As[buf][aq * 4 + 2][arow] = v.z; As[buf][aq * 4 + 3][arow] = v.w;
        }
    };
    auto loadB = [&](int kt, int buf) {
        for (int r = tid; r < BK * BN / 4; r += 256) {
            int brow = r / 16, bq = r % 16;
            cp16(&Bs[buf][brow][bq * 4],
                 wf_ptr(Wq, Wk, Wv, Wqp, Wkp, Wvp, kt * BK + brow, n0 + bq * 4));
        }
    };
    loadA(0, 0); loadB(0, 0); cp_commit();
    const int nsteps = CSd / BK;
    for (int kt = 0; kt < nsteps; kt++) {
        int buf = kt & 1;
        if (kt + 1 < nsteps) {
            loadA(kt + 1, buf ^ 1); loadB(kt + 1, buf ^ 1); cp_commit();
            cp_wait<1>();
        } else cp_wait<0>();
        __syncthreads();
        #pragma unroll
        for (int k = 0; k < BK; k++) {
            float ra[4], rb[4];
            *(float4*)ra = *(const float4*)&As[buf][k][tr * 4];
            *(float4*)rb = *(const float4*)&Bs[buf][k][tc * 4];
            #pragma unroll
            for (int i = 0; i < 4; i++)
                #pragma unroll
                for (int j = 0; j < 4; j++) acc[i][j] += ra[i] * rb[j];
        }
        __syncthreads();
    }
    #pragma unroll
    for (int i = 0; i < 4; i++)
        #pragma unroll
        for (int j = 0; j < 4; j++)
            C[(size_t)(m0 + tr * 4 + i) * PROJD + n0 + tc * 4 + j] = acc[i][j];
}

// ---------------- prep: frames + E/F + packed B2 ----------------
__global__ void prep_k(const float* __restrict__ rot, const float* __restrict__ trans,
                       const float* __restrict__ gamma_raw) {
    __shared__ float R[9], T[3], gqS[144], gkS[144], sqqS[12], sqkS[12], wcgS[12];
    int n = blockIdx.x, tid = threadIdx.x;
    if (tid < 9) R[tid] = rot[n * 9 + tid];
    if (tid < 3) T[tid] = trans[n * 3 + tid];
    if (tid >= 16 && tid < 28) {
        int h = tid - 16;
        float x = gamma_raw[h];
        wcgS[h] = WCc * ((x > 20.f) ? x : log1pf(expf(x)));
    }
    __syncthreads();
    const float* base = &g_proj[(size_t)n * PROJD];
    for (int t = tid; t < 96; t += 128) {
        int which = t / 48, p = t % 48;
        const float* src = base + (which ? OKP : OQP) + p * 3;
        float b0 = src[0], b1 = src[1], b2 = src[2];
        float* dst = (which ? gkS : gqS) + p * 3;
        #pragma unroll
        for (int a = 0; a < 3; a++)
            dst[a] = R[a * 3 + 0] * b0 + R[a * 3 + 1] * b1 + R[a * 3 + 2] * b2 + T[a];
    }
    for (int t = tid; t < 96; t += 128) {
        int h = t >> 3, p = t & 7;
        const float* src = base + OVP + t * 3;
        float b0 = src[0], b1 = src[1], b2 = src[2];
        #pragma unroll
        for (int a = 0; a < 3; a++) {
            float v = R[a * 3 + 0] * b0 + R[a * 3 + 1] * b1 + R[a * 3 + 2] * b2 + T[a];
            g_gv[n * 288 + t * 3 + a] = v;
            g_B2[n * 576 + h * 48 + 16 + p * 3 + a] = v;
        }
    }
    for (int t = tid; t < 192; t += 128) {
        int h = t >> 4, c = t & 15;
        g_B2[n * 576 + h * 48 + c] = base[OV + t];
    }
    for (int t = tid; t < 96; t += 128) {
        int h = t / 8, c = 40 + (t % 8);
        g_B2[n * 576 + h * 48 + c] = 0.f;
    }
    __syncthreads();
    if (tid < 24) {
        int h = tid >> 1, which = tid & 1;
        const float* g = (which ? gkS : gqS) + h * 12;
        float s = 0.f;
        #pragma unroll
        for (int e = 0; e < 12; e++) s += g[e] * g[e];
        (which ? sqkS : sqqS)[h] = s;
    }
    __syncthreads();
    for (int t = tid; t < Hh * 32; t += 128) {
        int h = t >> 5, c = t & 31;
        float wcg = wcgS[h];
        float e, f;
        if (c < 16)      { e = 0.25f * base[OQ + h * 16 + c]; f = base[OK0 + h * 16 + c]; }
        else if (c < 28) { e = wcg * gqS[h * 12 + c - 16];    f = gkS[h * 12 + c - 16]; }
        else if (c == 28){ e = sqqS[h];                        f = -0.5f * wcg; }
        else if (c == 29){ e = 1.f;                            f = -0.5f * wcg * sqkS[h]; }
        else             { e = 0.f;                            f = 0.f; }
        g_E[(size_t)((h << 9) | n) * 32 + c] = e;
        g_F[(size_t)((h << 9) | n) * 32 + c] = f;
    }
}

// ---------------- logit core: 64i x 128j tile, acc 4x8 ----------------
__global__ void core_k() {
    __shared__ float As[32][64], BsT[32][128];
    int h = blockIdx.z, i0 = blockIdx.y * 64, j0 = blockIdx.x * 128;
    int tid = threadIdx.x;
    const float* Eh = &g_E[((size_t)h * Nn + i0) * 32];
    const float* Fh = &g_F[((size_t)h * Nn + j0) * 32];
    for (int t = tid; t < 512; t += 256) {
        int row = t >> 3, d4 = t & 7;
        float4 v = *(const float4*)&Eh[row * 32 + d4 * 4];
        As[d4 * 4 + 0][row] = v.x; As[d4 * 4 + 1][row] = v.y;
        As[d4 * 4 + 2][row] = v.z; As[d4 * 4 + 3][row] = v.w;
    }
    for (int t = tid; t < 1024; t += 256) {
        int row = t >> 3, d4 = t & 7;
        float4 w = *(const float4*)&Fh[row * 32 + d4 * 4];
        BsT[d4 * 4 + 0][row] = w.x; BsT[d4 * 4 + 1][row] = w.y;
        BsT[d4 * 4 + 2][row] = w.z; BsT[d4 * 4 + 3][row] = w.w;
    }
    __syncthreads();
    int tr = tid >> 4, tc = tid & 15;
    float acc[4][8];
    #pragma unroll
    for (int i = 0; i < 4; i++)
        #pragma unroll
        for (int j = 0; j < 8; j++) acc[i][j] = 0.f;
    #pragma unroll
    for (int d = 0; d < 32; d++) {
        float ra[4], rb[8];
        *(float4*)ra = *(const float4*)&As[d][tr * 4];
        *(float4*)&rb[0] = *(const float4*)&BsT[d][tc * 8];
        *(float4*)&rb[4] = *(const float4*)&BsT[d][tc * 8 + 4];
        #pragma unroll
        for (int i = 0; i < 4; i++)
            #pragma unroll
            for (int j = 0; j < 8; j++) acc[i][j] += ra[i] * rb[j];
    }
    #pragma unroll
    for (int i = 0; i < 4; i++) {
        size_t rowb = ((size_t)(i0 + tr * 4 + i) * Hh + h) * Nn + j0 + tc * 8;
        float4 v0 = make_float4(WLc * acc[i][0], WLc * acc[i][1], WLc * acc[i][2], WLc * acc[i][3]);
        float4 v1 = make_float4(WLc * acc[i][4], WLc * acc[i][5], WLc * acc[i][6], WLc * acc[i][7]);
        *(float4*)&g_logits[rowb] = v0;
        *(float4*)&g_logits[rowb + 4] = v1;
    }
}

// ---------------- FLASH2: bias(2j/thread, warp=z-group) + softmax + o_pair(float4) ----
// grid (Nn, 8), 256 thr. smem: pairS[64*132] WbT[12*132] lS[12*64] comb[4*32*25]
__global__ void __launch_bounds__(256) flash2_k(const float* __restrict__ pair,
                                                const float* __restrict__ Wb) {
    extern __shared__ float sm[];
    float* pairS = sm;                  // 8448
    float* WbT   = pairS + 8448;        // 1584
    float* lS    = WbT + 1584;          // 768
    float* comb  = lS + 768;            // 3200
    int i = blockIdx.x, js = blockIdx.y, j0 = js << 6;
    int tid = threadIdx.x;
    int w = tid >> 5, lane = tid & 31;

    for (int r = tid; r < 64 * 32; r += 256) {
        int row = r >> 5, q = r & 31;
        cp16(&pairS[row * 132 + q * 4], &pair[((size_t)i * Nn + j0 + row) * CZd + q * 4]);
    }
    cp_commit();
    for (int t = tid; t < CZd * Hh; t += 256) WbT[(t % Hh) * 132 + (t / Hh)] = Wb[t];
    if (tid < 192) {
        int h = tid >> 4, q = tid & 15;
        *(float4*)&lS[h * 64 + q * 4] =
            *(const float4*)&g_logits[((size_t)i * Hh + h) * Nn + j0 + q * 4];
    }

    // ---- bias: warp w = z-group (16 z), lane = j (2 j: lane, lane+32) ----
    float acc0[12], acc1[12];
    #pragma unroll
    for (int h = 0; h < 12; h++) { acc0[h] = 0.f; acc1[h] = 0.f; }

    cp_wait<0>();
    __syncthreads();
    {
        const float4* ap0 = (const float4*)&pairS[lane * 132 + w * 16];
        const float4* ap1 = (const float4*)&pairS[(lane + 32) * 132 + w * 16];
        #pragma unroll
        for (int z4 = 0; z4 < 4; z4++) {
            float4 p0 = ap0[z4], p1 = ap1[z4];
            #pragma unroll
            for (int h = 0; h < 12; h++) {
                float4 wv = *(const float4*)&WbT[h * 132 + w * 16 + z4 * 4];
                acc0[h] += p0.x * wv.x + p0.y * wv.y + p0.z * wv.z + p0.w * wv.w;
                acc1[h] += p1.x * wv.x + p1.y * wv.y + p1.z * wv.z + p1.w * wv.w;
            }
        }
    }
    // two-round tree reduction over 8 z-groups (comb rows padded to 25)
    if (w >= 4) {
        float* c = &comb[((w - 4) * 32 + lane) * 25];
        #pragma unroll
        for (int h = 0; h < 12; h++) { c[h] = acc0[h]; c[12 + h] = acc1[h]; }
    }
    __syncthreads();
    if (w < 4) {
        const float* c = &comb[(w * 32 + lane) * 25];
        #pragma unroll
        for (int h = 0; h < 12; h++) { acc0[h] += c[h]; acc1[h] += c[12 + h]; }
    }
    __syncthreads();
    if (w >= 1 && w < 4) {
        float* c = &comb[((w - 1) * 32 + lane) * 25];
        #pragma unroll
        for (int h = 0; h < 12; h++) { c[h] = acc0[h]; c[12 + h] = acc1[h]; }
    }
    __syncthreads();
    if (w == 0) {
        #pragma unroll
        for (int h = 0; h < 12; h++) {
            float s0 = acc0[h], s1 = acc1[h];
            #pragma unroll
            for (int g = 0; g < 3; g++) {
                const float* c = &comb[(g * 32 + lane) * 25];
                s0 += c[h]; s1 += c[12 + h];
            }
            lS[h * 64 + lane] += WLc * s0;
            lS[h * 64 + 32 + lane] += WLc * s1;
        }
    }
    __syncthreads();

    // ---- local softmax: warp w -> head w; warps 0..3 also head 8+w ----
    #pragma unroll
    for (int rep = 0; rep < 2; rep++) {
        int h = w + rep * 8;
        if (h < Hh) {
            float l0 = lS[h * 64 + lane], l1 = lS[h * 64 + 32 + lane];
            float m = fmaxf(l0, l1);
            #pragma unroll
            for (int off = 16; off; off >>= 1) m = fmaxf(m, __shfl_xor_sync(0xffffffffu, m, off));
            float e0 = __expf(l0 - m), e1 = __expf(l1 - m);
            float s = e0 + e1;
            #pragma unroll
            for (int off = 16; off; off >>= 1) s += __shfl_xor_sync(0xffffffffu, s, off);
            lS[h * 64 + lane] = e0;
            lS[h * 64 + 32 + lane] = e1;
            size_t gb = ((size_t)i * Hh + h) * Nn + j0;
            g_logits[gb + lane] = e0;
            g_logits[gb + 32 + lane] = e1;
            if (lane == 0) {
                int msb = (((i * Hh) + h) * 8 + js) * 2;
                g_ms[msb] = m;
                g_ms[msb + 1] = s;
            }
        }
    }
    __syncthreads();

    // ---- o_pair: jh halves of 32 j; thread = (ht 3h) x (zz 4z float4) ----
    int jh = tid >> 7, rem = tid & 127, ht = rem >> 5, zz = rem & 31;
    float a3[3][4];
    #pragma unroll
    for (int b = 0; b < 3; b++)
        #pragma unroll
        for (int a = 0; a < 4; a++) a3[b][a] = 0.f;
    const float* E0 = &lS[(ht * 3 + 0) * 64 + jh * 32];
    const float* E1 = &lS[(ht * 3 + 1) * 64 + jh * 32];
    const float* E2 = &lS[(ht * 3 + 2) * 64 + jh * 32];
    const float* pb = &pairS[jh * 32 * 132];
    #pragma unroll 8
    for (int j = 0; j < 32; j++) {
        float4 p = *(const float4*)&pb[j * 132 + zz * 4];
        float v0 = E0[j], v1 = E1[j], v2 = E2[j];
        a3[0][0] += v0 * p.x; a3[0][1] += v0 * p.y; a3[0][2] += v0 * p.z; a3[0][3] += v0 * p.w;
        a3[1][0] += v1 * p.x; a3[1][1] += v1 * p.y; a3[1][2] += v1 * p.z; a3[1][3] += v1 * p.w;
        a3[2][0] += v2 * p.x; a3[2][1] += v2 * p.y; a3[2][2] += v2 * p.z; a3[2][3] += v2 * p.w;
    }
    if (jh == 1) {
        float* c = &comb[rem * 13];
        #pragma unroll
        for (int b = 0; b < 3; b++)
            #pragma unroll
            for (int a = 0; a < 4; a++) c[b * 4 + a] = a3[b][a];
    }
    __syncthreads();
    if (jh == 0) {
        const float* c = &comb[rem * 13];
        float* dst = &g_opP[((size_t)js * Nn + i) * (Hh * CZd)];
        #pragma unroll
        for (int b = 0; b < 3; b++) {
            float4 v;
            v.x = a3[b][0] + c[b * 4 + 0];
            v.y = a3[b][1] + c[b * 4 + 1];
            v.z = a3[b][2] + c[b * 4 + 2];
            v.w = a3[b][3] + c[b * 4 + 3];
            *(float4*)&dst[(ht * 3 + b) * CZd + zz * 4] = v;
        }
    }
}

// ---------------- combine: global stats + o_pair; factors -> g_fct ----------------
__global__ void combine_k() {
    __shared__ float fctS[96];
    int i = blockIdx.x, tid = threadIdx.x;
    if (tid < 96) {
        int h = tid >> 3, js = tid & 7;
        float mv[8], sv[8];
        float mg = -1e30f;
        #pragma unroll
        for (int k = 0; k < 8; k++) {
            int b = ((i * Hh + h) * 8 + k) * 2;
            mv[k] = g_ms[b]; sv[k] = g_ms[b + 1];
            mg = fmaxf(mg, mv[k]);
        }
        float sg = 0.f;
        #pragma unroll
        for (int k = 0; k < 8; k++) sg += sv[k] * __expf(mv[k] - mg);
        float f = __expf(mv[js] - mg) / sg;
        fctS[tid] = f;
        g_fct[i * 96 + tid] = f;
    }
    __syncthreads();
    const size_t S = (size_t)Nn * Hh * CZd;
    for (int c = tid; c < Hh * CZd; c += 256) {
        int h = c >> 7;
        float s = 0.f;
        #pragma unroll
        for (int js = 0; js < 8; js++)
            s += fctS[h * 8 + js] * g_opP[js * S + (size_t)i * (Hh * CZd) + c];
        g_concat[(size_t)i * OUTD + 576 + c] = s;
    }
}

// ---------------- o_v & o_pt: unnormalized e x per-chunk factor ----------------
__global__ void ov_k() {
    __shared__ float As[2][32 * 36];
    __shared__ float Bs[2][32 * 48];
    __shared__ float fS[32 * 8];
    int i0 = blockIdx.x * 32, h = blockIdx.y;
    int tid = threadIdx.x;
    int tr = tid / 16, tc = tid % 16;
    if (tid < 256) {
        int row = tid >> 3, js = tid & 7;
        fS[row * 8 + js] = g_fct[(i0 + row) * 96 + h * 8 + js];
    }
    float acc[2][3];
    #pragma unroll
    for (int a = 0; a < 2; a++)
        #pragma unroll
        for (int b = 0; b < 3; b++) acc[a][b] = 0.f;

    auto loadA = [&](int chunk, int buf) {
        int j0 = chunk * 32;
        int row = tid >> 3, q = tid & 7;
        cp16(&As[buf][row * 36 + q * 4],
             &g_logits[((size_t)(i0 + row) * Hh + h) * Nn + j0 + q * 4]);
    };
    auto loadB = [&](int chunk, int buf) {
        int j0 = chunk * 32;
        for (int t = tid; t < 384; t += 256) {
            int row = t / 12, q = t % 12;
            cp16(&Bs[buf][row * 48 + q * 4], &g_B2[(size_t)(j0 + row) * 576 + h * 48 + q * 4]);
        }
    };
    loadA(0, 0); loadB(0, 0); cp_commit();
    for (int chunk = 0; chunk < 16; chunk++) {
        int buf = chunk & 1;
        if (chunk + 1 < 16) {
            loadA(chunk + 1, buf ^ 1); loadB(chunk + 1, buf ^ 1); cp_commit();
            cp_wait<1>();
        } else cp_wait<0>();
        __syncthreads();
        float pacc[2][3];
        #pragma unroll
        for (int a = 0; a < 2; a++)
            #pragma unroll
            for (int b = 0; b < 3; b++) pacc[a][b] = 0.f;
        #pragma unroll 8
        for (int jl = 0; jl < 32; jl++) {
            float ra[2], rb[3];
            #pragma unroll
            for (int a = 0; a < 2; a++) ra[a] = As[buf][(tr * 2 + a) * 36 + jl];
            #pragma unroll
            for (int b = 0; b < 3; b++) rb[b] = Bs[buf][jl * 48 + tc * 3 + b];
            #pragma unroll
            for (int a = 0; a < 2; a++)
                #pragma unroll
                for (int b = 0; b < 3; b++) pacc[a][b] += ra[a] * rb[b];
        }
        int js = chunk >> 1;
        #pragma unroll
        for (int a = 0; a < 2; a++) {
            float f = fS[(tr * 2 + a) * 8 + js];
            #pragma unroll
            for (int b = 0; b < 3; b++) acc[a][b] += f * pacc[a][b];
        }
        __syncthreads();
    }
    #pragma unroll
    for (int a = 0; a < 2; a++) {
        int i = i0 + tr * 2 + a;
        #pragma unroll
        for (int b = 0; b < 3; b++) {
            int c = tc * 3 + b;
            if (c < 16)      g_concat[(size_t)i * OUTD + h * Cc + c] = acc[a][b];
            else if (c < 40) g_opt[i * (Hh * 24) + h * 24 + (c - 16)] = acc[a][b];
        }
    }
}

__global__ void post_pt_k(const float* __restrict__ rot, const float* __restrict__ trans) {
    int idx = blockIdx.x * blockDim.x + threadIdx.x;
    if (idx >= Nn * Hh * PVd) return;
    int i = idx / (Hh * PVd), t = idx % (Hh * PVd);
    float b0 = g_opt[i * (Hh * 24) + t * 3 + 0] - trans[i * 3 + 0];
    float b1 = g_opt[i * (Hh * 24) + t * 3 + 1] - trans[i * 3 + 1];
    float b2 = g_opt[i * (Hh * 24) + t * 3 + 2] - trans[i * 3 + 2];
    float l0 = rot[i * 9 + 0] * b0 + rot[i * 9 + 3] * b1 + rot[i * 9 + 6] * b2;
    float l1 = rot[i * 9 + 1] * b0 + rot[i * 9 + 4] * b1 + rot[i * 9 + 7] * b2;
    float l2 = rot[i * 9 + 2] * b0 + rot[i * 9 + 5] * b1 + rot[i * 9 + 8] * b2;
    float* crow = &g_concat[(size_t)i * OUTD];
    crow[192 + t * 3 + 0] = l0;
    crow[192 + t * 3 + 1] = l1;
    crow[192 + t * 3 + 2] = l2;
    crow[480 + t] = sqrtf(l0 * l0 + l1 * l1 + l2 * l2 + 1e-8f);
}

// ---------------- layer norms ----------------
__device__ __forceinline__ float blockSum384(float v, float* red) {
    int tid = threadIdx.x;
    red[tid] = v;
    if (tid < 128) red[384 + tid] = 0.f;
    __syncthreads();
    for (int s = 256; s > 0; s >>= 1) {
        if (tid < s) red[tid] += red[tid + s];
        __syncthreads();
    }
    float r = red[0];
    __syncthreads();
    return r;
}

__global__ void ln1_k(const float* __restrict__ single_in, const float* __restrict__ bo,
                      const float* __restrict__ g, const float* __restrict__ b) {
    __shared__ float red[512];
    int row = blockIdx.x, tid = threadIdx.x;
    float x = single_in[row * CSd + tid] + bo[tid];
    #pragma unroll
    for (int z = 0; z < 4; z++) x += g_wop[(size_t)z * Nn * CSd + row * CSd + tid];
    float mean = blockSum384(x, red) * (1.f / CSd);
    float dx = x - mean;
    float var = blockSum384(dx * dx, red) * (1.f / CSd);
    g_s1[row * CSd + tid] = dx * rsqrtf(var + 1e-5f) * g[tid] + b[tid];
}

__global__ void ln2_k(const float* __restrict__ g, const float* __restrict__ b,
                      float* __restrict__ out) {
    __shared__ float red[512];
    int row = blockIdx.x, tid = threadIdx.x;
    float x = g_s1[row * CSd + tid] + g_h3[row * CSd + tid];
    float mean = blockSum384(x, red) * (1.f / CSd);
    float dx = x - mean;
    float var = blockSum384(dx * dx, red) * (1.f / CSd);
    float y = dx * rsqrtf(var + 1e-5f) * g[tid] + b[tid];
    out[row * CSd + tid] = y;
    g_s2[row * CSd + tid] = y;
}

// ---------------- backbone update ----------------
__global__ void update_k(const float* __restrict__ rot, const float* __restrict__ trans,
                         const float* __restrict__ Wbu, const float* __restrict__ bbu,
                         float* __restrict__ out) {
    int gtid = blockIdx.x * blockDim.x + threadIdx.x;
    int n = gtid >> 5, lane = gtid & 31;
    if (n >= Nn) return;
    float u[6] = {0, 0, 0, 0, 0, 0};
    for (int s = lane; s < CSd; s += 32) {
        float x = g_s2[n * CSd + s];
        #pragma unroll
        for (int j = 0; j < 6; j++) u[j] += x * Wbu[s * 6 + j];
    }
    #pragma unroll
    for (int j = 0; j < 6; j++)
        #pragma unroll
        for (int off = 16; off; off >>= 1) u[j] += __shfl_xor_sync(0xffffffffu, u[j], off);
    if (lane != 0) return;
    #pragma unroll
    for (int j = 0; j < 6; j++) u[j] += bbu[j];
    float b = u[0], c = u[1], d = u[2];
    float inq = rsqrtf(1.f + b * b + c * c + d * d);
    float a = inq; b *= inq; c *= inq; d *= inq;
    float R[9] = {
        a*a + b*b - c*c - d*d, 2.f*(b*c - a*d),       2.f*(b*d + a*c),
        2.f*(b*c + a*d),       a*a - b*b + c*c - d*d, 2.f*(c*d - a*b),
        2.f*(b*d - a*c),       2.f*(c*d + a*b),       a*a - b*b - c*c + d*d };
    float rn[9];
    #pragma unroll
    for (int aa = 0; aa < 3; aa++)
        #pragma unroll
        for (int cc = 0; cc < 3; cc++) {
            float s2 = 0.f;
            #pragma unroll
            for (int bx = 0; bx < 3; bx++) s2 += rot[n * 9 + aa * 3 + bx] * R[bx * 3 + cc];
            rn[aa * 3 + cc] = s2;
        }
    float t0 = u[3], t1 = u[4], t2 = u[5];
    float tn[3];
    #pragma unroll
    for (int aa = 0; aa < 3; aa++)
        tn[aa] = rot[n * 9 + aa * 3 + 0] * t0 + rot[n * 9 + aa * 3 + 1] * t1 +
                 rot[n * 9 + aa * 3 + 2] * t2 + trans[n * 3 + aa];
    #pragma unroll
    for (int e = 0; e < 9; e++) { g_rotn[n * 9 + e] = rn[e]; out[Nn * CSd + n * 9 + e] = rn[e]; }
    #pragma unroll
    for (int e = 0; e < 3; e++) { g_trn[n * 3 + e] = tn[e]; out[Nn * CSd + Nn * 9 + n * 3 + e] = tn[e]; }
}

// ---------------- loss ----------------
__global__ void loss_part_k(const float* __restrict__ rt, const float* __restrict__ tt) {
    int i = blockIdx.x, tid = threadIdx.x;
    __shared__ float red[256];
    float rn[9], rte[9], tni[3], tti[3];
    #pragma unroll
    for (int e = 0; e < 9; e++) { rn[e] = g_rotn[i * 9 + e]; rte[e] = rt[i * 9 + e]; }
    #pragma unroll
    for (int e = 0; e < 3; e++) { tni[e] = g_trn[i * 3 + e]; tti[e] = tt[i * 3 + e]; }
    float s = 0.f;
    for (int j = tid; j < Nn; j += 256) {
        float db0 = g_trn[j * 3 + 0] - tni[0];
        float db1 = g_trn[j * 3 + 1] - tni[1];
        float db2 = g_trn[j * 3 + 2] - tni[2];
        float dp0 = rn[0] * db0 + rn[3] * db1 + rn[6] * db2;
        float dp1 = rn[1] * db0 + rn[4] * db1 + rn[7] * db2;
        float dp2 = rn[2] * db0 + rn[5] * db1 + rn[8] * db2;
        float eb0 = tt[j * 3 + 0] - tti[0];
        float eb1 = tt[j * 3 + 1] - tti[1];
        float eb2 = tt[j * 3 + 2] - tti[2];
        float dt0 = rte[0] * eb0 + rte[3] * eb1 + rte[6] * eb2;
        float dt1 = rte[1] * eb0 + rte[4] * eb1 + rte[7] * eb2;
        float dt2 = rte[2] * eb0 + rte[5] * eb1 + rte[8] * eb2;
        float d0 = dp0 - dt0, d1 = dp1 - dt1, d2 = dp2 - dt2;
        float dd = sqrtf(d0 * d0 + d1 * d1 + d2 * d2 + 1e-12f);
        s += fminf(dd, 10.f);
    }
    red[tid] = s; __syncthreads();
    for (int st = 128; st > 0; st >>= 1) {
        if (tid < st) red[tid] += red[tid + st];
        __syncthreads();
    }
    if (tid == 0) g_partial[i] = red[0];
}

__global__ void loss_final_k(float* __restrict__ out) {
    __shared__ float red[512];
    int tid = threadIdx.x;
    red[tid] = g_partial[tid];
    __syncthreads();
    for (int s = 256; s > 0; s >>= 1) {
        if (tid < s) red[tid] += red[tid + s];
        __syncthreads();
    }
    if (tid == 0)
        out[Nn * CSd + Nn * 9 + Nn * 3] = red[0] / ((float)Nn * (float)Nn) * 0.1f;
}

// ---------------- host ----------------
template <typename T>
static float* symaddr(T& sym) {
    void* p = nullptr;
    cudaGetSymbolAddress(&p, sym);
    return (float*)p;
}

extern "C" void kernel_launch(void* const* d_in, const int* in_sizes, int n_in,
                              void* d_out, int out_size) {
    const float* single      = (const float*)d_in[0];
    const float* pair        = (const float*)d_in[1];
    const float* rot         = (const float*)d_in[2];
    const float* trans       = (const float*)d_in[3];
    const float* rot_truth   = (const float*)d_in[4];
    const float* trans_truth = (const float*)d_in[5];
    const float* Wq  = (const float*)d_in[6];
    const float* Wk  = (const float*)d_in[7];
    const float* Wv  = (const float*)d_in[8];
    const float* Wqp = (const float*)d_in[9];
    const float* Wkp = (const float*)d_in[10];
    const float* Wvp = (const float*)d_in[11];
    const float* Wb  = (const float*)d_in[12];
    const float* Wo  = (const float*)d_in[13];
    const float* bo  = (const float*)d_in[14];
    const float* gamma_raw = (const float*)d_in[15];
    const float* ln1_g = (const float*)d_in[16];
    const float* ln1_b = (const float*)d_in[17];
    const float* ln2_g = (const float*)d_in[18];
    const float* ln2_b = (const float*)d_in[19];
    const float* W1 = (const float*)d_in[20];
    const float* b1 = (const float*)d_in[21];
    const float* W2 = (const float*)d_in[22];
    const float* b2 = (const float*)d_in[23];
    const float* W3 = (const float*)d_in[24];
    const float* b3 = (const float*)d_in[25];
    const float* Wbu = (const float*)d_in[26];
    const float* bbu = (const float*)d_in[27];
    float* out = (float*)d_out;

    float* pProj   = symaddr(g_proj);
    float* pConcat = symaddr(g_concat);
    float* pS1     = symaddr(g_s1);
    float* pH1     = symaddr(g_h1);
    float* pH2     = symaddr(g_h2);
    float* pH3     = symaddr(g_h3);

    const int FLASH2_SMEM = (8448 + 1584 + 768 + 3200) * 4;   // 56000
    cudaFuncSetAttribute(flash2_k, cudaFuncAttributeMaxDynamicSharedMemorySize, FLASH2_SMEM);

    proj_gemm_k<<<dim3(PROJD/64, Nn/64), 256>>>(single, Wq, Wk, Wv, Wqp, Wkp, Wvp, pProj);
    prep_k<<<Nn, 128>>>(rot, trans, gamma_raw);
    core_k<<<dim3(Nn/128, Nn/64, Hh), 256>>>();

    flash2_k<<<dim3(Nn, 8), 256, FLASH2_SMEM>>>(pair, Wb);   // profiler slot 4
    combine_k<<<Nn, 256>>>();
    ov_k<<<dim3(Nn/32, Hh), 256>>>();
    post_pt_k<<<(Nn * Hh * PVd + 255) / 256, 256>>>(rot, trans);

    sgemm_k<64,64,16,4,4,false,false,true><<<dim3(CSd/64, Nn/64, 4), 256>>>(
        pConcat, Wo, nullptr, symaddr(g_wop), Nn, CSd, OUTD, OUTD/4);
    ln1_k<<<Nn, CSd>>>(single, bo, ln1_g, ln1_b);

    sgemm_k<32,64,16,2,4,true,true,false><<<dim3(CSd/64, Nn/32, 1), 256>>>(
        pS1, W1, b1, pH1, Nn, CSd, CSd, CSd);
    sgemm_k<32,64,16,2,4,true,true,false><<<dim3(CSd/64, Nn/32, 1), 256>>>(
        pH1, W2, b2, pH2, Nn, CSd, CSd, CSd);
    sgemm_k<32,64,16,2,4,true,false,false><<<dim3(CSd/64, Nn/32, 1), 256>>>(
        pH2, W3, b3, pH3, Nn, CSd, CSd, CSd);
    ln2_k<<<Nn, CSd>>>(ln2_g, ln2_b, out);

    update_k<<<(Nn * 32 + 127) / 128, 128>>>(rot, trans, Wbu, bbu, out);
    loss_part_k<<<Nn, 256>>>(rot_truth, trans_truth);
    loss_final_k<<<1, 512>>>(out);
}